// round 4
// baseline (speedup 1.0000x reference)
#include <cuda_runtime.h>
#include <math.h>

#define HW 4096
#define EE 768
#define NCOL 7155
#define LDC 7168
#define LDWT 1536

static __device__ float g_C[(size_t)HW * LDC];
static __device__ float g_Wbig[(size_t)EE * LDC];
static __device__ float g_ow[27 * EE];
static __device__ float g_boff[27];
static __device__ float g_off[HW * 18];
static __device__ float g_mask[HW * 9];
static __device__ float g_blk[(size_t)HW * EE];
static __device__ float g_act[(size_t)HW * EE];
static __device__ float g_cat[(size_t)HW * EE];
static __device__ float g_x2[(size_t)HW * EE];
static __device__ float g_wT[EE * LDWT];
static __device__ float g_spqT[EE * 384];
static __device__ float g_q2[(size_t)HW * 384];
static __device__ float g_ps[32 * EE], g_pq[32 * EE], g_sc[EE], g_sh[EE];
static __device__ float g_q[HW], g_wq[HW];
static __device__ float g_pt[32 * EE], g_t[EE], g_r[384], g_wz[EE], g_s[EE];
static __device__ float g_mx[384], g_wq2[384], g_u[EE];

// ---------- generic SGEMM: C[M,N] (+)= A[M,K]@B[K,N]; 128x128x16, 256 thr, 8x8 ----------
__global__ __launch_bounds__(256, 2)
void k_sgemm(const float* __restrict__ A, int lda, const float* __restrict__ B, int ldb,
             float* __restrict__ C, int ldc, int M, int N, int K, int accum)
{
    __shared__ float As[16][128];
    __shared__ float Bs[16][128];
    int tid = threadIdx.x;
    int row0 = blockIdx.y * 128, col0 = blockIdx.x * 128;
    int tx = tid & 15, ty = tid >> 4;
    float acc[8][8];
#pragma unroll
    for (int i = 0; i < 8; i++)
#pragma unroll
        for (int j = 0; j < 8; j++) acc[i][j] = 0.f;
    int arow = tid >> 2, acol = (tid & 3) << 2;
    int brow = tid >> 5, bcol = (tid & 31) << 2;
    for (int k0 = 0; k0 < K; k0 += 16) {
#pragma unroll
        for (int h = 0; h < 2; h++) {
            int r = arow + h * 64, gr = row0 + r;
            float4 v = make_float4(0.f, 0.f, 0.f, 0.f);
            if (gr < M) v = *(const float4*)(A + (size_t)gr * lda + k0 + acol);
            As[acol + 0][r] = v.x; As[acol + 1][r] = v.y;
            As[acol + 2][r] = v.z; As[acol + 3][r] = v.w;
        }
#pragma unroll
        for (int h = 0; h < 2; h++) {
            int r = brow + h * 8;
            const float* Bp = B + (size_t)(k0 + r) * ldb;
            int gc = col0 + bcol;
            float4 v = make_float4(0.f, 0.f, 0.f, 0.f);
            if (gc + 3 < N) v = *(const float4*)(Bp + gc);
            else {
                if (gc + 0 < N) v.x = Bp[gc + 0];
                if (gc + 1 < N) v.y = Bp[gc + 1];
                if (gc + 2 < N) v.z = Bp[gc + 2];
                if (gc + 3 < N) v.w = Bp[gc + 3];
            }
            *(float4*)&Bs[r][bcol] = v;
        }
        __syncthreads();
#pragma unroll
        for (int kk = 0; kk < 16; kk++) {
            float a[8], b[8];
            *(float4*)&a[0] = *(const float4*)&As[kk][ty * 8];
            *(float4*)&a[4] = *(const float4*)&As[kk][ty * 8 + 4];
            *(float4*)&b[0] = *(const float4*)&Bs[kk][tx * 8];
            *(float4*)&b[4] = *(const float4*)&Bs[kk][tx * 8 + 4];
#pragma unroll
            for (int i = 0; i < 8; i++)
#pragma unroll
                for (int j = 0; j < 8; j++) acc[i][j] = fmaf(a[i], b[j], acc[i][j]);
        }
        __syncthreads();
    }
#pragma unroll
    for (int i = 0; i < 8; i++) {
        int r = row0 + ty * 8 + i;
        if (r >= M) continue;
        float* Cp = C + (size_t)r * ldc;
#pragma unroll
        for (int j = 0; j < 8; j++) {
            int cc = col0 + tx * 8 + j;
            if (cc < N) { float v = acc[i][j]; Cp[cc] = accum ? Cp[cc] + v : v; }
        }
    }
}

// ---------- generic GEMV: y[blockIdx.x] = dot(W[row,:K], x) + bias ----------
__global__ void k_gemv(const float* __restrict__ W, const float* __restrict__ x,
                       const float* __restrict__ bias, float* __restrict__ y, int K)
{
    int m = blockIdx.x, t = threadIdx.x;  // 128 threads
    float a = 0.f;
    for (int k = t; k < K; k += 128) a += W[(size_t)m * K + k] * x[k];
    __shared__ float red[128];
    red[t] = a; __syncthreads();
    for (int s = 64; s > 0; s >>= 1) { if (t < s) red[t] += red[t + s]; __syncthreads(); }
    if (t == 0) y[m] = red[0] + (bias ? bias[m] : 0.f);
}

// ---------- transpose src[M,768] -> dst[c*ldd + coloff + m] ----------
__global__ void k_transpose(const float* __restrict__ src, float* __restrict__ dst,
                            int M, int ldd, int coloff)
{
    int i = blockIdx.x * 256 + threadIdx.x;
    if (i < M * 768) { int m = i / 768, c = i % 768; dst[(size_t)c * ldd + coloff + m] = src[i]; }
}

__global__ void k_prep_ow(const float* __restrict__ offw, const float* __restrict__ mskw)
{
    int i = blockIdx.x * 256 + threadIdx.x;
    if (i < 27 * EE) { int j = i / EE, c = i % EE; g_ow[i] = (j < 18) ? offw[j * EE + c] : mskw[(j - 18) * EE + c]; }
}

// Wbig[c, kk*768+o] = conv_w[o,c,kk];  Wbig[c, 6912+j*9+kk] = sum_o ow[j,o]*conv_w[o,c,kk]
__global__ void k_build_wbig(const float* __restrict__ convw)
{
    int idx = blockIdx.x * 256 + threadIdx.x;
    const int T1 = EE * 6912;
    if (idx < T1) {
        int o = idx / 6912, rem = idx % 6912, c = rem / 9, kk = rem % 9;
        g_Wbig[(size_t)c * LDC + kk * EE + o] = convw[idx];
    } else if (idx < T1 + 27 * 6912) {
        int i = idx - T1, j = i / 6912, r = i % 6912;
        float s = 0.f;
        for (int o = 0; o < EE; o++) s += g_ow[j * EE + o] * convw[(size_t)o * 6912 + r];
        g_Wbig[(size_t)(r / 9) * LDC + 6912 + j * 9 + (r % 9)] = s;
    }
}

// ---------- offsets (shift-add of P cols) + mask softmax ----------
__global__ void k_offmask()
{
    int hw = blockIdx.x, y = hw >> 6, x = hw & 63;
    int j = threadIdx.x;  // 32 threads, 27 active
    __shared__ float lg[9];
    __shared__ float mx_s, sum_s;
    if (j < 27) {
        float v = g_boff[j];
#pragma unroll
        for (int k = 0; k < 9; k++) {
            int yy = y + k / 3 - 1, xx = x + k % 3 - 1;
            if (yy >= 0 && yy < 64 && xx >= 0 && xx < 64)
                v += g_C[(size_t)(yy * 64 + xx) * LDC + 6912 + j * 9 + k];
        }
        if (j < 18) g_off[hw * 18 + j] = v; else lg[j - 18] = v;
    }
    __syncthreads();
    if (j == 0) {
        float mx = lg[0];
        for (int t = 1; t < 9; t++) mx = fmaxf(mx, lg[t]);
        float s = 0.f;
        for (int t = 0; t < 9; t++) s += expf(lg[t] - mx);
        mx_s = mx; sum_s = s;
    }
    __syncthreads();
    if (j < 9) g_mask[hw * 9 + j] = expf(lg[j] - mx_s) / sum_s;
}

// ---------- deform output: bilinear gather of per-tap pointwise conv results ----------
__global__ __launch_bounds__(192)
void k_deform_gather(const float* __restrict__ convb)
{
    int hw = blockIdx.x, y = hw >> 6, x = hw & 63;
    __shared__ int sidx[9][4];
    __shared__ float swgt[9][4];
    int tid = threadIdx.x;  // 192
    if (tid < 9) {
        int k = tid;
        float dy = g_off[hw * 18 + 2 * k], dx = g_off[hw * 18 + 2 * k + 1];
        float m = g_mask[k * HW + hw];  // raw-reshape (torch .reshape) mask indexing
        float py = (float)(y + k / 3 - 1) + dy;
        float px = (float)(x + k % 3 - 1) + dx;
        float y0f = floorf(py), x0f = floorf(px);
        float wy1 = py - y0f, wx1 = px - x0f;
        int y0 = (int)y0f, x0 = (int)x0f;
#pragma unroll
        for (int c = 0; c < 4; c++) {
            int yy = y0 + (c >> 1), xx = x0 + (c & 1);
            bool valid = (yy >= 0 && yy <= 63 && xx >= 0 && xx <= 63);
            int yc = min(max(yy, 0), 63), xc = min(max(xx, 0), 63);
            float w = ((c >> 1) ? wy1 : 1.f - wy1) * ((c & 1) ? wx1 : 1.f - wx1);
            sidx[k][c] = yc * 64 + xc;
            swgt[k][c] = valid ? w * m : 0.f;
        }
    }
    __syncthreads();
    int o = tid * 4;
    float4 acc = *(const float4*)(convb + o);
#pragma unroll
    for (int k = 0; k < 9; k++) {
        size_t cb = (size_t)k * EE + o;
#pragma unroll
        for (int c = 0; c < 4; c++) {
            float w = swgt[k][c];
            const float4 v = *(const float4*)(&g_C[(size_t)sidx[k][c] * LDC + cb]);
            acc.x = fmaf(w, v.x, acc.x); acc.y = fmaf(w, v.y, acc.y);
            acc.z = fmaf(w, v.z, acc.z); acc.w = fmaf(w, v.w, acc.w);
        }
    }
    *(float4*)(&g_blk[(size_t)hw * EE + o]) = acc;
}

// ---------- BatchNorm (train stats) + relu ----------
__global__ void k_bn_partial()
{
    int b = blockIdx.x, t = threadIdx.x;  // 32 x 256
    float s0 = 0, s1 = 0, s2 = 0, q0 = 0, q1 = 0, q2v = 0;
    for (int r = 0; r < 128; r++) {
        const float* row = &g_blk[(size_t)(b * 128 + r) * EE];
        float v0 = row[t], v1 = row[t + 256], v2 = row[t + 512];
        s0 += v0; s1 += v1; s2 += v2; q0 += v0 * v0; q1 += v1 * v1; q2v += v2 * v2;
    }
    g_ps[b * EE + t] = s0; g_ps[b * EE + t + 256] = s1; g_ps[b * EE + t + 512] = s2;
    g_pq[b * EE + t] = q0; g_pq[b * EE + t + 256] = q1; g_pq[b * EE + t + 512] = q2v;
}
__global__ void k_bn_final(const float* __restrict__ bng, const float* __restrict__ bnb)
{
    int c = threadIdx.x;  // 768
    float s = 0, q = 0;
    for (int b = 0; b < 32; b++) { s += g_ps[b * EE + c]; q += g_pq[b * EE + c]; }
    float mu = s * (1.f / 4096.f);
    float var = q * (1.f / 4096.f) - mu * mu;
    float sc = rsqrtf(var + 1e-5f) * bng[c];
    g_sc[c] = sc; g_sh[c] = bnb[c] - mu * sc;
}
__global__ void k_bn_relu()
{
    int idx = (blockIdx.x * 256 + threadIdx.x) * 4;
    int c = idx % EE;
    float4 v = *(const float4*)&g_blk[idx];
    float4 sc = *(const float4*)&g_sc[c];
    float4 sh = *(const float4*)&g_sh[c];
    float4 r;
    r.x = fmaxf(0.f, fmaf(v.x, sc.x, sh.x)); r.y = fmaxf(0.f, fmaf(v.y, sc.y, sh.y));
    r.z = fmaxf(0.f, fmaf(v.z, sc.z, sh.z)); r.w = fmaxf(0.f, fmaf(v.w, sc.w, sh.w));
    *(float4*)&g_act[idx] = r;
}

// ---------- CAM ----------
__global__ void k_softmax_hw()
{
    __shared__ float sm[4096];
    __shared__ float red[1024];
    int t = threadIdx.x;
    float lm = -1e30f;
    for (int i = t; i < 4096; i += 1024) { float v = g_q[i]; sm[i] = v; lm = fmaxf(lm, v); }
    red[t] = lm; __syncthreads();
    for (int s = 512; s > 0; s >>= 1) { if (t < s) red[t] = fmaxf(red[t], red[t + s]); __syncthreads(); }
    float mx = red[0]; __syncthreads();
    float ls = 0.f;
    for (int i = t; i < 4096; i += 1024) { float e = expf(sm[i] - mx); sm[i] = e; ls += e; }
    red[t] = ls; __syncthreads();
    for (int s = 512; s > 0; s >>= 1) { if (t < s) red[t] += red[t + s]; __syncthreads(); }
    float inv = 1.f / red[0]; __syncthreads();
    for (int i = t; i < 4096; i += 1024) g_wq[i] = sm[i] * inv;
}
__global__ void k_poolw()
{
    int b = blockIdx.x, t = threadIdx.x;  // 32 x 256
    float a0 = 0, a1 = 0, a2 = 0;
    for (int r = 0; r < 128; r++) {
        int hw = b * 128 + r;
        float w = g_wq[hw];
        const float* row = &g_cat[(size_t)hw * EE];
        a0 += w * row[t]; a1 += w * row[t + 256]; a2 += w * row[t + 512];
    }
    g_pt[b * EE + t] = a0; g_pt[b * EE + t + 256] = a1; g_pt[b * EE + t + 512] = a2;
}
__global__ void k_pool_fin()
{
    int c = threadIdx.x;
    float s = 0;
    for (int b = 0; b < 32; b++) s += g_pt[b * EE + c];
    g_t[c] = s;
}
__global__ void k_ln_sigmoid(const float* __restrict__ lng, const float* __restrict__ lnb)
{
    int c = threadIdx.x;  // 768
    __shared__ float buf[768];
    __shared__ float red[256];
    float v = g_wz[c];
    buf[c] = v; __syncthreads();
    if (c < 256) red[c] = buf[c] + buf[c + 256] + buf[c + 512];
    __syncthreads();
    for (int s = 128; s > 0; s >>= 1) { if (c < s) red[c] += red[c + s]; __syncthreads(); }
    float mu = red[0] * (1.f / 768.f); __syncthreads();
    float d = v - mu;
    buf[c] = d * d; __syncthreads();
    if (c < 256) red[c] = buf[c] + buf[c + 256] + buf[c + 512];
    __syncthreads();
    for (int s = 128; s > 0; s >>= 1) { if (c < s) red[c] += red[c + s]; __syncthreads(); }
    float var = red[0] * (1.f / 768.f);
    float z = d * rsqrtf(var + 1e-5f) * lng[c] + lnb[c];
    g_s[c] = 1.f / (1.f + expf(-z));
}
__global__ void k_x2()
{
    int idx = (blockIdx.x * 256 + threadIdx.x) * 4;
    int c = idx % EE;
    float4 v = *(const float4*)&g_cat[idx];
    float4 s = *(const float4*)&g_s[c];
    float4 r; r.x = v.x * s.x; r.y = v.y * s.y; r.z = v.z * s.z; r.w = v.w * s.w;
    *(float4*)&g_x2[idx] = r;
}
__global__ void k_colmax()
{
    int rr = blockIdx.x, t = threadIdx.x;  // 384 x 256
    float m = -1e30f;
    for (int i = t; i < 4096; i += 256) m = fmaxf(m, g_q2[(size_t)i * 384 + rr]);
    __shared__ float red[256];
    red[t] = m; __syncthreads();
    for (int s = 128; s > 0; s >>= 1) { if (t < s) red[t] = fmaxf(red[t], red[t + s]); __syncthreads(); }
    if (t == 0) g_mx[rr] = red[0];
}
__global__ void k_softmax384()
{
    int t = threadIdx.x;  // 384
    __shared__ float b[384];
    __shared__ float mx, sm;
    b[t] = g_mx[t]; __syncthreads();
    if (t == 0) { float m = b[0]; for (int i = 1; i < 384; i++) m = fmaxf(m, b[i]); mx = m; }
    __syncthreads();
    float e = expf(b[t] - mx);
    b[t] = e; __syncthreads();
    if (t == 0) { float s = 0; for (int i = 0; i < 384; i++) s += b[i]; sm = s; }
    __syncthreads();
    g_wq2[t] = e / sm;
}
__global__ void k_u(const float* __restrict__ spv)
{
    int c = threadIdx.x;  // 768
    float s = 0;
    for (int r = 0; r < 384; r++) s += g_wq2[r] * spv[r * EE + c];
    g_u[c] = s;
}
// wz2 = sigmoid(u . x2[hw]); v = wz2*x2 + cat + x5; channel layernorm -> out
__global__ void k_final(const float* __restrict__ x5, const float* __restrict__ ng,
                        const float* __restrict__ nb, float* __restrict__ out)
{
    int hw = blockIdx.x, t = threadIdx.x;  // 256
    __shared__ float v[768];
    __shared__ float red[256];
    const float* x2r = g_x2 + (size_t)hw * EE;
    const float* catr = g_cat + (size_t)hw * EE;
    const float* x5r = x5 + (size_t)hw * EE;
    float d = 0;
    for (int c = t; c < 768; c += 256) d += g_u[c] * x2r[c];
    red[t] = d; __syncthreads();
    for (int s = 128; s > 0; s >>= 1) { if (t < s) red[t] += red[t + s]; __syncthreads(); }
    float wz2 = 1.f / (1.f + expf(-red[0])); __syncthreads();
    float ls = 0;
    for (int c = t; c < 768; c += 256) { float val = wz2 * x2r[c] + catr[c] + x5r[c]; v[c] = val; ls += val; }
    red[t] = ls; __syncthreads();
    for (int s = 128; s > 0; s >>= 1) { if (t < s) red[t] += red[t + s]; __syncthreads(); }
    float mu = red[0] * (1.f / 768.f); __syncthreads();
    float lq = 0;
    for (int c = t; c < 768; c += 256) { float dd = v[c] - mu; lq += dd * dd; }
    red[t] = lq; __syncthreads();
    for (int s = 128; s > 0; s >>= 1) { if (t < s) red[t] += red[t + s]; __syncthreads(); }
    float rstd = rsqrtf(red[0] * (1.f / 768.f) + 1e-5f); __syncthreads();
    for (int c = t; c < 768; c += 256) out[(size_t)hw * EE + c] = (v[c] - mu) * rstd * ng[c] + nb[c];
}

extern "C" void kernel_launch(void* const* d_in, const int* in_sizes, int n_in,
                              void* d_out, int out_size)
{
    const float* x[5];
    for (int i = 0; i < 5; i++) x[i] = (const float*)d_in[i];
    const float* convw = (const float*)d_in[5];
    const float* convb = (const float*)d_in[6];
    const float* offw = (const float*)d_in[7];
    const float* offb = (const float*)d_in[8];
    const float* mskw = (const float*)d_in[9];
    const float* mskb = (const float*)d_in[10];
    const float* bng = (const float*)d_in[11];
    const float* bnb = (const float*)d_in[12];
    const float* chq = (const float*)d_in[13];
    const float* chv = (const float*)d_in[14];
    const float* chz = (const float*)d_in[15];
    const float* lng = (const float*)d_in[16];
    const float* lnb = (const float*)d_in[17];
    const float* spq = (const float*)d_in[18];
    const float* spv = (const float*)d_in[19];
    const float* wsrc[8] = {(const float*)d_in[20], (const float*)d_in[21], (const float*)d_in[22],
                            (const float*)d_in[24], (const float*)d_in[26], (const float*)d_in[23],
                            (const float*)d_in[25], (const float*)d_in[27]};
    const float* normg = (const float*)d_in[28];
    const float* normb = (const float*)d_in[29];

    float *pC, *pW, *pOw, *pBoff, *pWT, *pSpqT, *pCat, *pAct, *pX2, *pQ2, *pQ, *pT, *pR, *pWz;
    cudaGetSymbolAddress((void**)&pC, g_C);
    cudaGetSymbolAddress((void**)&pW, g_Wbig);
    cudaGetSymbolAddress((void**)&pOw, g_ow);
    cudaGetSymbolAddress((void**)&pBoff, g_boff);
    cudaGetSymbolAddress((void**)&pWT, g_wT);
    cudaGetSymbolAddress((void**)&pSpqT, g_spqT);
    cudaGetSymbolAddress((void**)&pCat, g_cat);
    cudaGetSymbolAddress((void**)&pAct, g_act);
    cudaGetSymbolAddress((void**)&pX2, g_x2);
    cudaGetSymbolAddress((void**)&pQ2, g_q2);
    cudaGetSymbolAddress((void**)&pQ, g_q);
    cudaGetSymbolAddress((void**)&pT, g_t);
    cudaGetSymbolAddress((void**)&pR, g_r);
    cudaGetSymbolAddress((void**)&pWz, g_wz);

    // ---- prep ----
    k_prep_ow<<<(27 * EE + 255) / 256, 256>>>(offw, mskw);
    k_gemv<<<18, 128>>>(pOw, convb, offb, pBoff, 768);
    k_gemv<<<9, 128>>>(pOw + 18 * 768, convb, mskb, pBoff + 18, 768);
    int tot = EE * 6912 + 27 * 6912;
    k_build_wbig<<<(tot + 255) / 256, 256>>>(convw);
    // column layout in g_wT (LDWT=1536): a-weights [0,30) [32,132) [132,282) [284,504) [504,772)
    //                                    b-weights [772,922) [924,1144) [1148,1416)  -- no overlap
    int wM[8] = {30, 100, 150, 220, 268, 150, 220, 268};
    int wOff[8] = {0, 32, 132, 284, 504, 772, 924, 1148};
    for (int i = 0; i < 8; i++)
        k_transpose<<<(wM[i] * 768 + 255) / 256, 256>>>(wsrc[i], pWT, wM[i], LDWT, wOff[i]);
    k_transpose<<<(384 * 768 + 255) / 256, 256>>>(spq, pSpqT, 384, 384, 0);

    // ---- 5 blocks ----
    int chOff[5] = {0, 30, 130, 280, 500}, chN[5] = {30, 100, 150, 220, 268};
    int aOff[5] = {0, 32, 132, 284, 504}, bOff[5] = {0, 0, 772, 924, 1148};
    for (int b = 0; b < 5; b++) {
        dim3 g1((NCOL + 127) / 128, 32);
        k_sgemm<<<g1, 256>>>(x[b], 768, pW, LDC, pC, LDC, HW, NCOL, 768, 0);
        k_offmask<<<HW, 32>>>();
        k_deform_gather<<<HW, 192>>>(convb);
        k_bn_partial<<<32, 256>>>();
        k_bn_final<<<1, 768>>>(bng, bnb);
        k_bn_relu<<<HW * EE / 1024, 256>>>();
        dim3 g2((chN[b] + 127) / 128, 32);
        k_sgemm<<<g2, 256>>>(pAct, 768, pWT + aOff[b], LDWT, pCat + chOff[b], 768, HW, chN[b], 768, 0);
        if (b >= 2)
            k_sgemm<<<g2, 256>>>(x[b], 768, pWT + bOff[b], LDWT, pCat + chOff[b], 768, HW, chN[b], 768, 1);
    }

    // ---- CAM ----
    k_gemv<<<HW, 128>>>(pCat, chq, nullptr, pQ, 768);
    k_softmax_hw<<<1, 1024>>>();
    k_poolw<<<32, 256>>>();
    k_pool_fin<<<1, 768>>>();
    k_gemv<<<384, 128>>>(chv, pT, nullptr, pR, 768);
    k_gemv<<<768, 128>>>(chz, pR, nullptr, pWz, 384);
    k_ln_sigmoid<<<1, 768>>>(lng, lnb);
    k_x2<<<HW * EE / 1024, 256>>>();
    dim3 g3((384 + 127) / 128, 32);
    k_sgemm<<<g3, 256>>>(pX2, 768, pSpqT, 384, pQ2, 384, HW, 384, 768, 0);
    k_colmax<<<384, 256>>>();
    k_softmax384<<<1, 384>>>();
    k_u<<<1, 768>>>(spv);
    k_final<<<HW, 256>>>(x[4], normg, normb, (float*)d_out);
}

// round 7
// speedup vs baseline: 2.0739x; 2.0739x over previous
#include <cuda_runtime.h>
#include <cuda_bf16.h>
#include <math.h>
#include <stdint.h>

#define HW 4096
#define EE 768
#define NCOL 7155
#define LDC 7168
#define LDWT 1536
#define KSPLIT 1536   // [hi(768) | lo(768)] bf16 per row

static __device__ float g_C[(size_t)HW * LDC];
static __device__ __nv_bfloat16 g_Ah[(size_t)HW * KSPLIT];      // A split  [m][hi|lo]
static __device__ __nv_bfloat16 g_Bh[(size_t)LDC * KSPLIT];     // B split  [n][hi|lo]
static __device__ float g_ow[27 * EE];
static __device__ float g_boff[27];
static __device__ float g_off[HW * 18];
static __device__ float g_mask[HW * 9];
static __device__ float g_blk[(size_t)HW * EE];
static __device__ float g_act[(size_t)HW * EE];
static __device__ float g_cat[(size_t)HW * EE];
static __device__ float g_x2[(size_t)HW * EE];
static __device__ float g_wT[EE * LDWT];
static __device__ float g_spqT[EE * 384];
static __device__ float g_q2[(size_t)HW * 384];
static __device__ float g_ps[32 * EE], g_pq[32 * EE], g_sc[EE], g_sh[EE];
static __device__ float g_q[HW], g_wq[HW];
static __device__ float g_pt[32 * EE], g_t[EE], g_r[384], g_wz[EE], g_s[EE];
static __device__ float g_mx[384], g_wq2[384], g_u[EE];

// ================= helpers =================
__device__ __forceinline__ uint32_t smem_u32(const void* p) {
    uint32_t a;
    asm("{ .reg .u64 t; cvta.to.shared.u64 t, %1; cvt.u32.u64 %0, t; }" : "=r"(a) : "l"(p));
    return a;
}
__device__ __forceinline__ void cp16(uint32_t dst, const void* src) {
    asm volatile("cp.async.cg.shared.global [%0], [%1], 16;" :: "r"(dst), "l"(src) : "memory");
}
template <int N> __device__ __forceinline__ void cp_wait() {
    asm volatile("cp.async.wait_group %0;" :: "n"(N) : "memory");
}
__device__ __forceinline__ void ldm_x4(uint32_t& r0, uint32_t& r1, uint32_t& r2, uint32_t& r3,
                                       uint32_t addr) {
    asm volatile("ldmatrix.sync.aligned.m8n8.x4.shared.b16 {%0,%1,%2,%3}, [%4];"
                 : "=r"(r0), "=r"(r1), "=r"(r2), "=r"(r3) : "r"(addr));
}
__device__ __forceinline__ void mma16816(float& d0, float& d1, float& d2, float& d3,
                                         uint32_t a0, uint32_t a1, uint32_t a2, uint32_t a3,
                                         uint32_t b0, uint32_t b1) {
    asm volatile(
        "mma.sync.aligned.m16n8k16.row.col.f32.bf16.bf16.f32 "
        "{%0,%1,%2,%3}, {%4,%5,%6,%7}, {%8,%9}, {%0,%1,%2,%3};"
        : "+f"(d0), "+f"(d1), "+f"(d2), "+f"(d3)
        : "r"(a0), "r"(a1), "r"(a2), "r"(a3), "r"(b0), "r"(b1));
}
#define SWZ128(x) ((x) ^ (((x) >> 3) & 0x70))

// chunk -> K offset (3 split segments: ah*bh, ah*bl, al*bh), 64 bf16 per chunk
__device__ __forceinline__ void chunk_koffs(int chunk, int& kA, int& kB) {
    kA = (chunk < 12) ? chunk * 64 : (chunk < 24 ? (chunk - 12) * 64 : 768 + (chunk - 24) * 64);
    kB = (chunk < 12) ? chunk * 64 : (chunk < 24 ? 768 + (chunk - 12) * 64 : (chunk - 24) * 64);
}

// 256 threads: tid<128 loads A row (row0+tid), else B row (col0+tid-128). 8x16B per row, SW128.
__device__ __forceinline__ void load_chunk(uint32_t sbase, int s, int chunk,
                                           int row0, int col0, int tid) {
    int kA, kB;
    chunk_koffs(chunk, kA, kB);
    int r = tid & 127;
    bool isB = tid >= 128;
    const __nv_bfloat16* g = isB ? &g_Bh[(size_t)(col0 + r) * KSPLIT + kB]
                                 : &g_Ah[(size_t)(row0 + r) * KSPLIT + kA];
    uint32_t base = sbase + s * 32768 + (isB ? 16384 : 0);
    int rb = r * 128;
#pragma unroll
    for (int seg = 0; seg < 8; seg++)
        cp16(base + SWZ128(rb + seg * 16), g + seg * 8);
    asm volatile("cp.async.commit_group;" ::: "memory");
}

// ========== main GEMM: C[4096 x 7168] = split-fp32 A @ B^T via mma.sync bf16 ==========
__global__ __launch_bounds__(256, 2)
void k_mma_main(float* __restrict__ C)
{
    extern __shared__ char smem_raw[];   // 2 stages x (16KB A + 16KB B) = 64KB
    uint32_t sbase = smem_u32(smem_raw);
    int tid = threadIdx.x, wid = tid >> 5, lane = tid & 31;
    int row0 = blockIdx.y * 128, col0 = blockIdx.x * 128;
    int wm = (wid & 1) * 64;      // warp m offset in tile
    int wn = (wid >> 1) * 32;     // warp n offset in tile

    float acc[4][4][4];
#pragma unroll
    for (int i = 0; i < 4; i++)
#pragma unroll
        for (int j = 0; j < 4; j++)
#pragma unroll
            for (int k = 0; k < 4; k++) acc[i][j][k] = 0.f;

    // prologue: chunks 0,1 -> stages 0,1
    load_chunk(sbase, 0, 0, row0, col0, tid);
    load_chunk(sbase, 1, 1, row0, col0, tid);

    for (int it = 0; it < 36; it++) {
        int s = it & 1;
        if (it < 35) cp_wait<1>(); else cp_wait<0>();
        __syncthreads();
        uint32_t abase = sbase + s * 32768;
        uint32_t bbase = abase + 16384;
#pragma unroll
        for (int k16 = 0; k16 < 4; k16++) {
            uint32_t b[4][2];
#pragma unroll
            for (int nb2 = 0; nb2 < 2; nb2++) {
                int n_row = wn + nb2 * 16 + (lane & 7) + ((lane >> 4) << 3);
                int k_byte = k16 * 32 + ((lane >> 3) & 1) * 16;
                uint32_t addr = bbase + SWZ128(n_row * 128 + k_byte);
                ldm_x4(b[nb2 * 2][0], b[nb2 * 2][1], b[nb2 * 2 + 1][0], b[nb2 * 2 + 1][1], addr);
            }
#pragma unroll
            for (int mf = 0; mf < 4; mf++) {
                int m_row = wm + mf * 16 + (lane & 15);
                int k_byte = k16 * 32 + (lane >> 4) * 16;
                uint32_t addr = abase + SWZ128(m_row * 128 + k_byte);
                uint32_t a0, a1, a2, a3;
                ldm_x4(a0, a1, a2, a3, addr);
#pragma unroll
                for (int nf = 0; nf < 4; nf++)
                    mma16816(acc[mf][nf][0], acc[mf][nf][1], acc[mf][nf][2], acc[mf][nf][3],
                             a0, a1, a2, a3, b[nf][0], b[nf][1]);
            }
        }
        __syncthreads();
        if (it + 2 < 36) load_chunk(sbase, s, it + 2, row0, col0, tid);
    }

    // epilogue: direct fp32 stores (m16n8 C fragment mapping)
    int rr = lane >> 2, cc = (lane & 3) * 2;
#pragma unroll
    for (int mf = 0; mf < 4; mf++) {
#pragma unroll
        for (int nf = 0; nf < 4; nf++) {
            int r = row0 + wm + mf * 16 + rr;
            int c = col0 + wn + nf * 8 + cc;
            *(float2*)&C[(size_t)r * LDC + c] = make_float2(acc[mf][nf][0], acc[mf][nf][1]);
            *(float2*)&C[(size_t)(r + 8) * LDC + c] = make_float2(acc[mf][nf][2], acc[mf][nf][3]);
        }
    }
}

// ---------- split builders ----------
__global__ void k_splitA(const float* __restrict__ x)
{
    int idx = blockIdx.x * 256 + threadIdx.x;
    if (idx < HW * EE) {
        int m = idx / EE, c = idx % EE;
        float v = x[idx];
        __nv_bfloat16 h = __float2bfloat16(v);
        g_Ah[(size_t)m * KSPLIT + c] = h;
        g_Ah[(size_t)m * KSPLIT + 768 + c] = __float2bfloat16(v - __bfloat162float(h));
    }
}
__global__ void k_buildB(const float* __restrict__ convw)
{
    int idx = blockIdx.x * 256 + threadIdx.x;
    if (idx >= LDC * EE) return;
    int n = idx / EE, c = idx % EE;
    float v;
    if (n < 6912) {
        int kk = n / 768, o = n % 768;
        v = convw[((size_t)o * 768 + c) * 9 + kk];
    } else if (n < NCOL) {
        int j = (n - 6912) / 9, kk = (n - 6912) % 9;
        float s = 0.f;
        for (int o = 0; o < 768; o++) s += g_ow[j * 768 + o] * convw[((size_t)o * 768 + c) * 9 + kk];
        v = s;
    } else v = 0.f;
    __nv_bfloat16 h = __float2bfloat16(v);
    g_Bh[(size_t)n * KSPLIT + c] = h;
    g_Bh[(size_t)n * KSPLIT + 768 + c] = __float2bfloat16(v - __bfloat162float(h));
}

// ---------- SIMT SGEMM for the small projections ----------
__global__ __launch_bounds__(256, 2)
void k_sgemm(const float* __restrict__ A, int lda, const float* __restrict__ B, int ldb,
             float* __restrict__ C, int ldc, int M, int N, int K, int accum)
{
    __shared__ float As[16][128];
    __shared__ float Bs[16][128];
    int tid = threadIdx.x;
    int row0 = blockIdx.y * 128, col0 = blockIdx.x * 128;
    int tx = tid & 15, ty = tid >> 4;
    float acc[8][8];
#pragma unroll
    for (int i = 0; i < 8; i++)
#pragma unroll
        for (int j = 0; j < 8; j++) acc[i][j] = 0.f;
    int arow = tid >> 2, acol = (tid & 3) << 2;
    int brow = tid >> 5, bcol = (tid & 31) << 2;
    for (int k0 = 0; k0 < K; k0 += 16) {
#pragma unroll
        for (int h = 0; h < 2; h++) {
            int r = arow + h * 64, gr = row0 + r;
            float4 v = make_float4(0.f, 0.f, 0.f, 0.f);
            if (gr < M) v = *(const float4*)(A + (size_t)gr * lda + k0 + acol);
            As[acol + 0][r] = v.x; As[acol + 1][r] = v.y;
            As[acol + 2][r] = v.z; As[acol + 3][r] = v.w;
        }
#pragma unroll
        for (int h = 0; h < 2; h++) {
            int r = brow + h * 8;
            const float* Bp = B + (size_t)(k0 + r) * ldb;
            int gc = col0 + bcol;
            float4 v = make_float4(0.f, 0.f, 0.f, 0.f);
            if (gc + 3 < N) v = *(const float4*)(Bp + gc);
            else {
                if (gc + 0 < N) v.x = Bp[gc + 0];
                if (gc + 1 < N) v.y = Bp[gc + 1];
                if (gc + 2 < N) v.z = Bp[gc + 2];
                if (gc + 3 < N) v.w = Bp[gc + 3];
            }
            *(float4*)&Bs[r][bcol] = v;
        }
        __syncthreads();
#pragma unroll
        for (int kk = 0; kk < 16; kk++) {
            float a[8], b[8];
            *(float4*)&a[0] = *(const float4*)&As[kk][ty * 8];
            *(float4*)&a[4] = *(const float4*)&As[kk][ty * 8 + 4];
            *(float4*)&b[0] = *(const float4*)&Bs[kk][tx * 8];
            *(float4*)&b[4] = *(const float4*)&Bs[kk][tx * 8 + 4];
#pragma unroll
            for (int i = 0; i < 8; i++)
#pragma unroll
                for (int j = 0; j < 8; j++) acc[i][j] = fmaf(a[i], b[j], acc[i][j]);
        }
        __syncthreads();
    }
#pragma unroll
    for (int i = 0; i < 8; i++) {
        int r = row0 + ty * 8 + i;
        if (r >= M) continue;
        float* Cp = C + (size_t)r * ldc;
#pragma unroll
        for (int j = 0; j < 8; j++) {
            int cc = col0 + tx * 8 + j;
            if (cc < N) { float v = acc[i][j]; Cp[cc] = accum ? Cp[cc] + v : v; }
        }
    }
}

__global__ void k_gemv(const float* __restrict__ W, const float* __restrict__ x,
                       const float* __restrict__ bias, float* __restrict__ y, int K)
{
    int m = blockIdx.x, t = threadIdx.x;
    float a = 0.f;
    for (int k = t; k < K; k += 128) a += W[(size_t)m * K + k] * x[k];
    __shared__ float red[128];
    red[t] = a; __syncthreads();
    for (int s = 64; s > 0; s >>= 1) { if (t < s) red[t] += red[t + s]; __syncthreads(); }
    if (t == 0) y[m] = red[0] + (bias ? bias[m] : 0.f);
}

__global__ void k_transpose(const float* __restrict__ src, float* __restrict__ dst,
                            int M, int ldd, int coloff)
{
    int i = blockIdx.x * 256 + threadIdx.x;
    if (i < M * 768) { int m = i / 768, c = i % 768; dst[(size_t)c * ldd + coloff + m] = src[i]; }
}

__global__ void k_prep_ow(const float* __restrict__ offw, const float* __restrict__ mskw)
{
    int i = blockIdx.x * 256 + threadIdx.x;
    if (i < 27 * EE) { int j = i / EE, c = i % EE; g_ow[i] = (j < 18) ? offw[j * EE + c] : mskw[(j - 18) * EE + c]; }
}

__global__ void k_offmask()
{
    int hw = blockIdx.x, y = hw >> 6, x = hw & 63;
    int j = threadIdx.x;
    __shared__ float lg[9];
    __shared__ float mx_s, sum_s;
    if (j < 27) {
        float v = g_boff[j];
#pragma unroll
        for (int k = 0; k < 9; k++) {
            int yy = y + k / 3 - 1, xx = x + k % 3 - 1;
            if (yy >= 0 && yy < 64 && xx >= 0 && xx < 64)
                v += g_C[(size_t)(yy * 64 + xx) * LDC + 6912 + j * 9 + k];
        }
        if (j < 18) g_off[hw * 18 + j] = v; else lg[j - 18] = v;
    }
    __syncthreads();
    if (j == 0) {
        float mx = lg[0];
        for (int t = 1; t < 9; t++) mx = fmaxf(mx, lg[t]);
        float s = 0.f;
        for (int t = 0; t < 9; t++) s += expf(lg[t] - mx);
        mx_s = mx; sum_s = s;
    }
    __syncthreads();
    if (j < 9) g_mask[hw * 9 + j] = expf(lg[j] - mx_s) / sum_s;
}

__global__ __launch_bounds__(192)
void k_deform_gather(const float* __restrict__ convb)
{
    int hw = blockIdx.x, y = hw >> 6, x = hw & 63;
    __shared__ int sidx[9][4];
    __shared__ float swgt[9][4];
    int tid = threadIdx.x;
    if (tid < 9) {
        int k = tid;
        float dy = g_off[hw * 18 + 2 * k], dx = g_off[hw * 18 + 2 * k + 1];
        float m = g_mask[k * HW + hw];  // raw-reshape mask indexing
        float py = (float)(y + k / 3 - 1) + dy;
        float px = (float)(x + k % 3 - 1) + dx;
        float y0f = floorf(py), x0f = floorf(px);
        float wy1 = py - y0f, wx1 = px - x0f;
        int y0 = (int)y0f, x0 = (int)x0f;
#pragma unroll
        for (int c = 0; c < 4; c++) {
            int yy = y0 + (c >> 1), xx = x0 + (c & 1);
            bool valid = (yy >= 0 && yy <= 63 && xx >= 0 && xx <= 63);
            int yc = min(max(yy, 0), 63), xc = min(max(xx, 0), 63);
            float w = ((c >> 1) ? wy1 : 1.f - wy1) * ((c & 1) ? wx1 : 1.f - wx1);
            sidx[k][c] = yc * 64 + xc;
            swgt[k][c] = valid ? w * m : 0.f;
        }
    }
    __syncthreads();
    int o = tid * 4;
    float4 acc = *(const float4*)(convb + o);
#pragma unroll
    for (int k = 0; k < 9; k++) {
        size_t cb = (size_t)k * EE + o;
#pragma unroll
        for (int c = 0; c < 4; c++) {
            float w = swgt[k][c];
            const float4 v = *(const float4*)(&g_C[(size_t)sidx[k][c] * LDC + cb]);
            acc.x = fmaf(w, v.x, acc.x); acc.y = fmaf(w, v.y, acc.y);
            acc.z = fmaf(w, v.z, acc.z); acc.w = fmaf(w, v.w, acc.w);
        }
    }
    *(float4*)(&g_blk[(size_t)hw * EE + o]) = acc;
}

__global__ void k_bn_partial()
{
    int b = blockIdx.x, t = threadIdx.x;
    float s0 = 0, s1 = 0, s2 = 0, q0 = 0, q1 = 0, q2v = 0;
    for (int r = 0; r < 128; r++) {
        const float* row = &g_blk[(size_t)(b * 128 + r) * EE];
        float v0 = row[t], v1 = row[t + 256], v2 = row[t + 512];
        s0 += v0; s1 += v1; s2 += v2; q0 += v0 * v0; q1 += v1 * v1; q2v += v2 * v2;
    }
    g_ps[b * EE + t] = s0; g_ps[b * EE + t + 256] = s1; g_ps[b * EE + t + 512] = s2;
    g_pq[b * EE + t] = q0; g_pq[b * EE + t + 256] = q1; g_pq[b * EE + t + 512] = q2v;
}
__global__ void k_bn_final(const float* __restrict__ bng, const float* __restrict__ bnb)
{
    int c = threadIdx.x;
    float s = 0, q = 0;
    for (int b = 0; b < 32; b++) { s += g_ps[b * EE + c]; q += g_pq[b * EE + c]; }
    float mu = s * (1.f / 4096.f);
    float var = q * (1.f / 4096.f) - mu * mu;
    float sc = rsqrtf(var + 1e-5f) * bng[c];
    g_sc[c] = sc; g_sh[c] = bnb[c] - mu * sc;
}
__global__ void k_bn_relu()
{
    int idx = (blockIdx.x * 256 + threadIdx.x) * 4;
    int c = idx % EE;
    float4 v = *(const float4*)&g_blk[idx];
    float4 sc = *(const float4*)&g_sc[c];
    float4 sh = *(const float4*)&g_sh[c];
    float4 r;
    r.x = fmaxf(0.f, fmaf(v.x, sc.x, sh.x)); r.y = fmaxf(0.f, fmaf(v.y, sc.y, sh.y));
    r.z = fmaxf(0.f, fmaf(v.z, sc.z, sh.z)); r.w = fmaxf(0.f, fmaf(v.w, sc.w, sh.w));
    *(float4*)&g_act[idx] = r;
}

__global__ void k_softmax_hw()
{
    __shared__ float sm[4096];
    __shared__ float red[1024];
    int t = threadIdx.x;
    float lm = -1e30f;
    for (int i = t; i < 4096; i += 1024) { float v = g_q[i]; sm[i] = v; lm = fmaxf(lm, v); }
    red[t] = lm; __syncthreads();
    for (int s = 512; s > 0; s >>= 1) { if (t < s) red[t] = fmaxf(red[t], red[t + s]); __syncthreads(); }
    float mx = red[0]; __syncthreads();
    float ls = 0.f;
    for (int i = t; i < 4096; i += 1024) { float e = expf(sm[i] - mx); sm[i] = e; ls += e; }
    red[t] = ls; __syncthreads();
    for (int s = 512; s > 0; s >>= 1) { if (t < s) red[t] += red[t + s]; __syncthreads(); }
    float inv = 1.f / red[0]; __syncthreads();
    for (int i = t; i < 4096; i += 1024) g_wq[i] = sm[i] * inv;
}
__global__ void k_poolw()
{
    int b = blockIdx.x, t = threadIdx.x;
    float a0 = 0, a1 = 0, a2 = 0;
    for (int r = 0; r < 128; r++) {
        int hw = b * 128 + r;
        float w = g_wq[hw];
        const float* row = &g_cat[(size_t)hw * EE];
        a0 += w * row[t]; a1 += w * row[t + 256]; a2 += w * row[t + 512];
    }
    g_pt[b * EE + t] = a0; g_pt[b * EE + t + 256] = a1; g_pt[b * EE + t + 512] = a2;
}
__global__ void k_pool_fin()
{
    int c = threadIdx.x;
    float s = 0;
    for (int b = 0; b < 32; b++) s += g_pt[b * EE + c];
    g_t[c] = s;
}
__global__ void k_ln_sigmoid(const float* __restrict__ lng, const float* __restrict__ lnb)
{
    int c = threadIdx.x;
    __shared__ float buf[768];
    __shared__ float red[256];
    float v = g_wz[c];
    buf[c] = v; __syncthreads();
    if (c < 256) red[c] = buf[c] + buf[c + 256] + buf[c + 512];
    __syncthreads();
    for (int s = 128; s > 0; s >>= 1) { if (c < s) red[c] += red[c + s]; __syncthreads(); }
    float mu = red[0] * (1.f / 768.f); __syncthreads();
    float d = v - mu;
    buf[c] = d * d; __syncthreads();
    if (c < 256) red[c] = buf[c] + buf[c + 256] + buf[c + 512];
    __syncthreads();
    for (int s = 128; s > 0; s >>= 1) { if (c < s) red[c] += red[c + s]; __syncthreads(); }
    float var = red[0] * (1.f / 768.f);
    float z = d * rsqrtf(var + 1e-5f) * lng[c] + lnb[c];
    g_s[c] = 1.f / (1.f + expf(-z));
}
__global__ void k_x2()
{
    int idx = (blockIdx.x * 256 + threadIdx.x) * 4;
    int c = idx % EE;
    float4 v = *(const float4*)&g_cat[idx];
    float4 s = *(const float4*)&g_s[c];
    float4 r; r.x = v.x * s.x; r.y = v.y * s.y; r.z = v.z * s.z; r.w = v.w * s.w;
    *(float4*)&g_x2[idx] = r;
}
__global__ void k_colmax()
{
    int rr = blockIdx.x, t = threadIdx.x;
    float m = -1e30f;
    for (int i = t; i < 4096; i += 256) m = fmaxf(m, g_q2[(size_t)i * 384 + rr]);
    __shared__ float red[256];
    red[t] = m; __syncthreads();
    for (int s = 128; s > 0; s >>= 1) { if (t < s) red[t] = fmaxf(red[t], red[t + s]); __syncthreads(); }
    if (t == 0) g_mx[rr] = red[0];
}
__global__ void k_softmax384()
{
    int t = threadIdx.x;
    __shared__ float b[384];
    __shared__ float mx, sm;
    b[t] = g_mx[t]; __syncthreads();
    if (t == 0) { float m = b[0]; for (int i = 1; i < 384; i++) m = fmaxf(m, b[i]); mx = m; }
    __syncthreads();
    float e = expf(b[t] - mx);
    b[t] = e; __syncthreads();
    if (t == 0) { float s = 0; for (int i = 0; i < 384; i++) s += b[i]; sm = s; }
    __syncthreads();
    g_wq2[t] = e / sm;
}
__global__ void k_u(const float* __restrict__ spv)
{
    int c = threadIdx.x;
    float s = 0;
    for (int r = 0; r < 384; r++) s += g_wq2[r] * spv[r * EE + c];
    g_u[c] = s;
}
__global__ void k_final(const float* __restrict__ x5, const float* __restrict__ ng,
                        const float* __restrict__ nb, float* __restrict__ out)
{
    int hw = blockIdx.x, t = threadIdx.x;
    __shared__ float v[768];
    __shared__ float red[256];
    const float* x2r = g_x2 + (size_t)hw * EE;
    const float* catr = g_cat + (size_t)hw * EE;
    const float* x5r = x5 + (size_t)hw * EE;
    float d = 0;
    for (int c = t; c < 768; c += 256) d += g_u[c] * x2r[c];
    red[t] = d; __syncthreads();
    for (int s = 128; s > 0; s >>= 1) { if (t < s) red[t] += red[t + s]; __syncthreads(); }
    float wz2 = 1.f / (1.f + expf(-red[0])); __syncthreads();
    float ls = 0;
    for (int c = t; c < 768; c += 256) { float val = wz2 * x2r[c] + catr[c] + x5r[c]; v[c] = val; ls += val; }
    red[t] = ls; __syncthreads();
    for (int s = 128; s > 0; s >>= 1) { if (t < s) red[t] += red[t + s]; __syncthreads(); }
    float mu = red[0] * (1.f / 768.f); __syncthreads();
    float lq = 0;
    for (int c = t; c < 768; c += 256) { float dd = v[c] - mu; lq += dd * dd; }
    red[t] = lq; __syncthreads();
    for (int s = 128; s > 0; s >>= 1) { if (t < s) red[t] += red[t + s]; __syncthreads(); }
    float rstd = rsqrtf(red[0] * (1.f / 768.f) + 1e-5f); __syncthreads();
    for (int c = t; c < 768; c += 256) out[(size_t)hw * EE + c] = (v[c] - mu) * rstd * ng[c] + nb[c];
}

extern "C" void kernel_launch(void* const* d_in, const int* in_sizes, int n_in,
                              void* d_out, int out_size)
{
    const float* x[5];
    for (int i = 0; i < 5; i++) x[i] = (const float*)d_in[i];
    const float* convw = (const float*)d_in[5];
    const float* convb = (const float*)d_in[6];
    const float* offw = (const float*)d_in[7];
    const float* offb = (const float*)d_in[8];
    const float* mskw = (const float*)d_in[9];
    const float* mskb = (const float*)d_in[10];
    const float* bng = (const float*)d_in[11];
    const float* bnb = (const float*)d_in[12];
    const float* chq = (const float*)d_in[13];
    const float* chv = (const float*)d_in[14];
    const float* chz = (const float*)d_in[15];
    const float* lng = (const float*)d_in[16];
    const float* lnb = (const float*)d_in[17];
    const float* spq = (const float*)d_in[18];
    const float* spv = (const float*)d_in[19];
    const float* wsrc[8] = {(const float*)d_in[20], (const float*)d_in[21], (const float*)d_in[22],
                            (const float*)d_in[24], (const float*)d_in[26], (const float*)d_in[23],
                            (const float*)d_in[25], (const float*)d_in[27]};
    const float* normg = (const float*)d_in[28];
    const float* normb = (const float*)d_in[29];

    float *pC, *pOw, *pBoff, *pWT, *pSpqT, *pCat, *pAct, *pX2, *pQ2, *pQ, *pT, *pR, *pWz;
    cudaGetSymbolAddress((void**)&pC, g_C);
    cudaGetSymbolAddress((void**)&pOw, g_ow);
    cudaGetSymbolAddress((void**)&pBoff, g_boff);
    cudaGetSymbolAddress((void**)&pWT, g_wT);
    cudaGetSymbolAddress((void**)&pSpqT, g_spqT);
    cudaGetSymbolAddress((void**)&pCat, g_cat);
    cudaGetSymbolAddress((void**)&pAct, g_act);
    cudaGetSymbolAddress((void**)&pX2, g_x2);
    cudaGetSymbolAddress((void**)&pQ2, g_q2);
    cudaGetSymbolAddress((void**)&pQ, g_q);
    cudaGetSymbolAddress((void**)&pT, g_t);
    cudaGetSymbolAddress((void**)&pR, g_r);
    cudaGetSymbolAddress((void**)&pWz, g_wz);

    const int SMEM_MAIN = 2 * 32768;
    cudaFuncSetAttribute(k_mma_main, cudaFuncAttributeMaxDynamicSharedMemorySize, SMEM_MAIN);

    // ---- prep ----
    k_prep_ow<<<(27 * EE + 255) / 256, 256>>>(offw, mskw);
    k_gemv<<<18, 128>>>(pOw, convb, offb, pBoff, 768);
    k_gemv<<<9, 128>>>(pOw + 18 * 768, convb, mskb, pBoff + 18, 768);
    k_buildB<<<(LDC * EE + 255) / 256, 256>>>(convw);
    int wM[8] = {30, 100, 150, 220, 268, 150, 220, 268};
    int wOff[8] = {0, 32, 132, 284, 504, 772, 924, 1148};
    for (int i = 0; i < 8; i++)
        k_transpose<<<(wM[i] * 768 + 255) / 256, 256>>>(wsrc[i], pWT, wM[i], LDWT, wOff[i]);
    k_transpose<<<(384 * 768 + 255) / 256, 256>>>(spq, pSpqT, 384, 384, 0);

    // ---- 5 blocks ----
    int chOff[5] = {0, 30, 130, 280, 500}, chN[5] = {30, 100, 150, 220, 268};
    int aOff[5] = {0, 32, 132, 284, 504}, bOff[5] = {0, 0, 772, 924, 1148};
    for (int b = 0; b < 5; b++) {
        k_splitA<<<(HW * EE + 255) / 256, 256>>>(x[b]);
        k_mma_main<<<dim3(56, 32), 256, SMEM_MAIN>>>(pC);
        k_offmask<<<HW, 32>>>();
        k_deform_gather<<<HW, 192>>>(convb);
        k_bn_partial<<<32, 256>>>();
        k_bn_final<<<1, 768>>>(bng, bnb);
        k_bn_relu<<<HW * EE / 1024, 256>>>();
        dim3 g2((chN[b] + 127) / 128, 32);
        k_sgemm<<<g2, 256>>>(pAct, 768, pWT + aOff[b], LDWT, pCat + chOff[b], 768, HW, chN[b], 768, 0);
        if (b >= 2)
            k_sgemm<<<g2, 256>>>(x[b], 768, pWT + bOff[b], LDWT, pCat + chOff[b], 768, HW, chN[b], 768, 1);
    }

    // ---- CAM ----
    k_gemv<<<HW, 128>>>(pCat, chq, nullptr, pQ, 768);
    k_softmax_hw<<<1, 1024>>>();
    k_poolw<<<32, 256>>>();
    k_pool_fin<<<1, 768>>>();
    k_gemv<<<384, 128>>>(chv, pT, nullptr, pR, 768);
    k_gemv<<<768, 128>>>(chz, pR, nullptr, pWz, 384);
    k_ln_sigmoid<<<1, 768>>>(lng, lnb);
    k_x2<<<HW * EE / 1024, 256>>>();
    dim3 g3((384 + 127) / 128, 32);
    k_sgemm<<<g3, 256>>>(pX2, 768, pSpqT, 384, pQ2, 384, HW, 384, 768, 0);
    k_colmax<<<384, 256>>>();
    k_softmax384<<<1, 384>>>();
    k_u<<<1, 768>>>(spv);
    k_final<<<HW, 256>>>(x[4], normg, normb, (float*)d_out);
}

// round 9
// speedup vs baseline: 2.2370x; 1.0786x over previous
#include <cuda_runtime.h>
#include <cuda_bf16.h>
#include <math.h>
#include <stdint.h>

#define HW 4096
#define EE 768
#define NCOL 7155
#define LDC 7168
#define KSPLIT 1536   // [hi(768) | lo(768)] bf16 per row
#define KW 3072       // proj weight row: [src0 hi|lo | src1 hi|lo]

static __device__ float g_C[(size_t)HW * LDC];
static __device__ __nv_bfloat16 g_Ah[(size_t)HW * KSPLIT];      // x split
static __device__ __nv_bfloat16 g_acts[(size_t)HW * KSPLIT];    // act split
static __device__ __nv_bfloat16 g_x2s[(size_t)HW * KSPLIT];     // x2 split
static __device__ __nv_bfloat16 g_Bh[(size_t)LDC * KSPLIT];     // B split
static __device__ __nv_bfloat16 g_Wp[5 * 384 * KW];             // proj weights per block
static __device__ __nv_bfloat16 g_Wsp[384 * KW];                // spq weights
static __device__ float g_F[27 * 6912];
static __device__ float g_ow[27 * EE];
static __device__ float g_boff[27];
static __device__ float g_off[HW * 18];
static __device__ float g_mask[HW * 9];
static __device__ float g_blk[(size_t)HW * EE];
static __device__ float g_cat[(size_t)HW * EE];
static __device__ float g_x2[(size_t)HW * EE];
static __device__ float g_q2[(size_t)HW * 384];
static __device__ float g_ps[32 * EE], g_pq[32 * EE], g_sc[EE], g_sh[EE];
static __device__ float g_q[HW], g_wq[HW];
static __device__ float g_pt[32 * EE], g_t[EE], g_r[384], g_wz[EE], g_s[EE];
static __device__ float g_mx[384], g_wq2[384], g_u[EE];

// ================= helpers =================
__device__ __forceinline__ uint32_t smem_u32(const void* p) {
    uint32_t a;
    asm("{ .reg .u64 t; cvta.to.shared.u64 t, %1; cvt.u32.u64 %0, t; }" : "=r"(a) : "l"(p));
    return a;
}
__device__ __forceinline__ void cp16(uint32_t dst, const void* src) {
    asm volatile("cp.async.cg.shared.global [%0], [%1], 16;" :: "r"(dst), "l"(src) : "memory");
}
template <int N> __device__ __forceinline__ void cp_wait() {
    asm volatile("cp.async.wait_group %0;" :: "n"(N) : "memory");
}
__device__ __forceinline__ void ldm_x4(uint32_t& r0, uint32_t& r1, uint32_t& r2, uint32_t& r3,
                                       uint32_t addr) {
    asm volatile("ldmatrix.sync.aligned.m8n8.x4.shared.b16 {%0,%1,%2,%3}, [%4];"
                 : "=r"(r0), "=r"(r1), "=r"(r2), "=r"(r3) : "r"(addr));
}
__device__ __forceinline__ void mma16816(float& d0, float& d1, float& d2, float& d3,
                                         uint32_t a0, uint32_t a1, uint32_t a2, uint32_t a3,
                                         uint32_t b0, uint32_t b1) {
    asm volatile(
        "mma.sync.aligned.m16n8k16.row.col.f32.bf16.bf16.f32 "
        "{%0,%1,%2,%3}, {%4,%5,%6,%7}, {%8,%9}, {%0,%1,%2,%3};"
        : "+f"(d0), "+f"(d1), "+f"(d2), "+f"(d3)
        : "r"(a0), "r"(a1), "r"(a2), "r"(a3), "r"(b0), "r"(b1));
}
#define SWZ128(x) ((x) ^ (((x) >> 3) & 0x70))

__device__ __forceinline__ void chunk_koffs(int chunk, int& kA, int& kB) {
    kA = (chunk < 12) ? chunk * 64 : (chunk < 24 ? (chunk - 12) * 64 : 768 + (chunk - 24) * 64);
    kB = (chunk < 12) ? chunk * 64 : (chunk < 24 ? 768 + (chunk - 12) * 64 : (chunk - 24) * 64);
}

// 256 threads: tid<128 loads A row (row0+tid), else B row (col0+tid-128). 8x16B per row, SW128.
__device__ __forceinline__ void load_chunk_main(uint32_t sbase, int s, int chunk,
                                                int row0, int col0, int tid) {
    int kA, kB;
    chunk_koffs(chunk, kA, kB);
    int r = tid & 127;
    bool isB = tid >= 128;
    const __nv_bfloat16* g = isB ? &g_Bh[(size_t)(col0 + r) * KSPLIT + kB]
                                 : &g_Ah[(size_t)(row0 + r) * KSPLIT + kA];
    uint32_t base = sbase + s * 32768 + (isB ? 16384 : 0);
    int rb = r * 128;
#pragma unroll
    for (int seg = 0; seg < 8; seg++)
        cp16(base + SWZ128(rb + seg * 16), g + seg * 8);
    asm volatile("cp.async.commit_group;" ::: "memory");
}

// ========== main GEMM: C[4096 x 7168] = split-fp32 A @ B^T; 3-stage cp.async ==========
__global__ __launch_bounds__(256, 2)
void k_mma_main(float* __restrict__ C)
{
    extern __shared__ char smem_raw[];   // 3 stages x 32KB
    uint32_t sbase = smem_u32(smem_raw);
    int tid = threadIdx.x, wid = tid >> 5, lane = tid & 31;
    int row0 = blockIdx.y * 128, col0 = blockIdx.x * 128;
    int wm = (wid & 1) * 64, wn = (wid >> 1) * 32;

    float acc[4][4][4];
#pragma unroll
    for (int i = 0; i < 4; i++)
#pragma unroll
        for (int j = 0; j < 4; j++)
#pragma unroll
            for (int k = 0; k < 4; k++) acc[i][j][k] = 0.f;

    load_chunk_main(sbase, 0, 0, row0, col0, tid);
    load_chunk_main(sbase, 1, 1, row0, col0, tid);
    load_chunk_main(sbase, 2, 2, row0, col0, tid);

    for (int it = 0; it < 36; it++) {
        int s = it % 3;
        if (it < 34) cp_wait<2>(); else if (it == 34) cp_wait<1>(); else cp_wait<0>();
        __syncthreads();
        uint32_t abase = sbase + s * 32768;
        uint32_t bbase = abase + 16384;
#pragma unroll
        for (int k16 = 0; k16 < 4; k16++) {
            uint32_t b[4][2];
#pragma unroll
            for (int nb2 = 0; nb2 < 2; nb2++) {
                int n_row = wn + nb2 * 16 + (lane & 7) + ((lane >> 4) << 3);
                int k_byte = k16 * 32 + ((lane >> 3) & 1) * 16;
                uint32_t addr = bbase + SWZ128(n_row * 128 + k_byte);
                ldm_x4(b[nb2 * 2][0], b[nb2 * 2][1], b[nb2 * 2 + 1][0], b[nb2 * 2 + 1][1], addr);
            }
#pragma unroll
            for (int mf = 0; mf < 4; mf++) {
                int m_row = wm + mf * 16 + (lane & 15);
                int k_byte = k16 * 32 + (lane >> 4) * 16;
                uint32_t addr = abase + SWZ128(m_row * 128 + k_byte);
                uint32_t a0, a1, a2, a3;
                ldm_x4(a0, a1, a2, a3, addr);
#pragma unroll
                for (int nf = 0; nf < 4; nf++)
                    mma16816(acc[mf][nf][0], acc[mf][nf][1], acc[mf][nf][2], acc[mf][nf][3],
                             a0, a1, a2, a3, b[nf][0], b[nf][1]);
            }
        }
        __syncthreads();
        if (it + 3 < 36) load_chunk_main(sbase, s, it + 3, row0, col0, tid);
    }

    int rr = lane >> 2, cc = (lane & 3) * 2;
#pragma unroll
    for (int mf = 0; mf < 4; mf++) {
#pragma unroll
        for (int nf = 0; nf < 4; nf++) {
            int r = row0 + wm + mf * 16 + rr;
            int c = col0 + wn + nf * 8 + cc;
            *(float2*)&C[(size_t)r * LDC + c] = make_float2(acc[mf][nf][0], acc[mf][nf][1]);
            *(float2*)&C[(size_t)(r + 8) * LDC + c] = make_float2(acc[mf][nf][2], acc[mf][nf][3]);
        }
    }
}

// ========== proj GEMM: C[:,colOff:colOff+N] = [A0|A1] @ W^T ; 2-stage ==========
__global__ __launch_bounds__(256, 2)
void k_mma_proj(const __nv_bfloat16* __restrict__ A0, const __nv_bfloat16* __restrict__ A1,
                const __nv_bfloat16* __restrict__ W, float* __restrict__ C,
                int ldc, int colOff, int N, int nch)
{
    extern __shared__ char smem_raw[];   // 2 stages x 32KB
    uint32_t sbase = smem_u32(smem_raw);
    int tid = threadIdx.x, wid = tid >> 5, lane = tid & 31;
    int row0 = blockIdx.y * 128, col0 = blockIdx.x * 128;
    int wm = (wid & 1) * 64, wn = (wid >> 1) * 32;

    float acc[4][4][4];
#pragma unroll
    for (int i = 0; i < 4; i++)
#pragma unroll
        for (int j = 0; j < 4; j++)
#pragma unroll
            for (int k = 0; k < 4; k++) acc[i][j][k] = 0.f;

    auto load = [&](int s, int chunk) {
        int src = (chunk >= 36) ? 1 : 0;
        int cc0 = chunk - src * 36;
        int kA, kB;
        chunk_koffs(cc0, kA, kB);
        int r = tid & 127;
        const __nv_bfloat16* g;
        uint32_t base;
        if (tid < 128) {
            g = (src ? A1 : A0) + (size_t)(row0 + r) * KSPLIT + kA;
            base = sbase + s * 32768;
        } else {
            g = W + (size_t)(col0 + r) * KW + src * 1536 + kB;
            base = sbase + s * 32768 + 16384;
        }
        int rb = r * 128;
#pragma unroll
        for (int seg = 0; seg < 8; seg++)
            cp16(base + SWZ128(rb + seg * 16), g + seg * 8);
        asm volatile("cp.async.commit_group;" ::: "memory");
    };

    load(0, 0);
    load(1, 1);

    for (int it = 0; it < nch; it++) {
        int s = it & 1;
        if (it < nch - 1) cp_wait<1>(); else cp_wait<0>();
        __syncthreads();
        uint32_t abase = sbase + s * 32768;
        uint32_t bbase = abase + 16384;
#pragma unroll
        for (int k16 = 0; k16 < 4; k16++) {
            uint32_t b[4][2];
#pragma unroll
            for (int nb2 = 0; nb2 < 2; nb2++) {
                int n_row = wn + nb2 * 16 + (lane & 7) + ((lane >> 4) << 3);
                int k_byte = k16 * 32 + ((lane >> 3) & 1) * 16;
                uint32_t addr = bbase + SWZ128(n_row * 128 + k_byte);
                ldm_x4(b[nb2 * 2][0], b[nb2 * 2][1], b[nb2 * 2 + 1][0], b[nb2 * 2 + 1][1], addr);
            }
#pragma unroll
            for (int mf = 0; mf < 4; mf++) {
                int m_row = wm + mf * 16 + (lane & 15);
                int k_byte = k16 * 32 + (lane >> 4) * 16;
                uint32_t addr = abase + SWZ128(m_row * 128 + k_byte);
                uint32_t a0, a1, a2, a3;
                ldm_x4(a0, a1, a2, a3, addr);
#pragma unroll
                for (int nf = 0; nf < 4; nf++)
                    mma16816(acc[mf][nf][0], acc[mf][nf][1], acc[mf][nf][2], acc[mf][nf][3],
                             a0, a1, a2, a3, b[nf][0], b[nf][1]);
            }
        }
        __syncthreads();
        if (it + 2 < nch) load(s, it + 2);
    }

    int rr = lane >> 2, cc = (lane & 3) * 2;
#pragma unroll
    for (int mf = 0; mf < 4; mf++) {
#pragma unroll
        for (int nf = 0; nf < 4; nf++) {
            int c = col0 + wn + nf * 8 + cc;
            if (c < N) {
                int r = row0 + wm + mf * 16 + rr;
                *(float2*)&C[(size_t)r * ldc + colOff + c] =
                    make_float2(acc[mf][nf][0], acc[mf][nf][1]);
                *(float2*)&C[(size_t)(r + 8) * ldc + colOff + c] =
                    make_float2(acc[mf][nf][2], acc[mf][nf][3]);
            }
        }
    }
}

// ---------- split / weight builders ----------
__global__ void k_splitA(const float* __restrict__ x)
{
    int idx = blockIdx.x * 256 + threadIdx.x;
    if (idx < HW * EE) {
        int m = idx / EE, c = idx % EE;
        float v = x[idx];
        __nv_bfloat16 h = __float2bfloat16(v);
        g_Ah[(size_t)m * KSPLIT + c] = h;
        g_Ah[(size_t)m * KSPLIT + 768 + c] = __float2bfloat16(v - __bfloat162float(h));
    }
}
// F = ow @ convw : 27 accumulators per thread, convw read once
__global__ void k_fusedF(const float* __restrict__ convw)
{
    __shared__ float sow[27 * 128];
    int r = blockIdx.x * 256 + threadIdx.x;
    float acc[27];
#pragma unroll
    for (int j = 0; j < 27; j++) acc[j] = 0.f;
    for (int ob = 0; ob < 768; ob += 128) {
        for (int i = threadIdx.x; i < 27 * 128; i += 256) {
            int j = i / 128, oo = i % 128;
            sow[i] = g_ow[j * 768 + ob + oo];
        }
        __syncthreads();
        for (int oo = 0; oo < 128; oo++) {
            float cv = convw[(size_t)(ob + oo) * 6912 + r];
#pragma unroll
            for (int j = 0; j < 27; j++) acc[j] = fmaf(sow[j * 128 + oo], cv, acc[j]);
        }
        __syncthreads();
    }
#pragma unroll
    for (int j = 0; j < 27; j++) g_F[j * 6912 + r] = acc[j];
}
__global__ void k_buildB(const float* __restrict__ convw)
{
    int idx = blockIdx.x * 256 + threadIdx.x;
    if (idx >= LDC * EE) return;
    int n = idx / EE, c = idx % EE;
    float v;
    if (n < 6912) {
        int kk = n / 768, o = n % 768;
        v = convw[((size_t)o * 768 + c) * 9 + kk];
    } else if (n < NCOL) {
        int j = (n - 6912) / 9, kk = (n - 6912) % 9;
        v = g_F[j * 6912 + c * 9 + kk];
    } else v = 0.f;
    __nv_bfloat16 h = __float2bfloat16(v);
    g_Bh[(size_t)n * KSPLIT + c] = h;
    g_Bh[(size_t)n * KSPLIT + 768 + c] = __float2bfloat16(v - __bfloat162float(h));
}
__global__ void k_buildWp(const float* __restrict__ w, __nv_bfloat16* __restrict__ dst,
                          int chN, int srcslot)
{
    int idx = blockIdx.x * 256 + threadIdx.x;
    if (idx >= 384 * 768) return;
    int n = idx / 768, c = idx % 768;
    float v = (n < chN) ? w[n * 768 + c] : 0.f;
    __nv_bfloat16 h = __float2bfloat16(v);
    dst[(size_t)n * KW + srcslot * 1536 + c] = h;
    dst[(size_t)n * KW + srcslot * 1536 + 768 + c] = __float2bfloat16(v - __bfloat162float(h));
}

__global__ void k_gemv(const float* __restrict__ W, const float* __restrict__ x,
                       const float* __restrict__ bias, float* __restrict__ y, int K)
{
    int m = blockIdx.x, t = threadIdx.x;
    float a = 0.f;
    for (int k = t; k < K; k += 128) a += W[(size_t)m * K + k] * x[k];
    __shared__ float red[128];
    red[t] = a; __syncthreads();
    for (int s = 64; s > 0; s >>= 1) { if (t < s) red[t] += red[t + s]; __syncthreads(); }
    if (t == 0) y[m] = red[0] + (bias ? bias[m] : 0.f);
}
__global__ void k_prep_ow(const float* __restrict__ offw, const float* __restrict__ mskw)
{
    int i = blockIdx.x * 256 + threadIdx.x;
    if (i < 27 * EE) { int j = i / EE, c = i % EE; g_ow[i] = (j < 18) ? offw[j * EE + c] : mskw[(j - 18) * EE + c]; }
}

__global__ void k_offmask()
{
    int hw = blockIdx.x, y = hw >> 6, x = hw & 63;
    int j = threadIdx.x;
    __shared__ float lg[9];
    __shared__ float mx_s, sum_s;
    if (j < 27) {
        float v = g_boff[j];
#pragma unroll
        for (int k = 0; k < 9; k++) {
            int yy = y + k / 3 - 1, xx = x + k % 3 - 1;
            if (yy >= 0 && yy < 64 && xx >= 0 && xx < 64)
                v += g_C[(size_t)(yy * 64 + xx) * LDC + 6912 + j * 9 + k];
        }
        if (j < 18) g_off[hw * 18 + j] = v; else lg[j - 18] = v;
    }
    __syncthreads();
    if (j == 0) {
        float mx = lg[0];
        for (int t = 1; t < 9; t++) mx = fmaxf(mx, lg[t]);
        float s = 0.f;
        for (int t = 0; t < 9; t++) s += expf(lg[t] - mx);
        mx_s = mx; sum_s = s;
    }
    __syncthreads();
    if (j < 9) g_mask[hw * 9 + j] = expf(lg[j] - mx_s) / sum_s;
}

__global__ __launch_bounds__(192)
void k_deform_gather(const float* __restrict__ convb)
{
    int hw = blockIdx.x, y = hw >> 6, x = hw & 63;
    __shared__ int sidx[9][4];
    __shared__ float swgt[9][4];
    int tid = threadIdx.x;
    if (tid < 9) {
        int k = tid;
        float dy = g_off[hw * 18 + 2 * k], dx = g_off[hw * 18 + 2 * k + 1];
        float m = g_mask[k * HW + hw];  // raw-reshape mask indexing
        float py = (float)(y + k / 3 - 1) + dy;
        float px = (float)(x + k % 3 - 1) + dx;
        float y0f = floorf(py), x0f = floorf(px);
        float wy1 = py - y0f, wx1 = px - x0f;
        int y0 = (int)y0f, x0 = (int)x0f;
#pragma unroll
        for (int c = 0; c < 4; c++) {
            int yy = y0 + (c >> 1), xx = x0 + (c & 1);
            bool valid = (yy >= 0 && yy <= 63 && xx >= 0 && xx <= 63);
            int yc = min(max(yy, 0), 63), xc = min(max(xx, 0), 63);
            float w = ((c >> 1) ? wy1 : 1.f - wy1) * ((c & 1) ? wx1 : 1.f - wx1);
            sidx[k][c] = yc * 64 + xc;
            swgt[k][c] = valid ? w * m : 0.f;
        }
    }
    __syncthreads();
    int o = tid * 4;
    float4 acc = *(const float4*)(convb + o);
#pragma unroll
    for (int k = 0; k < 9; k++) {
        size_t cb = (size_t)k * EE + o;
#pragma unroll
        for (int c = 0; c < 4; c++) {
            float w = swgt[k][c];
            const float4 v = *(const float4*)(&g_C[(size_t)sidx[k][c] * LDC + cb]);
            acc.x = fmaf(w, v.x, acc.x); acc.y = fmaf(w, v.y, acc.y);
            acc.z = fmaf(w, v.z, acc.z); acc.w = fmaf(w, v.w, acc.w);
        }
    }
    *(float4*)(&g_blk[(size_t)hw * EE + o]) = acc;
}

__global__ void k_bn_partial()
{
    int b = blockIdx.x, t = threadIdx.x;
    float s0 = 0, s1 = 0, s2 = 0, q0 = 0, q1 = 0, q2v = 0;
    for (int r = 0; r < 128; r++) {
        const float* row = &g_blk[(size_t)(b * 128 + r) * EE];
        float v0 = row[t], v1 = row[t + 256], v2 = row[t + 512];
        s0 += v0; s1 += v1; s2 += v2; q0 += v0 * v0; q1 += v1 * v1; q2v += v2 * v2;
    }
    g_ps[b * EE + t] = s0; g_ps[b * EE + t + 256] = s1; g_ps[b * EE + t + 512] = s2;
    g_pq[b * EE + t] = q0; g_pq[b * EE + t + 256] = q1; g_pq[b * EE + t + 512] = q2v;
}
__global__ void k_bn_final(const float* __restrict__ bng, const float* __restrict__ bnb)
{
    int c = threadIdx.x;
    float s = 0, q = 0;
    for (int b = 0; b < 32; b++) { s += g_ps[b * EE + c]; q += g_pq[b * EE + c]; }
    float mu = s * (1.f / 4096.f);
    float var = q * (1.f / 4096.f) - mu * mu;
    float sc = rsqrtf(var + 1e-5f) * bng[c];
    g_sc[c] = sc; g_sh[c] = bnb[c] - mu * sc;
}
// BN + relu, emits split-bf16 act directly
__global__ void k_bn_relu()
{
    int idx = (blockIdx.x * 256 + threadIdx.x) * 4;
    int m = idx / EE, c = idx % EE;
    float4 v = *(const float4*)&g_blk[idx];
    float4 sc = *(const float4*)&g_sc[c];
    float4 sh = *(const float4*)&g_sh[c];
    float r[4];
    r[0] = fmaxf(0.f, fmaf(v.x, sc.x, sh.x)); r[1] = fmaxf(0.f, fmaf(v.y, sc.y, sh.y));
    r[2] = fmaxf(0.f, fmaf(v.z, sc.z, sh.z)); r[3] = fmaxf(0.f, fmaf(v.w, sc.w, sh.w));
    __nv_bfloat16 hi[4], lo[4];
#pragma unroll
    for (int t = 0; t < 4; t++) {
        hi[t] = __float2bfloat16(r[t]);
        lo[t] = __float2bfloat16(r[t] - __bfloat162float(hi[t]));
    }
    *(uint2*)&g_acts[(size_t)m * KSPLIT + c] = *(uint2*)hi;
    *(uint2*)&g_acts[(size_t)m * KSPLIT + 768 + c] = *(uint2*)lo;
}

__global__ void k_softmax_hw()
{
    __shared__ float sm[4096];
    __shared__ float red[1024];
    int t = threadIdx.x;
    float lm = -1e30f;
    for (int i = t; i < 4096; i += 1024) { float v = g_q[i]; sm[i] = v; lm = fmaxf(lm, v); }
    red[t] = lm; __syncthreads();
    for (int s = 512; s > 0; s >>= 1) { if (t < s) red[t] = fmaxf(red[t], red[t + s]); __syncthreads(); }
    float mx = red[0]; __syncthreads();
    float ls = 0.f;
    for (int i = t; i < 4096; i += 1024) { float e = expf(sm[i] - mx); sm[i] = e; ls += e; }
    red[t] = ls; __syncthreads();
    for (int s = 512; s > 0; s >>= 1) { if (t < s) red[t] += red[t + s]; __syncthreads(); }
    float inv = 1.f / red[0]; __syncthreads();
    for (int i = t; i < 4096; i += 1024) g_wq[i] = sm[i] * inv;
}
__global__ void k_poolw()
{
    int b = blockIdx.x, t = threadIdx.x;
    float a0 = 0, a1 = 0, a2 = 0;
    for (int r = 0; r < 128; r++) {
        int hw = b * 128 + r;
        float w = g_wq[hw];
        const float* row = &g_cat[(size_t)hw * EE];
        a0 += w * row[t]; a1 += w * row[t + 256]; a2 += w * row[t + 512];
    }
    g_pt[b * EE + t] = a0; g_pt[b * EE + t + 256] = a1; g_pt[b * EE + t + 512] = a2;
}
__global__ void k_pool_fin()
{
    int c = threadIdx.x;
    float s = 0;
    for (int b = 0; b < 32; b++) s += g_pt[b * EE + c];
    g_t[c] = s;
}
__global__ void k_ln_sigmoid(const float* __restrict__ lng, const float* __restrict__ lnb)
{
    int c = threadIdx.x;
    __shared__ float buf[768];
    __shared__ float red[256];
    float v = g_wz[c];
    buf[c] = v; __syncthreads();
    if (c < 256) red[c] = buf[c] + buf[c + 256] + buf[c + 512];
    __syncthreads();
    for (int s = 128; s > 0; s >>= 1) { if (c < s) red[c] += red[c + s]; __syncthreads(); }
    float mu = red[0] * (1.f / 768.f); __syncthreads();
    float d = v - mu;
    buf[c] = d * d; __syncthreads();
    if (c < 256) red[c] = buf[c] + buf[c + 256] + buf[c + 512];
    __syncthreads();
    for (int s = 128; s > 0; s >>= 1) { if (c < s) red[c] += red[c + s]; __syncthreads(); }
    float var = red[0] * (1.f / 768.f);
    float z = d * rsqrtf(var + 1e-5f) * lng[c] + lnb[c];
    g_s[c] = 1.f / (1.f + expf(-z));
}
// x2 = sigmoid(wz)*cat; emits fp32 + split-bf16
__global__ void k_x2()
{
    int idx = (blockIdx.x * 256 + threadIdx.x) * 4;
    int m = idx / EE, c = idx % EE;
    float4 v = *(const float4*)&g_cat[idx];
    float4 s = *(const float4*)&g_s[c];
    float r[4] = {v.x * s.x, v.y * s.y, v.z * s.z, v.w * s.w};
    *(float4*)&g_x2[idx] = *(float4*)r;
    __nv_bfloat16 hi[4], lo[4];
#pragma unroll
    for (int t = 0; t < 4; t++) {
        hi[t] = __float2bfloat16(r[t]);
        lo[t] = __float2bfloat16(r[t] - __bfloat162float(hi[t]));
    }
    *(uint2*)&g_x2s[(size_t)m * KSPLIT + c] = *(uint2*)hi;
    *(uint2*)&g_x2s[(size_t)m * KSPLIT + 768 + c] = *(uint2*)lo;
}
__global__ void k_colmax()
{
    int rr = blockIdx.x, t = threadIdx.x;
    float m = -1e30f;
    for (int i = t; i < 4096; i += 256) m = fmaxf(m, g_q2[(size_t)i * 384 + rr]);
    __shared__ float red[256];
    red[t] = m; __syncthreads();
    for (int s = 128; s > 0; s >>= 1) { if (t < s) red[t] = fmaxf(red[t], red[t + s]); __syncthreads(); }
    if (t == 0) g_mx[rr] = red[0];
}
__global__ void k_softmax384()
{
    int t = threadIdx.x;
    __shared__ float b[384];
    __shared__ float mx, sm;
    b[t] = g_mx[t]; __syncthreads();
    if (t == 0) { float m = b[0]; for (int i = 1; i < 384; i++) m = fmaxf(m, b[i]); mx = m; }
    __syncthreads();
    float e = expf(b[t] - mx);
    b[t] = e; __syncthreads();
    if (t == 0) { float s = 0; for (int i = 0; i < 384; i++) s += b[i]; sm = s; }
    __syncthreads();
    g_wq2[t] = e / sm;
}
__global__ void k_u(const float* __restrict__ spv)
{
    int c = threadIdx.x;
    float s = 0;
    for (int r = 0; r < 384; r++) s += g_wq2[r] * spv[r * EE + c];
    g_u[c] = s;
}
__global__ void k_final(const float* __restrict__ x5, const float* __restrict__ ng,
                        const float* __restrict__ nb, float* __restrict__ out)
{
    int hw = blockIdx.x, t = threadIdx.x;
    __shared__ float v[768];
    __shared__ float red[256];
    const float* x2r = g_x2 + (size_t)hw * EE;
    const float* catr = g_cat + (size_t)hw * EE;
    const float* x5r = x5 + (size_t)hw * EE;
    float d = 0;
    for (int c = t; c < 768; c += 256) d += g_u[c] * x2r[c];
    red[t] = d; __syncthreads();
    for (int s = 128; s > 0; s >>= 1) { if (t < s) red[t] += red[t + s]; __syncthreads(); }
    float wz2 = 1.f / (1.f + expf(-red[0])); __syncthreads();
    float ls = 0;
    for (int c = t; c < 768; c += 256) { float val = wz2 * x2r[c] + catr[c] + x5r[c]; v[c] = val; ls += val; }
    red[t] = ls; __syncthreads();
    for (int s = 128; s > 0; s >>= 1) { if (t < s) red[t] += red[t + s]; __syncthreads(); }
    float mu = red[0] * (1.f / 768.f); __syncthreads();
    float lq = 0;
    for (int c = t; c < 768; c += 256) { float dd = v[c] - mu; lq += dd * dd; }
    red[t] = lq; __syncthreads();
    for (int s = 128; s > 0; s >>= 1) { if (t < s) red[t] += red[t + s]; __syncthreads(); }
    float rstd = rsqrtf(red[0] * (1.f / 768.f) + 1e-5f); __syncthreads();
    for (int c = t; c < 768; c += 256) out[(size_t)hw * EE + c] = (v[c] - mu) * rstd * ng[c] + nb[c];
}

extern "C" void kernel_launch(void* const* d_in, const int* in_sizes, int n_in,
                              void* d_out, int out_size)
{
    const float* x[5];
    for (int i = 0; i < 5; i++) x[i] = (const float*)d_in[i];
    const float* convw = (const float*)d_in[5];
    const float* convb = (const float*)d_in[6];
    const float* offw = (const float*)d_in[7];
    const float* offb = (const float*)d_in[8];
    const float* mskw = (const float*)d_in[9];
    const float* mskb = (const float*)d_in[10];
    const float* bng = (const float*)d_in[11];
    const float* bnb = (const float*)d_in[12];
    const float* chq = (const float*)d_in[13];
    const float* chv = (const float*)d_in[14];
    const float* chz = (const float*)d_in[15];
    const float* lng = (const float*)d_in[16];
    const float* lnb = (const float*)d_in[17];
    const float* spq = (const float*)d_in[18];
    const float* spv = (const float*)d_in[19];
    const float* wa[5] = {(const float*)d_in[20], (const float*)d_in[21], (const float*)d_in[22],
                          (const float*)d_in[24], (const float*)d_in[26]};
    const float* wb[5] = {nullptr, nullptr, (const float*)d_in[23],
                          (const float*)d_in[25], (const float*)d_in[27]};
    const float* normg = (const float*)d_in[28];
    const float* normb = (const float*)d_in[29];

    float *pC, *pOw, *pBoff, *pCat, *pX2, *pQ2, *pQ, *pT, *pR, *pWz;
    __nv_bfloat16 *pAh, *pActs, *pX2s, *pWp, *pWsp;
    cudaGetSymbolAddress((void**)&pC, g_C);
    cudaGetSymbolAddress((void**)&pOw, g_ow);
    cudaGetSymbolAddress((void**)&pBoff, g_boff);
    cudaGetSymbolAddress((void**)&pCat, g_cat);
    cudaGetSymbolAddress((void**)&pX2, g_x2);
    cudaGetSymbolAddress((void**)&pQ2, g_q2);
    cudaGetSymbolAddress((void**)&pQ, g_q);
    cudaGetSymbolAddress((void**)&pT, g_t);
    cudaGetSymbolAddress((void**)&pR, g_r);
    cudaGetSymbolAddress((void**)&pWz, g_wz);
    cudaGetSymbolAddress((void**)&pAh, g_Ah);
    cudaGetSymbolAddress((void**)&pActs, g_acts);
    cudaGetSymbolAddress((void**)&pX2s, g_x2s);
    cudaGetSymbolAddress((void**)&pWp, g_Wp);
    cudaGetSymbolAddress((void**)&pWsp, g_Wsp);

    const int SMEM_MAIN = 3 * 32768;
    const int SMEM_PROJ = 2 * 32768;
    cudaFuncSetAttribute(k_mma_main, cudaFuncAttributeMaxDynamicSharedMemorySize, SMEM_MAIN);
    cudaFuncSetAttribute(k_mma_proj, cudaFuncAttributeMaxDynamicSharedMemorySize, SMEM_PROJ);

    // ---- prep ----
    k_prep_ow<<<(27 * EE + 255) / 256, 256>>>(offw, mskw);
    k_gemv<<<18, 128>>>(pOw, convb, offb, pBoff, 768);
    k_gemv<<<9, 128>>>(pOw + 18 * 768, convb, mskb, pBoff + 18, 768);
    k_fusedF<<<27, 256>>>(convw);
    k_buildB<<<(LDC * EE + 255) / 256, 256>>>(convw);
    int chN[5] = {30, 100, 150, 220, 268};
    int chOff[5] = {0, 30, 130, 280, 500};
    for (int b = 0; b < 5; b++) {
        k_buildWp<<<(384 * 768 + 255) / 256, 256>>>(wa[b], pWp + (size_t)b * 384 * KW, chN[b], 0);
        if (wb[b])
            k_buildWp<<<(384 * 768 + 255) / 256, 256>>>(wb[b], pWp + (size_t)b * 384 * KW, chN[b], 1);
    }
    k_buildWp<<<(384 * 768 + 255) / 256, 256>>>(spq, pWsp, 384, 0);

    // ---- 5 blocks ----
    for (int b = 0; b < 5; b++) {
        k_splitA<<<(HW * EE + 255) / 256, 256>>>(x[b]);
        k_mma_main<<<dim3(56, 32), 256, SMEM_MAIN>>>(pC);
        k_offmask<<<HW, 32>>>();
        k_deform_gather<<<HW, 192>>>(convb);
        k_bn_partial<<<32, 256>>>();
        k_bn_final<<<1, 768>>>(bng, bnb);
        k_bn_relu<<<HW * EE / 1024, 256>>>();
        int nt = (chN[b] + 127) / 128;
        k_mma_proj<<<dim3(nt, 32), 256, SMEM_PROJ>>>(
            pActs, pAh, pWp + (size_t)b * 384 * KW, pCat, 768, chOff[b], chN[b],
            wb[b] ? 72 : 36);
    }

    // ---- CAM ----
    k_gemv<<<HW, 128>>>(pCat, chq, nullptr, pQ, 768);
    k_softmax_hw<<<1, 1024>>>();
    k_poolw<<<32, 256>>>();
    k_pool_fin<<<1, 768>>>();
    k_gemv<<<384, 128>>>(chv, pT, nullptr, pR, 768);
    k_gemv<<<768, 128>>>(chz, pR, nullptr, pWz, 384);
    k_ln_sigmoid<<<1, 768>>>(lng, lnb);
    k_x2<<<HW * EE / 1024, 256>>>();
    k_mma_proj<<<dim3(3, 32), 256, SMEM_PROJ>>>(pX2s, nullptr, pWsp, pQ2, 384, 0, 384, 36);
    k_colmax<<<384, 256>>>();
    k_softmax384<<<1, 384>>>();
    k_u<<<1, 768>>>(spv);
    k_final<<<HW, 256>>>(x[4], normg, normb, (float*)d_out);
}

// round 10
// speedup vs baseline: 2.4224x; 1.0829x over previous
#include <cuda_runtime.h>
#include <cuda_bf16.h>
#include <math.h>
#include <stdint.h>

#define HW 4096
#define EE 768
#define NCOL 7155
#define LDC 7168
#define KSPLIT 1536   // [hi(768) | lo(768)] bf16 per row
#define KW 3072       // proj weight row: [src0 hi|lo | src1 hi|lo]

static __device__ float g_C[(size_t)HW * LDC];
static __device__ __nv_bfloat16 g_Ah[(size_t)HW * KSPLIT];      // x split
static __device__ __nv_bfloat16 g_acts[(size_t)HW * KSPLIT];    // act split
static __device__ __nv_bfloat16 g_x2s[(size_t)HW * KSPLIT];     // x2 split
static __device__ __nv_bfloat16 g_Bh[(size_t)LDC * KSPLIT];     // B split
static __device__ __nv_bfloat16 g_Wp[5 * 384 * KW];             // proj weights per block
static __device__ __nv_bfloat16 g_Wsp[384 * KW];                // spq weights
static __device__ float g_F[27 * 6912];
static __device__ float g_Fp[32 * 27 * 6912];                   // split-K partials
static __device__ float g_ow[27 * EE];
static __device__ float g_boff[27];
static __device__ float g_off[HW * 18];
static __device__ float g_mask[HW * 9];
static __device__ float g_blk[(size_t)HW * EE];
static __device__ float g_cat[(size_t)HW * EE];
static __device__ float g_x2[(size_t)HW * EE];
static __device__ float g_q2[(size_t)HW * 384];
static __device__ float g_ps[32 * EE], g_pq[32 * EE], g_sc[EE], g_sh[EE];
static __device__ float g_q[HW], g_wq[HW];
static __device__ float g_pt[32 * EE], g_t[EE], g_r[384], g_wz[EE], g_s[EE];
static __device__ float g_mx[384], g_wq2[384], g_u[EE];

// ================= helpers =================
__device__ __forceinline__ uint32_t smem_u32(const void* p) {
    uint32_t a;
    asm("{ .reg .u64 t; cvta.to.shared.u64 t, %1; cvt.u32.u64 %0, t; }" : "=r"(a) : "l"(p));
    return a;
}
__device__ __forceinline__ void cp16(uint32_t dst, const void* src) {
    asm volatile("cp.async.cg.shared.global [%0], [%1], 16;" :: "r"(dst), "l"(src) : "memory");
}
template <int N> __device__ __forceinline__ void cp_wait() {
    asm volatile("cp.async.wait_group %0;" :: "n"(N) : "memory");
}
__device__ __forceinline__ void ldm_x4(uint32_t& r0, uint32_t& r1, uint32_t& r2, uint32_t& r3,
                                       uint32_t addr) {
    asm volatile("ldmatrix.sync.aligned.m8n8.x4.shared.b16 {%0,%1,%2,%3}, [%4];"
                 : "=r"(r0), "=r"(r1), "=r"(r2), "=r"(r3) : "r"(addr));
}
__device__ __forceinline__ void mma16816(float& d0, float& d1, float& d2, float& d3,
                                         uint32_t a0, uint32_t a1, uint32_t a2, uint32_t a3,
                                         uint32_t b0, uint32_t b1) {
    asm volatile(
        "mma.sync.aligned.m16n8k16.row.col.f32.bf16.bf16.f32 "
        "{%0,%1,%2,%3}, {%4,%5,%6,%7}, {%8,%9}, {%0,%1,%2,%3};"
        : "+f"(d0), "+f"(d1), "+f"(d2), "+f"(d3)
        : "r"(a0), "r"(a1), "r"(a2), "r"(a3), "r"(b0), "r"(b1));
}
#define SWZ128(x) ((x) ^ (((x) >> 3) & 0x70))

__device__ __forceinline__ void chunk_koffs(int chunk, int& kA, int& kB) {
    kA = (chunk < 12) ? chunk * 64 : (chunk < 24 ? (chunk - 12) * 64 : 768 + (chunk - 24) * 64);
    kB = (chunk < 12) ? chunk * 64 : (chunk < 24 ? 768 + (chunk - 12) * 64 : (chunk - 24) * 64);
}

__device__ __forceinline__ void load_chunk_main(uint32_t sbase, int s, int chunk,
                                                int row0, int col0, int tid) {
    int kA, kB;
    chunk_koffs(chunk, kA, kB);
    int r = tid & 127;
    bool isB = tid >= 128;
    const __nv_bfloat16* g = isB ? &g_Bh[(size_t)(col0 + r) * KSPLIT + kB]
                                 : &g_Ah[(size_t)(row0 + r) * KSPLIT + kA];
    uint32_t base = sbase + s * 32768 + (isB ? 16384 : 0);
    int rb = r * 128;
#pragma unroll
    for (int seg = 0; seg < 8; seg++)
        cp16(base + SWZ128(rb + seg * 16), g + seg * 8);
    asm volatile("cp.async.commit_group;" ::: "memory");
}

// ========== main GEMM: C[4096 x 7168] = split-fp32 A @ B^T; 3-stage cp.async ==========
__global__ __launch_bounds__(256, 2)
void k_mma_main(float* __restrict__ C)
{
    extern __shared__ char smem_raw[];
    uint32_t sbase = smem_u32(smem_raw);
    int tid = threadIdx.x, wid = tid >> 5, lane = tid & 31;
    int row0 = blockIdx.y * 128, col0 = blockIdx.x * 128;
    int wm = (wid & 1) * 64, wn = (wid >> 1) * 32;

    float acc[4][4][4];
#pragma unroll
    for (int i = 0; i < 4; i++)
#pragma unroll
        for (int j = 0; j < 4; j++)
#pragma unroll
            for (int k = 0; k < 4; k++) acc[i][j][k] = 0.f;

    load_chunk_main(sbase, 0, 0, row0, col0, tid);
    load_chunk_main(sbase, 1, 1, row0, col0, tid);
    load_chunk_main(sbase, 2, 2, row0, col0, tid);

    for (int it = 0; it < 36; it++) {
        int s = it % 3;
        if (it < 34) cp_wait<2>(); else if (it == 34) cp_wait<1>(); else cp_wait<0>();
        __syncthreads();
        uint32_t abase = sbase + s * 32768;
        uint32_t bbase = abase + 16384;
#pragma unroll
        for (int k16 = 0; k16 < 4; k16++) {
            uint32_t b[4][2];
#pragma unroll
            for (int nb2 = 0; nb2 < 2; nb2++) {
                int n_row = wn + nb2 * 16 + (lane & 7) + ((lane >> 4) << 3);
                int k_byte = k16 * 32 + ((lane >> 3) & 1) * 16;
                uint32_t addr = bbase + SWZ128(n_row * 128 + k_byte);
                ldm_x4(b[nb2 * 2][0], b[nb2 * 2][1], b[nb2 * 2 + 1][0], b[nb2 * 2 + 1][1], addr);
            }
#pragma unroll
            for (int mf = 0; mf < 4; mf++) {
                int m_row = wm + mf * 16 + (lane & 15);
                int k_byte = k16 * 32 + (lane >> 4) * 16;
                uint32_t addr = abase + SWZ128(m_row * 128 + k_byte);
                uint32_t a0, a1, a2, a3;
                ldm_x4(a0, a1, a2, a3, addr);
#pragma unroll
                for (int nf = 0; nf < 4; nf++)
                    mma16816(acc[mf][nf][0], acc[mf][nf][1], acc[mf][nf][2], acc[mf][nf][3],
                             a0, a1, a2, a3, b[nf][0], b[nf][1]);
            }
        }
        __syncthreads();
        if (it + 3 < 36) load_chunk_main(sbase, s, it + 3, row0, col0, tid);
    }

    int rr = lane >> 2, cc = (lane & 3) * 2;
#pragma unroll
    for (int mf = 0; mf < 4; mf++) {
#pragma unroll
        for (int nf = 0; nf < 4; nf++) {
            int r = row0 + wm + mf * 16 + rr;
            int c = col0 + wn + nf * 8 + cc;
            *(float2*)&C[(size_t)r * LDC + c] = make_float2(acc[mf][nf][0], acc[mf][nf][1]);
            *(float2*)&C[(size_t)(r + 8) * LDC + c] = make_float2(acc[mf][nf][2], acc[mf][nf][3]);
        }
    }
}

// ========== proj GEMM: C[:,colOff:colOff+N] = [A0|A1] @ W^T ; 2-stage ==========
__global__ __launch_bounds__(256, 2)
void k_mma_proj(const __nv_bfloat16* __restrict__ A0, const __nv_bfloat16* __restrict__ A1,
                const __nv_bfloat16* __restrict__ W, float* __restrict__ C,
                int ldc, int colOff, int N, int nch)
{
    extern __shared__ char smem_raw[];
    uint32_t sbase = smem_u32(smem_raw);
    int tid = threadIdx.x, wid = tid >> 5, lane = tid & 31;
    int row0 = blockIdx.y * 128, col0 = blockIdx.x * 128;
    int wm = (wid & 1) * 64, wn = (wid >> 1) * 32;

    float acc[4][4][4];
#pragma unroll
    for (int i = 0; i < 4; i++)
#pragma unroll
        for (int j = 0; j < 4; j++)
#pragma unroll
            for (int k = 0; k < 4; k++) acc[i][j][k] = 0.f;

    auto load = [&](int s, int chunk) {
        int src = (chunk >= 36) ? 1 : 0;
        int cc0 = chunk - src * 36;
        int kA, kB;
        chunk_koffs(cc0, kA, kB);
        int r = tid & 127;
        const __nv_bfloat16* g;
        uint32_t base;
        if (tid < 128) {
            g = (src ? A1 : A0) + (size_t)(row0 + r) * KSPLIT + kA;
            base = sbase + s * 32768;
        } else {
            g = W + (size_t)(col0 + r) * KW + src * 1536 + kB;
            base = sbase + s * 32768 + 16384;
        }
        int rb = r * 128;
#pragma unroll
        for (int seg = 0; seg < 8; seg++)
            cp16(base + SWZ128(rb + seg * 16), g + seg * 8);
        asm volatile("cp.async.commit_group;" ::: "memory");
    };

    load(0, 0);
    load(1, 1);

    for (int it = 0; it < nch; it++) {
        int s = it & 1;
        if (it < nch - 1) cp_wait<1>(); else cp_wait<0>();
        __syncthreads();
        uint32_t abase = sbase + s * 32768;
        uint32_t bbase = abase + 16384;
#pragma unroll
        for (int k16 = 0; k16 < 4; k16++) {
            uint32_t b[4][2];
#pragma unroll
            for (int nb2 = 0; nb2 < 2; nb2++) {
                int n_row = wn + nb2 * 16 + (lane & 7) + ((lane >> 4) << 3);
                int k_byte = k16 * 32 + ((lane >> 3) & 1) * 16;
                uint32_t addr = bbase + SWZ128(n_row * 128 + k_byte);
                ldm_x4(b[nb2 * 2][0], b[nb2 * 2][1], b[nb2 * 2 + 1][0], b[nb2 * 2 + 1][1], addr);
            }
#pragma unroll
            for (int mf = 0; mf < 4; mf++) {
                int m_row = wm + mf * 16 + (lane & 15);
                int k_byte = k16 * 32 + (lane >> 4) * 16;
                uint32_t addr = abase + SWZ128(m_row * 128 + k_byte);
                uint32_t a0, a1, a2, a3;
                ldm_x4(a0, a1, a2, a3, addr);
#pragma unroll
                for (int nf = 0; nf < 4; nf++)
                    mma16816(acc[mf][nf][0], acc[mf][nf][1], acc[mf][nf][2], acc[mf][nf][3],
                             a0, a1, a2, a3, b[nf][0], b[nf][1]);
            }
        }
        __syncthreads();
        if (it + 2 < nch) load(s, it + 2);
    }

    int rr = lane >> 2, cc = (lane & 3) * 2;
#pragma unroll
    for (int mf = 0; mf < 4; mf++) {
#pragma unroll
        for (int nf = 0; nf < 4; nf++) {
            int c = col0 + wn + nf * 8 + cc;
            if (c < N) {
                int r = row0 + wm + mf * 16 + rr;
                *(float2*)&C[(size_t)r * ldc + colOff + c] =
                    make_float2(acc[mf][nf][0], acc[mf][nf][1]);
                *(float2*)&C[(size_t)(r + 8) * ldc + colOff + c] =
                    make_float2(acc[mf][nf][2], acc[mf][nf][3]);
            }
        }
    }
}

// ---------- split / weight builders ----------
__global__ void k_splitA(const float* __restrict__ x)
{
    int idx = blockIdx.x * 256 + threadIdx.x;
    if (idx < HW * EE) {
        int m = idx / EE, c = idx % EE;
        float v = x[idx];
        __nv_bfloat16 h = __float2bfloat16(v);
        g_Ah[(size_t)m * KSPLIT + c] = h;
        g_Ah[(size_t)m * KSPLIT + 768 + c] = __float2bfloat16(v - __bfloat162float(h));
    }
}
// F = ow @ convw, split-K: grid (27, 32), each block reduces 24 o-values
__global__ void k_fusedF_part(const float* __restrict__ convw)
{
    __shared__ float sow[27 * 24];
    int r = blockIdx.x * 256 + threadIdx.x;        // 0..6911
    int os = blockIdx.y * 24;
    for (int i = threadIdx.x; i < 27 * 24; i += 256)
        sow[i] = g_ow[(i / 24) * 768 + os + (i % 24)];
    __syncthreads();
    float acc[27];
#pragma unroll
    for (int j = 0; j < 27; j++) acc[j] = 0.f;
    for (int oo = 0; oo < 24; oo++) {
        float cv = convw[(size_t)(os + oo) * 6912 + r];
#pragma unroll
        for (int j = 0; j < 27; j++) acc[j] = fmaf(sow[j * 24 + oo], cv, acc[j]);
    }
#pragma unroll
    for (int j = 0; j < 27; j++)
        g_Fp[(size_t)blockIdx.y * (27 * 6912) + j * 6912 + r] = acc[j];
}
__global__ void k_fusedF_red()
{
    int i = blockIdx.x * 256 + threadIdx.x;        // 27*6912 total
    float s = 0.f;
#pragma unroll
    for (int p = 0; p < 32; p++) s += g_Fp[(size_t)p * (27 * 6912) + i];
    g_F[i] = s;
}
// tap columns of B: one block per output channel o; coalesced convw read via smem
__global__ void k_buildB_taps(const float* __restrict__ convw)
{
    __shared__ float s[6912];
    int o = blockIdx.x, t = threadIdx.x;
    const float* src = convw + (size_t)o * 6912;
    for (int i = t; i < 6912; i += 256) s[i] = src[i];
    __syncthreads();
#pragma unroll
    for (int kk = 0; kk < 9; kk++) {
        size_t base = (size_t)(kk * 768 + o) * KSPLIT;
        for (int c = t; c < 768; c += 256) {
            float v = s[c * 9 + kk];
            __nv_bfloat16 h = __float2bfloat16(v);
            g_Bh[base + c] = h;
            g_Bh[base + 768 + c] = __float2bfloat16(v - __bfloat162float(h));
        }
    }
}
// fused columns [6912, NCOL) from g_F, plus zero padding rows [NCOL, LDC)
__global__ void k_buildB_fused()
{
    int idx = blockIdx.x * 256 + threadIdx.x;      // (LDC-6912)*768
    if (idx >= (LDC - 6912) * EE) return;
    int nr = idx / EE, c = idx % EE;
    int n = 6912 + nr;
    float v = 0.f;
    if (n < NCOL) {
        int j = nr / 9, kk = nr % 9;
        v = g_F[j * 6912 + c * 9 + kk];
    }
    __nv_bfloat16 h = __float2bfloat16(v);
    g_Bh[(size_t)n * KSPLIT + c] = h;
    g_Bh[(size_t)n * KSPLIT + 768 + c] = __float2bfloat16(v - __bfloat162float(h));
}
__global__ void k_buildWp(const float* __restrict__ w, __nv_bfloat16* __restrict__ dst,
                          int chN, int srcslot)
{
    int idx = blockIdx.x * 256 + threadIdx.x;
    if (idx >= 384 * 768) return;
    int n = idx / 768, c = idx % 768;
    float v = (n < chN) ? w[n * 768 + c] : 0.f;
    __nv_bfloat16 h = __float2bfloat16(v);
    dst[(size_t)n * KW + srcslot * 1536 + c] = h;
    dst[(size_t)n * KW + srcslot * 1536 + 768 + c] = __float2bfloat16(v - __bfloat162float(h));
}

__global__ void k_gemv(const float* __restrict__ W, const float* __restrict__ x,
                       const float* __restrict__ bias, float* __restrict__ y, int K)
{
    int m = blockIdx.x, t = threadIdx.x;
    float a = 0.f;
    for (int k = t; k < K; k += 128) a += W[(size_t)m * K + k] * x[k];
    __shared__ float red[128];
    red[t] = a; __syncthreads();
    for (int s = 64; s > 0; s >>= 1) { if (t < s) red[t] += red[t + s]; __syncthreads(); }
    if (t == 0) y[m] = red[0] + (bias ? bias[m] : 0.f);
}
__global__ void k_prep_ow(const float* __restrict__ offw, const float* __restrict__ mskw)
{
    int i = blockIdx.x * 256 + threadIdx.x;
    if (i < 27 * EE) { int j = i / EE, c = i % EE; g_ow[i] = (j < 18) ? offw[j * EE + c] : mskw[(j - 18) * EE + c]; }
}

__global__ void k_offmask()
{
    int hw = blockIdx.x, y = hw >> 6, x = hw & 63;
    int j = threadIdx.x;
    __shared__ float lg[9];
    __shared__ float mx_s, sum_s;
    if (j < 27) {
        float v = g_boff[j];
#pragma unroll
        for (int k = 0; k < 9; k++) {
            int yy = y + k / 3 - 1, xx = x + k % 3 - 1;
            if (yy >= 0 && yy < 64 && xx >= 0 && xx < 64)
                v += g_C[(size_t)(yy * 64 + xx) * LDC + 6912 + j * 9 + k];
        }
        if (j < 18) g_off[hw * 18 + j] = v; else lg[j - 18] = v;
    }
    __syncthreads();
    if (j == 0) {
        float mx = lg[0];
        for (int t = 1; t < 9; t++) mx = fmaxf(mx, lg[t]);
        float s = 0.f;
        for (int t = 0; t < 9; t++) s += expf(lg[t] - mx);
        mx_s = mx; sum_s = s;
    }
    __syncthreads();
    if (j < 9) g_mask[hw * 9 + j] = expf(lg[j] - mx_s) / sum_s;
}

__global__ __launch_bounds__(192)
void k_deform_gather(const float* __restrict__ convb)
{
    int hw = blockIdx.x, y = hw >> 6, x = hw & 63;
    __shared__ int sidx[9][4];
    __shared__ float swgt[9][4];
    int tid = threadIdx.x;
    if (tid < 9) {
        int k = tid;
        float dy = g_off[hw * 18 + 2 * k], dx = g_off[hw * 18 + 2 * k + 1];
        float m = g_mask[k * HW + hw];  // raw-reshape mask indexing
        float py = (float)(y + k / 3 - 1) + dy;
        float px = (float)(x + k % 3 - 1) + dx;
        float y0f = floorf(py), x0f = floorf(px);
        float wy1 = py - y0f, wx1 = px - x0f;
        int y0 = (int)y0f, x0 = (int)x0f;
#pragma unroll
        for (int c = 0; c < 4; c++) {
            int yy = y0 + (c >> 1), xx = x0 + (c & 1);
            bool valid = (yy >= 0 && yy <= 63 && xx >= 0 && xx <= 63);
            int yc = min(max(yy, 0), 63), xc = min(max(xx, 0), 63);
            float w = ((c >> 1) ? wy1 : 1.f - wy1) * ((c & 1) ? wx1 : 1.f - wx1);
            sidx[k][c] = yc * 64 + xc;
            swgt[k][c] = valid ? w * m : 0.f;
        }
    }
    __syncthreads();
    int o = tid * 4;
    float4 acc = *(const float4*)(convb + o);
#pragma unroll
    for (int k = 0; k < 9; k++) {
        size_t cb = (size_t)k * EE + o;
#pragma unroll
        for (int c = 0; c < 4; c++) {
            float w = swgt[k][c];
            const float4 v = *(const float4*)(&g_C[(size_t)sidx[k][c] * LDC + cb]);
            acc.x = fmaf(w, v.x, acc.x); acc.y = fmaf(w, v.y, acc.y);
            acc.z = fmaf(w, v.z, acc.z); acc.w = fmaf(w, v.w, acc.w);
        }
    }
    *(float4*)(&g_blk[(size_t)hw * EE + o]) = acc;
}

__global__ void k_bn_partial()
{
    int b = blockIdx.x, t = threadIdx.x;
    float s0 = 0, s1 = 0, s2 = 0, q0 = 0, q1 = 0, q2v = 0;
    for (int r = 0; r < 128; r++) {
        const float* row = &g_blk[(size_t)(b * 128 + r) * EE];
        float v0 = row[t], v1 = row[t + 256], v2 = row[t + 512];
        s0 += v0; s1 += v1; s2 += v2; q0 += v0 * v0; q1 += v1 * v1; q2v += v2 * v2;
    }
    g_ps[b * EE + t] = s0; g_ps[b * EE + t + 256] = s1; g_ps[b * EE + t + 512] = s2;
    g_pq[b * EE + t] = q0; g_pq[b * EE + t + 256] = q1; g_pq[b * EE + t + 512] = q2v;
}
__global__ void k_bn_final(const float* __restrict__ bng, const float* __restrict__ bnb)
{
    int c = threadIdx.x;
    float s = 0, q = 0;
    for (int b = 0; b < 32; b++) { s += g_ps[b * EE + c]; q += g_pq[b * EE + c]; }
    float mu = s * (1.f / 4096.f);
    float var = q * (1.f / 4096.f) - mu * mu;
    float sc = rsqrtf(var + 1e-5f) * bng[c];
    g_sc[c] = sc; g_sh[c] = bnb[c] - mu * sc;
}
__global__ void k_bn_relu()
{
    int idx = (blockIdx.x * 256 + threadIdx.x) * 4;
    int m = idx / EE, c = idx % EE;
    float4 v = *(const float4*)&g_blk[idx];
    float4 sc = *(const float4*)&g_sc[c];
    float4 sh = *(const float4*)&g_sh[c];
    float r[4];
    r[0] = fmaxf(0.f, fmaf(v.x, sc.x, sh.x)); r[1] = fmaxf(0.f, fmaf(v.y, sc.y, sh.y));
    r[2] = fmaxf(0.f, fmaf(v.z, sc.z, sh.z)); r[3] = fmaxf(0.f, fmaf(v.w, sc.w, sh.w));
    __nv_bfloat16 hi[4], lo[4];
#pragma unroll
    for (int t = 0; t < 4; t++) {
        hi[t] = __float2bfloat16(r[t]);
        lo[t] = __float2bfloat16(r[t] - __bfloat162float(hi[t]));
    }
    *(uint2*)&g_acts[(size_t)m * KSPLIT + c] = *(uint2*)hi;
    *(uint2*)&g_acts[(size_t)m * KSPLIT + 768 + c] = *(uint2*)lo;
}

__global__ void k_softmax_hw()
{
    __shared__ float sm[4096];
    __shared__ float red[1024];
    int t = threadIdx.x;
    float lm = -1e30f;
    for (int i = t; i < 4096; i += 1024) { float v = g_q[i]; sm[i] = v; lm = fmaxf(lm, v); }
    red[t] = lm; __syncthreads();
    for (int s = 512; s > 0; s >>= 1) { if (t < s) red[t] = fmaxf(red[t], red[t + s]); __syncthreads(); }
    float mx = red[0]; __syncthreads();
    float ls = 0.f;
    for (int i = t; i < 4096; i += 1024) { float e = expf(sm[i] - mx); sm[i] = e; ls += e; }
    red[t] = ls; __syncthreads();
    for (int s = 512; s > 0; s >>= 1) { if (t < s) red[t] += red[t + s]; __syncthreads(); }
    float inv = 1.f / red[0]; __syncthreads();
    for (int i = t; i < 4096; i += 1024) g_wq[i] = sm[i] * inv;
}
__global__ void k_poolw()
{
    int b = blockIdx.x, t = threadIdx.x;
    float a0 = 0, a1 = 0, a2 = 0;
    for (int r = 0; r < 128; r++) {
        int hw = b * 128 + r;
        float w = g_wq[hw];
        const float* row = &g_cat[(size_t)hw * EE];
        a0 += w * row[t]; a1 += w * row[t + 256]; a2 += w * row[t + 512];
    }
    g_pt[b * EE + t] = a0; g_pt[b * EE + t + 256] = a1; g_pt[b * EE + t + 512] = a2;
}
__global__ void k_pool_fin()
{
    int c = threadIdx.x;
    float s = 0;
    for (int b = 0; b < 32; b++) s += g_pt[b * EE + c];
    g_t[c] = s;
}
__global__ void k_ln_sigmoid(const float* __restrict__ lng, const float* __restrict__ lnb)
{
    int c = threadIdx.x;
    __shared__ float buf[768];
    __shared__ float red[256];
    float v = g_wz[c];
    buf[c] = v; __syncthreads();
    if (c < 256) red[c] = buf[c] + buf[c + 256] + buf[c + 512];
    __syncthreads();
    for (int s = 128; s > 0; s >>= 1) { if (c < s) red[c] += red[c + s]; __syncthreads(); }
    float mu = red[0] * (1.f / 768.f); __syncthreads();
    float d = v - mu;
    buf[c] = d * d; __syncthreads();
    if (c < 256) red[c] = buf[c] + buf[c + 256] + buf[c + 512];
    __syncthreads();
    for (int s = 128; s > 0; s >>= 1) { if (c < s) red[c] += red[c + s]; __syncthreads(); }
    float var = red[0] * (1.f / 768.f);
    float z = d * rsqrtf(var + 1e-5f) * lng[c] + lnb[c];
    g_s[c] = 1.f / (1.f + expf(-z));
}
__global__ void k_x2()
{
    int idx = (blockIdx.x * 256 + threadIdx.x) * 4;
    int m = idx / EE, c = idx % EE;
    float4 v = *(const float4*)&g_cat[idx];
    float4 s = *(const float4*)&g_s[c];
    float r[4] = {v.x * s.x, v.y * s.y, v.z * s.z, v.w * s.w};
    *(float4*)&g_x2[idx] = *(float4*)r;
    __nv_bfloat16 hi[4], lo[4];
#pragma unroll
    for (int t = 0; t < 4; t++) {
        hi[t] = __float2bfloat16(r[t]);
        lo[t] = __float2bfloat16(r[t] - __bfloat162float(hi[t]));
    }
    *(uint2*)&g_x2s[(size_t)m * KSPLIT + c] = *(uint2*)hi;
    *(uint2*)&g_x2s[(size_t)m * KSPLIT + 768 + c] = *(uint2*)lo;
}
__global__ void k_colmax()
{
    int rr = blockIdx.x, t = threadIdx.x;
    float m = -1e30f;
    for (int i = t; i < 4096; i += 256) m = fmaxf(m, g_q2[(size_t)i * 384 + rr]);
    __shared__ float red[256];
    red[t] = m; __syncthreads();
    for (int s = 128; s > 0; s >>= 1) { if (t < s) red[t] = fmaxf(red[t], red[t + s]); __syncthreads(); }
    if (t == 0) g_mx[rr] = red[0];
}
__global__ void k_softmax384()
{
    int t = threadIdx.x;
    __shared__ float b[384];
    __shared__ float mx, sm;
    b[t] = g_mx[t]; __syncthreads();
    if (t == 0) { float m = b[0]; for (int i = 1; i < 384; i++) m = fmaxf(m, b[i]); mx = m; }
    __syncthreads();
    float e = expf(b[t] - mx);
    b[t] = e; __syncthreads();
    if (t == 0) { float s = 0; for (int i = 0; i < 384; i++) s += b[i]; sm = s; }
    __syncthreads();
    g_wq2[t] = e / sm;
}
__global__ void k_u(const float* __restrict__ spv)
{
    int c = threadIdx.x;
    float s = 0;
    for (int r = 0; r < 384; r++) s += g_wq2[r] * spv[r * EE + c];
    g_u[c] = s;
}
__global__ void k_final(const float* __restrict__ x5, const float* __restrict__ ng,
                        const float* __restrict__ nb, float* __restrict__ out)
{
    int hw = blockIdx.x, t = threadIdx.x;
    __shared__ float v[768];
    __shared__ float red[256];
    const float* x2r = g_x2 + (size_t)hw * EE;
    const float* catr = g_cat + (size_t)hw * EE;
    const float* x5r = x5 + (size_t)hw * EE;
    float d = 0;
    for (int c = t; c < 768; c += 256) d += g_u[c] * x2r[c];
    red[t] = d; __syncthreads();
    for (int s = 128; s > 0; s >>= 1) { if (t < s) red[t] += red[t + s]; __syncthreads(); }
    float wz2 = 1.f / (1.f + expf(-red[0])); __syncthreads();
    float ls = 0;
    for (int c = t; c < 768; c += 256) { float val = wz2 * x2r[c] + catr[c] + x5r[c]; v[c] = val; ls += val; }
    red[t] = ls; __syncthreads();
    for (int s = 128; s > 0; s >>= 1) { if (t < s) red[t] += red[t + s]; __syncthreads(); }
    float mu = red[0] * (1.f / 768.f); __syncthreads();
    float lq = 0;
    for (int c = t; c < 768; c += 256) { float dd = v[c] - mu; lq += dd * dd; }
    red[t] = lq; __syncthreads();
    for (int s = 128; s > 0; s >>= 1) { if (t < s) red[t] += red[t + s]; __syncthreads(); }
    float rstd = rsqrtf(red[0] * (1.f / 768.f) + 1e-5f); __syncthreads();
    for (int c = t; c < 768; c += 256) out[(size_t)hw * EE + c] = (v[c] - mu) * rstd * ng[c] + nb[c];
}

extern "C" void kernel_launch(void* const* d_in, const int* in_sizes, int n_in,
                              void* d_out, int out_size)
{
    const float* x[5];
    for (int i = 0; i < 5; i++) x[i] = (const float*)d_in[i];
    const float* convw = (const float*)d_in[5];
    const float* convb = (const float*)d_in[6];
    const float* offw = (const float*)d_in[7];
    const float* offb = (const float*)d_in[8];
    const float* mskw = (const float*)d_in[9];
    const float* mskb = (const float*)d_in[10];
    const float* bng = (const float*)d_in[11];
    const float* bnb = (const float*)d_in[12];
    const float* chq = (const float*)d_in[13];
    const float* chv = (const float*)d_in[14];
    const float* chz = (const float*)d_in[15];
    const float* lng = (const float*)d_in[16];
    const float* lnb = (const float*)d_in[17];
    const float* spq = (const float*)d_in[18];
    const float* spv = (const float*)d_in[19];
    const float* wa[5] = {(const float*)d_in[20], (const float*)d_in[21], (const float*)d_in[22],
                          (const float*)d_in[24], (const float*)d_in[26]};
    const float* wb[5] = {nullptr, nullptr, (const float*)d_in[23],
                          (const float*)d_in[25], (const float*)d_in[27]};
    const float* normg = (const float*)d_in[28];
    const float* normb = (const float*)d_in[29];

    float *pC, *pOw, *pBoff, *pCat, *pX2, *pQ2, *pQ, *pT, *pR, *pWz;
    __nv_bfloat16 *pAh, *pActs, *pX2s, *pWp, *pWsp;
    cudaGetSymbolAddress((void**)&pC, g_C);
    cudaGetSymbolAddress((void**)&pOw, g_ow);
    cudaGetSymbolAddress((void**)&pBoff, g_boff);
    cudaGetSymbolAddress((void**)&pCat, g_cat);
    cudaGetSymbolAddress((void**)&pX2, g_x2);
    cudaGetSymbolAddress((void**)&pQ2, g_q2);
    cudaGetSymbolAddress((void**)&pQ, g_q);
    cudaGetSymbolAddress((void**)&pT, g_t);
    cudaGetSymbolAddress((void**)&pR, g_r);
    cudaGetSymbolAddress((void**)&pWz, g_wz);
    cudaGetSymbolAddress((void**)&pAh, g_Ah);
    cudaGetSymbolAddress((void**)&pActs, g_acts);
    cudaGetSymbolAddress((void**)&pX2s, g_x2s);
    cudaGetSymbolAddress((void**)&pWp, g_Wp);
    cudaGetSymbolAddress((void**)&pWsp, g_Wsp);

    const int SMEM_MAIN = 3 * 32768;
    const int SMEM_PROJ = 2 * 32768;
    cudaFuncSetAttribute(k_mma_main, cudaFuncAttributeMaxDynamicSharedMemorySize, SMEM_MAIN);
    cudaFuncSetAttribute(k_mma_proj, cudaFuncAttributeMaxDynamicSharedMemorySize, SMEM_PROJ);

    // ---- prep ----
    k_prep_ow<<<(27 * EE + 255) / 256, 256>>>(offw, mskw);
    k_gemv<<<18, 128>>>(pOw, convb, offb, pBoff, 768);
    k_gemv<<<9, 128>>>(pOw + 18 * 768, convb, mskb, pBoff + 18, 768);
    k_fusedF_part<<<dim3(27, 32), 256>>>(convw);
    k_fusedF_red<<<27 * 6912 / 256, 256>>>();
    k_buildB_taps<<<768, 256>>>(convw);
    k_buildB_fused<<<((LDC - 6912) * EE + 255) / 256, 256>>>();
    int chN[5] = {30, 100, 150, 220, 268};
    int chOff[5] = {0, 30, 130, 280, 500};
    for (int b = 0; b < 5; b++) {
        k_buildWp<<<(384 * 768 + 255) / 256, 256>>>(wa[b], pWp + (size_t)b * 384 * KW, chN[b], 0);
        if (wb[b])
            k_buildWp<<<(384 * 768 + 255) / 256, 256>>>(wb[b], pWp + (size_t)b * 384 * KW, chN[b], 1);
    }
    k_buildWp<<<(384 * 768 + 255) / 256, 256>>>(spq, pWsp, 384, 0);

    // ---- 5 blocks ----
    for (int b = 0; b < 5; b++) {
        k_splitA<<<(HW * EE + 255) / 256, 256>>>(x[b]);
        k_mma_main<<<dim3(56, 32), 256, SMEM_MAIN>>>(pC);
        k_offmask<<<HW, 32>>>();
        k_deform_gather<<<HW, 192>>>(convb);
        k_bn_partial<<<32, 256>>>();
        k_bn_final<<<1, 768>>>(bng, bnb);
        k_bn_relu<<<HW * EE / 1024, 256>>>();
        int nt = (chN[b] + 127) / 128;
        k_mma_proj<<<dim3(nt, 32), 256, SMEM_PROJ>>>(
            pActs, pAh, pWp + (size_t)b * 384 * KW, pCat, 768, chOff[b], chN[b],
            wb[b] ? 72 : 36);
    }

    // ---- CAM ----
    k_gemv<<<HW, 128>>>(pCat, chq, nullptr, pQ, 768);
    k_softmax_hw<<<1, 1024>>>();
    k_poolw<<<32, 256>>>();
    k_pool_fin<<<1, 768>>>();
    k_gemv<<<384, 128>>>(chv, pT, nullptr, pR, 768);
    k_gemv<<<768, 128>>>(chz, pR, nullptr, pWz, 384);
    k_ln_sigmoid<<<1, 768>>>(lng, lnb);
    k_x2<<<HW * EE / 1024, 256>>>();
    k_mma_proj<<<dim3(3, 32), 256, SMEM_PROJ>>>(pX2s, nullptr, pWsp, pQ2, 384, 0, 384, 36);
    k_colmax<<<384, 256>>>();
    k_softmax384<<<1, 384>>>();
    k_u<<<1, 768>>>(spv);
    k_final<<<HW, 256>>>(x[4], normg, normb, (float*)d_out);
}

// round 12
// speedup vs baseline: 3.0985x; 1.2791x over previous
#include <cuda_runtime.h>
#include <cuda_bf16.h>
#include <cuda_fp16.h>
#include <math.h>
#include <stdint.h>

#define HW 4096
#define EE 768
#define NCOL 7155
#define LDC 7168
#define KSPLIT 1536   // split row: [hi(768) | lo(768)]
#define KW 3072       // proj weight row: [src0 hi|lo | src1 hi|lo] bf16

static __device__ float g_C[(size_t)HW * LDC];
static __device__ __half g_Ah[(size_t)HW * KSPLIT];             // x split fp16 (main)
static __device__ __half g_Bh[(size_t)LDC * EE];                // B single fp16 (main)
static __device__ __nv_bfloat16 g_xs[(size_t)HW * KSPLIT];      // x split bf16 (proj)
static __device__ __nv_bfloat16 g_acts[(size_t)HW * KSPLIT];    // act split bf16 (proj)
static __device__ __nv_bfloat16 g_x2s[(size_t)HW * KSPLIT];     // x2 split bf16 (proj)
static __device__ __nv_bfloat16 g_Wp[5 * 384 * KW];
static __device__ __nv_bfloat16 g_Wsp[384 * KW];
static __device__ float g_F[27 * 6912];
static __device__ float g_Fp[32 * 27 * 6912];
static __device__ float g_ow[27 * EE];
static __device__ float g_boff[27];
static __device__ float g_off[HW * 18];
static __device__ float g_mask[HW * 9];
static __device__ float g_blk[(size_t)HW * EE];
static __device__ float g_cat[(size_t)HW * EE];
static __device__ float g_x2[(size_t)HW * EE];
static __device__ float g_q2[(size_t)HW * 384];
static __device__ float g_ps[32 * EE], g_pq[32 * EE], g_sc[EE], g_sh[EE];
static __device__ float g_q[HW], g_wq[HW];
static __device__ float g_pt[32 * EE], g_t[EE], g_r[384], g_wz[EE], g_s[EE];
static __device__ float g_mx[384], g_wq2[384], g_u[EE];

// ================= helpers =================
__device__ __forceinline__ uint32_t smem_u32(const void* p) {
    uint32_t a;
    asm("{ .reg .u64 t; cvta.to.shared.u64 t, %1; cvt.u32.u64 %0, t; }" : "=r"(a) : "l"(p));
    return a;
}
__device__ __forceinline__ void cp16(uint32_t dst, const void* src) {
    asm volatile("cp.async.cg.shared.global [%0], [%1], 16;" :: "r"(dst), "l"(src) : "memory");
}
template <int N> __device__ __forceinline__ void cp_wait() {
    asm volatile("cp.async.wait_group %0;" :: "n"(N) : "memory");
}
__device__ __forceinline__ void ldm_x4(uint32_t& r0, uint32_t& r1, uint32_t& r2, uint32_t& r3,
                                       uint32_t addr) {
    asm volatile("ldmatrix.sync.aligned.m8n8.x4.shared.b16 {%0,%1,%2,%3}, [%4];"
                 : "=r"(r0), "=r"(r1), "=r"(r2), "=r"(r3) : "r"(addr));
}
__device__ __forceinline__ void mma_bf16(float& d0, float& d1, float& d2, float& d3,
                                         uint32_t a0, uint32_t a1, uint32_t a2, uint32_t a3,
                                         uint32_t b0, uint32_t b1) {
    asm volatile(
        "mma.sync.aligned.m16n8k16.row.col.f32.bf16.bf16.f32 "
        "{%0,%1,%2,%3}, {%4,%5,%6,%7}, {%8,%9}, {%0,%1,%2,%3};"
        : "+f"(d0), "+f"(d1), "+f"(d2), "+f"(d3)
        : "r"(a0), "r"(a1), "r"(a2), "r"(a3), "r"(b0), "r"(b1));
}
__device__ __forceinline__ void mma_f16(float& d0, float& d1, float& d2, float& d3,
                                        uint32_t a0, uint32_t a1, uint32_t a2, uint32_t a3,
                                        uint32_t b0, uint32_t b1) {
    asm volatile(
        "mma.sync.aligned.m16n8k16.row.col.f32.f16.f16.f32 "
        "{%0,%1,%2,%3}, {%4,%5,%6,%7}, {%8,%9}, {%0,%1,%2,%3};"
        : "+f"(d0), "+f"(d1), "+f"(d2), "+f"(d3)
        : "r"(a0), "r"(a1), "r"(a2), "r"(a3), "r"(b0), "r"(b1));
}
#define SWZ128(x) ((x) ^ (((x) >> 3) & 0x70))

__device__ __forceinline__ void chunk_koffs(int chunk, int& kA, int& kB) {
    kA = (chunk < 12) ? chunk * 64 : (chunk < 24 ? (chunk - 12) * 64 : 768 + (chunk - 24) * 64);
    kB = (chunk < 12) ? chunk * 64 : (chunk < 24 ? 768 + (chunk - 12) * 64 : (chunk - 24) * 64);
}

// main 2-segment fp16: seg0 = ah.b, seg1 = al.b (24 chunks of K=64)
__device__ __forceinline__ void load_chunk_main(uint32_t sbase, int s, int chunk,
                                                int row0, int col0, int tid) {
    int kA = (chunk < 12) ? chunk * 64 : 768 + (chunk - 12) * 64;
    int kB = (chunk < 12 ? chunk : chunk - 12) * 64;
    int r = tid & 127;
    bool isB = tid >= 128;
    const __half* g = isB ? &g_Bh[(size_t)(col0 + r) * EE + kB]
                          : &g_Ah[(size_t)(row0 + r) * KSPLIT + kA];
    uint32_t base = sbase + s * 32768 + (isB ? 16384 : 0);
    int rb = r * 128;
#pragma unroll
    for (int seg = 0; seg < 8; seg++)
        cp16(base + SWZ128(rb + seg * 16), g + seg * 8);
    asm volatile("cp.async.commit_group;" ::: "memory");
}

// ========== main GEMM: C[4096 x 7168] = (ah+al)_f16 @ b_f16^T; 3-stage ==========
__global__ __launch_bounds__(256, 2)
void k_mma_main(float* __restrict__ C)
{
    extern __shared__ char smem_raw[];
    uint32_t sbase = smem_u32(smem_raw);
    int tid = threadIdx.x, wid = tid >> 5, lane = tid & 31;
    int row0 = blockIdx.y * 128, col0 = blockIdx.x * 128;
    int wm = (wid & 1) * 64, wn = (wid >> 1) * 32;

    float acc[4][4][4];
#pragma unroll
    for (int i = 0; i < 4; i++)
#pragma unroll
        for (int j = 0; j < 4; j++)
#pragma unroll
            for (int k = 0; k < 4; k++) acc[i][j][k] = 0.f;

    load_chunk_main(sbase, 0, 0, row0, col0, tid);
    load_chunk_main(sbase, 1, 1, row0, col0, tid);
    load_chunk_main(sbase, 2, 2, row0, col0, tid);

    for (int it = 0; it < 24; it++) {
        int s = it % 3;
        if (it < 22) cp_wait<2>(); else if (it == 22) cp_wait<1>(); else cp_wait<0>();
        __syncthreads();
        uint32_t abase = sbase + s * 32768;
        uint32_t bbase = abase + 16384;
#pragma unroll
        for (int k16 = 0; k16 < 4; k16++) {
            uint32_t b[4][2];
#pragma unroll
            for (int nb2 = 0; nb2 < 2; nb2++) {
                int n_row = wn + nb2 * 16 + (lane & 7) + ((lane >> 4) << 3);
                int k_byte = k16 * 32 + ((lane >> 3) & 1) * 16;
                uint32_t addr = bbase + SWZ128(n_row * 128 + k_byte);
                ldm_x4(b[nb2 * 2][0], b[nb2 * 2][1], b[nb2 * 2 + 1][0], b[nb2 * 2 + 1][1], addr);
            }
#pragma unroll
            for (int mf = 0; mf < 4; mf++) {
                int m_row = wm + mf * 16 + (lane & 15);
                int k_byte = k16 * 32 + (lane >> 4) * 16;
                uint32_t addr = abase + SWZ128(m_row * 128 + k_byte);
                uint32_t a0, a1, a2, a3;
                ldm_x4(a0, a1, a2, a3, addr);
#pragma unroll
                for (int nf = 0; nf < 4; nf++)
                    mma_f16(acc[mf][nf][0], acc[mf][nf][1], acc[mf][nf][2], acc[mf][nf][3],
                            a0, a1, a2, a3, b[nf][0], b[nf][1]);
            }
        }
        __syncthreads();
        if (it + 3 < 24) load_chunk_main(sbase, s, it + 3, row0, col0, tid);
    }

    int rr = lane >> 2, cc = (lane & 3) * 2;
#pragma unroll
    for (int mf = 0; mf < 4; mf++) {
#pragma unroll
        for (int nf = 0; nf < 4; nf++) {
            int r = row0 + wm + mf * 16 + rr;
            int c = col0 + wn + nf * 8 + cc;
            *(float2*)&C[(size_t)r * LDC + c] = make_float2(acc[mf][nf][0], acc[mf][nf][1]);
            *(float2*)&C[(size_t)(r + 8) * LDC + c] = make_float2(acc[mf][nf][2], acc[mf][nf][3]);
        }
    }
}

// ========== proj GEMM: C[:,colOff:colOff+N] = [A0|A1] @ W^T ; 2-stage bf16 ==========
__global__ __launch_bounds__(256, 2)
void k_mma_proj(const __nv_bfloat16* __restrict__ A0, const __nv_bfloat16* __restrict__ A1,
                const __nv_bfloat16* __restrict__ W, float* __restrict__ C,
                int ldc, int colOff, int N, int nch)
{
    extern __shared__ char smem_raw[];
    uint32_t sbase = smem_u32(smem_raw);
    int tid = threadIdx.x, wid = tid >> 5, lane = tid & 31;
    int row0 = blockIdx.y * 128, col0 = blockIdx.x * 128;
    int wm = (wid & 1) * 64, wn = (wid >> 1) * 32;

    float acc[4][4][4];
#pragma unroll
    for (int i = 0; i < 4; i++)
#pragma unroll
        for (int j = 0; j < 4; j++)
#pragma unroll
            for (int k = 0; k < 4; k++) acc[i][j][k] = 0.f;

    auto load = [&](int s, int chunk) {
        int src = (chunk >= 36) ? 1 : 0;
        int cc0 = chunk - src * 36;
        int kA, kB;
        chunk_koffs(cc0, kA, kB);
        int r = tid & 127;
        const __nv_bfloat16* g;
        uint32_t base;
        if (tid < 128) {
            g = (src ? A1 : A0) + (size_t)(row0 + r) * KSPLIT + kA;
            base = sbase + s * 32768;
        } else {
            g = W + (size_t)(col0 + r) * KW + src * 1536 + kB;
            base = sbase + s * 32768 + 16384;
        }
        int rb = r * 128;
#pragma unroll
        for (int seg = 0; seg < 8; seg++)
            cp16(base + SWZ128(rb + seg * 16), g + seg * 8);
        asm volatile("cp.async.commit_group;" ::: "memory");
    };

    load(0, 0);
    load(1, 1);

    for (int it = 0; it < nch; it++) {
        int s = it & 1;
        if (it < nch - 1) cp_wait<1>(); else cp_wait<0>();
        __syncthreads();
        uint32_t abase = sbase + s * 32768;
        uint32_t bbase = abase + 16384;
#pragma unroll
        for (int k16 = 0; k16 < 4; k16++) {
            uint32_t b[4][2];
#pragma unroll
            for (int nb2 = 0; nb2 < 2; nb2++) {
                int n_row = wn + nb2 * 16 + (lane & 7) + ((lane >> 4) << 3);
                int k_byte = k16 * 32 + ((lane >> 3) & 1) * 16;
                uint32_t addr = bbase + SWZ128(n_row * 128 + k_byte);
                ldm_x4(b[nb2 * 2][0], b[nb2 * 2][1], b[nb2 * 2 + 1][0], b[nb2 * 2 + 1][1], addr);
            }
#pragma unroll
            for (int mf = 0; mf < 4; mf++) {
                int m_row = wm + mf * 16 + (lane & 15);
                int k_byte = k16 * 32 + (lane >> 4) * 16;
                uint32_t addr = abase + SWZ128(m_row * 128 + k_byte);
                uint32_t a0, a1, a2, a3;
                ldm_x4(a0, a1, a2, a3, addr);
#pragma unroll
                for (int nf = 0; nf < 4; nf++)
                    mma_bf16(acc[mf][nf][0], acc[mf][nf][1], acc[mf][nf][2], acc[mf][nf][3],
                             a0, a1, a2, a3, b[nf][0], b[nf][1]);
            }
        }
        __syncthreads();
        if (it + 2 < nch) load(s, it + 2);
    }

    int rr = lane >> 2, cc = (lane & 3) * 2;
#pragma unroll
    for (int mf = 0; mf < 4; mf++) {
#pragma unroll
        for (int nf = 0; nf < 4; nf++) {
            int c = col0 + wn + nf * 8 + cc;
            if (c < N) {
                int r = row0 + wm + mf * 16 + rr;
                *(float2*)&C[(size_t)r * ldc + colOff + c] =
                    make_float2(acc[mf][nf][0], acc[mf][nf][1]);
                *(float2*)&C[(size_t)(r + 8) * ldc + colOff + c] =
                    make_float2(acc[mf][nf][2], acc[mf][nf][3]);
            }
        }
    }
}

// ---------- split / weight builders ----------
// writes BOTH the fp16 split (main) and bf16 split (proj A1 source)
__global__ void k_splitA(const float* __restrict__ x)
{
    int idx = blockIdx.x * 256 + threadIdx.x;
    if (idx < HW * EE) {
        int m = idx / EE, c = idx % EE;
        float v = x[idx];
        __half h = __float2half(v);
        g_Ah[(size_t)m * KSPLIT + c] = h;
        g_Ah[(size_t)m * KSPLIT + 768 + c] = __float2half(v - __half2float(h));
        __nv_bfloat16 bh = __float2bfloat16(v);
        g_xs[(size_t)m * KSPLIT + c] = bh;
        g_xs[(size_t)m * KSPLIT + 768 + c] = __float2bfloat16(v - __bfloat162float(bh));
    }
}
__global__ void k_fusedF_part(const float* __restrict__ convw)
{
    __shared__ float sow[27 * 24];
    int r = blockIdx.x * 256 + threadIdx.x;
    int os = blockIdx.y * 24;
    for (int i = threadIdx.x; i < 27 * 24; i += 256)
        sow[i] = g_ow[(i / 24) * 768 + os + (i % 24)];
    __syncthreads();
    float acc[27];
#pragma unroll
    for (int j = 0; j < 27; j++) acc[j] = 0.f;
    for (int oo = 0; oo < 24; oo++) {
        float cv = convw[(size_t)(os + oo) * 6912 + r];
#pragma unroll
        for (int j = 0; j < 27; j++) acc[j] = fmaf(sow[j * 24 + oo], cv, acc[j]);
    }
#pragma unroll
    for (int j = 0; j < 27; j++)
        g_Fp[(size_t)blockIdx.y * (27 * 6912) + j * 6912 + r] = acc[j];
}
__global__ void k_fusedF_red()
{
    int i = blockIdx.x * 256 + threadIdx.x;
    float s = 0.f;
#pragma unroll
    for (int p = 0; p < 32; p++) s += g_Fp[(size_t)p * (27 * 6912) + i];
    g_F[i] = s;
}
__global__ void k_buildB_taps(const float* __restrict__ convw)
{
    __shared__ float s[6912];
    int o = blockIdx.x, t = threadIdx.x;
    const float* src = convw + (size_t)o * 6912;
    for (int i = t; i < 6912; i += 256) s[i] = src[i];
    __syncthreads();
#pragma unroll
    for (int kk = 0; kk < 9; kk++) {
        size_t base = (size_t)(kk * 768 + o) * EE;
        for (int c = t; c < 768; c += 256)
            g_Bh[base + c] = __float2half(s[c * 9 + kk]);
    }
}
__global__ void k_buildB_fused()
{
    int idx = blockIdx.x * 256 + threadIdx.x;
    if (idx >= (LDC - 6912) * EE) return;
    int nr = idx / EE, c = idx % EE;
    int n = 6912 + nr;
    float v = 0.f;
    if (n < NCOL) {
        int j = nr / 9, kk = nr % 9;
        v = g_F[j * 6912 + c * 9 + kk];
    }
    g_Bh[(size_t)n * EE + c] = __float2half(v);
}
__global__ void k_buildWp(const float* __restrict__ w, __nv_bfloat16* __restrict__ dst,
                          int chN, int srcslot)
{
    int idx = blockIdx.x * 256 + threadIdx.x;
    if (idx >= 384 * 768) return;
    int n = idx / 768, c = idx % 768;
    float v = (n < chN) ? w[n * 768 + c] : 0.f;
    __nv_bfloat16 h = __float2bfloat16(v);
    dst[(size_t)n * KW + srcslot * 1536 + c] = h;
    dst[(size_t)n * KW + srcslot * 1536 + 768 + c] = __float2bfloat16(v - __bfloat162float(h));
}

__global__ void k_gemv(const float* __restrict__ W, const float* __restrict__ x,
                       const float* __restrict__ bias, float* __restrict__ y, int K)
{
    int m = blockIdx.x, t = threadIdx.x;
    float a = 0.f;
    for (int k = t; k < K; k += 128) a += W[(size_t)m * K + k] * x[k];
    __shared__ float red[128];
    red[t] = a; __syncthreads();
    for (int s = 64; s > 0; s >>= 1) { if (t < s) red[t] += red[t + s]; __syncthreads(); }
    if (t == 0) y[m] = red[0] + (bias ? bias[m] : 0.f);
}
__global__ void k_prep_ow(const float* __restrict__ offw, const float* __restrict__ mskw)
{
    int i = blockIdx.x * 256 + threadIdx.x;
    if (i < 27 * EE) { int j = i / EE, c = i % EE; g_ow[i] = (j < 18) ? offw[j * EE + c] : mskw[(j - 18) * EE + c]; }
}

__global__ void k_offmask()
{
    int hw = blockIdx.x, y = hw >> 6, x = hw & 63;
    int j = threadIdx.x;
    __shared__ float lg[9];
    __shared__ float mx_s, sum_s;
    if (j < 27) {
        float v = g_boff[j];
#pragma unroll
        for (int k = 0; k < 9; k++) {
            int yy = y + k / 3 - 1, xx = x + k % 3 - 1;
            if (yy >= 0 && yy < 64 && xx >= 0 && xx < 64)
                v += g_C[(size_t)(yy * 64 + xx) * LDC + 6912 + j * 9 + k];
        }
        if (j < 18) g_off[hw * 18 + j] = v; else lg[j - 18] = v;
    }
    __syncthreads();
    if (j == 0) {
        float mx = lg[0];
        for (int t = 1; t < 9; t++) mx = fmaxf(mx, lg[t]);
        float s = 0.f;
        for (int t = 0; t < 9; t++) s += expf(lg[t] - mx);
        mx_s = mx; sum_s = s;
    }
    __syncthreads();
    if (j < 9) g_mask[hw * 9 + j] = expf(lg[j] - mx_s) / sum_s;
}

__global__ __launch_bounds__(192)
void k_deform_gather(const float* __restrict__ convb)
{
    int hw = blockIdx.x, y = hw >> 6, x = hw & 63;
    __shared__ int sidx[9][4];
    __shared__ float swgt[9][4];
    int tid = threadIdx.x;
    if (tid < 9) {
        int k = tid;
        float dy = g_off[hw * 18 + 2 * k], dx = g_off[hw * 18 + 2 * k + 1];
        float m = g_mask[k * HW + hw];  // raw-reshape mask indexing
        float py = (float)(y + k / 3 - 1) + dy;
        float px = (float)(x + k % 3 - 1) + dx;
        float y0f = floorf(py), x0f = floorf(px);
        float wy1 = py - y0f, wx1 = px - x0f;
        int y0 = (int)y0f, x0 = (int)x0f;
#pragma unroll
        for (int c = 0; c < 4; c++) {
            int yy = y0 + (c >> 1), xx = x0 + (c & 1);
            bool valid = (yy >= 0 && yy <= 63 && xx >= 0 && xx <= 63);
            int yc = min(max(yy, 0), 63), xc = min(max(xx, 0), 63);
            float w = ((c >> 1) ? wy1 : 1.f - wy1) * ((c & 1) ? wx1 : 1.f - wx1);
            sidx[k][c] = yc * 64 + xc;
            swgt[k][c] = valid ? w * m : 0.f;
        }
    }
    __syncthreads();
    int o = tid * 4;
    float4 acc = *(const float4*)(convb + o);
#pragma unroll
    for (int k = 0; k < 9; k++) {
        size_t cb = (size_t)k * EE + o;
#pragma unroll
        for (int c = 0; c < 4; c++) {
            float w = swgt[k][c];
            const float4 v = *(const float4*)(&g_C[(size_t)sidx[k][c] * LDC + cb]);
            acc.x = fmaf(w, v.x, acc.x); acc.y = fmaf(w, v.y, acc.y);
            acc.z = fmaf(w, v.z, acc.z); acc.w = fmaf(w, v.w, acc.w);
        }
    }
    *(float4*)(&g_blk[(size_t)hw * EE + o]) = acc;
}

__global__ void k_bn_partial()
{
    int b = blockIdx.x, t = threadIdx.x;
    float s0 = 0, s1 = 0, s2 = 0, q0 = 0, q1 = 0, q2v = 0;
    for (int r = 0; r < 128; r++) {
        const float* row = &g_blk[(size_t)(b * 128 + r) * EE];
        float v0 = row[t], v1 = row[t + 256], v2 = row[t + 512];
        s0 += v0; s1 += v1; s2 += v2; q0 += v0 * v0; q1 += v1 * v1; q2v += v2 * v2;
    }
    g_ps[b * EE + t] = s0; g_ps[b * EE + t + 256] = s1; g_ps[b * EE + t + 512] = s2;
    g_pq[b * EE + t] = q0; g_pq[b * EE + t + 256] = q1; g_pq[b * EE + t + 512] = q2v;
}
__global__ void k_bn_final(const float* __restrict__ bng, const float* __restrict__ bnb)
{
    int c = threadIdx.x;
    float s = 0, q = 0;
    for (int b = 0; b < 32; b++) { s += g_ps[b * EE + c]; q += g_pq[b * EE + c]; }
    float mu = s * (1.f / 4096.f);
    float var = q * (1.f / 4096.f) - mu * mu;
    float sc = rsqrtf(var + 1e-5f) * bng[c];
    g_sc[c] = sc; g_sh[c] = bnb[c] - mu * sc;
}
__global__ void k_bn_relu()
{
    int idx = (blockIdx.x * 256 + threadIdx.x) * 4;
    int m = idx / EE, c = idx % EE;
    float4 v = *(const float4*)&g_blk[idx];
    float4 sc = *(const float4*)&g_sc[c];
    float4 sh = *(const float4*)&g_sh[c];
    float r[4];
    r[0] = fmaxf(0.f, fmaf(v.x, sc.x, sh.x)); r[1] = fmaxf(0.f, fmaf(v.y, sc.y, sh.y));
    r[2] = fmaxf(0.f, fmaf(v.z, sc.z, sh.z)); r[3] = fmaxf(0.f, fmaf(v.w, sc.w, sh.w));
    __nv_bfloat16 hi[4], lo[4];
#pragma unroll
    for (int t = 0; t < 4; t++) {
        hi[t] = __float2bfloat16(r[t]);
        lo[t] = __float2bfloat16(r[t] - __bfloat162float(hi[t]));
    }
    *(uint2*)&g_acts[(size_t)m * KSPLIT + c] = *(uint2*)hi;
    *(uint2*)&g_acts[(size_t)m * KSPLIT + 768 + c] = *(uint2*)lo;
}

__global__ void k_softmax_hw()
{
    __shared__ float sm[4096];
    __shared__ float red[1024];
    int t = threadIdx.x;
    float lm = -1e30f;
    for (int i = t; i < 4096; i += 1024) { float v = g_q[i]; sm[i] = v; lm = fmaxf(lm, v); }
    red[t] = lm; __syncthreads();
    for (int s = 512; s > 0; s >>= 1) { if (t < s) red[t] = fmaxf(red[t], red[t + s]); __syncthreads(); }
    float mx = red[0]; __syncthreads();
    float ls = 0.f;
    for (int i = t; i < 4096; i += 1024) { float e = expf(sm[i] - mx); sm[i] = e; ls += e; }
    red[t] = ls; __syncthreads();
    for (int s = 512; s > 0; s >>= 1) { if (t < s) red[t] += red[t + s]; __syncthreads(); }
    float inv = 1.f / red[0]; __syncthreads();
    for (int i = t; i < 4096; i += 1024) g_wq[i] = sm[i] * inv;
}
__global__ void k_poolw()
{
    int b = blockIdx.x, t = threadIdx.x;
    float a0 = 0, a1 = 0, a2 = 0;
    for (int r = 0; r < 128; r++) {
        int hw = b * 128 + r;
        float w = g_wq[hw];
        const float* row = &g_cat[(size_t)hw * EE];
        a0 += w * row[t]; a1 += w * row[t + 256]; a2 += w * row[t + 512];
    }
    g_pt[b * EE + t] = a0; g_pt[b * EE + t + 256] = a1; g_pt[b * EE + t + 512] = a2;
}
__global__ void k_pool_fin()
{
    int c = threadIdx.x;
    float s = 0;
    for (int b = 0; b < 32; b++) s += g_pt[b * EE + c];
    g_t[c] = s;
}
__global__ void k_ln_sigmoid(const float* __restrict__ lng, const float* __restrict__ lnb)
{
    int c = threadIdx.x;
    __shared__ float buf[768];
    __shared__ float red[256];
    float v = g_wz[c];
    buf[c] = v; __syncthreads();
    if (c < 256) red[c] = buf[c] + buf[c + 256] + buf[c + 512];
    __syncthreads();
    for (int s = 128; s > 0; s >>= 1) { if (c < s) red[c] += red[c + s]; __syncthreads(); }
    float mu = red[0] * (1.f / 768.f); __syncthreads();
    float d = v - mu;
    buf[c] = d * d; __syncthreads();
    if (c < 256) red[c] = buf[c] + buf[c + 256] + buf[c + 512];
    __syncthreads();
    for (int s = 128; s > 0; s >>= 1) { if (c < s) red[c] += red[c + s]; __syncthreads(); }
    float var = red[0] * (1.f / 768.f);
    float z = d * rsqrtf(var + 1e-5f) * lng[c] + lnb[c];
    g_s[c] = 1.f / (1.f + expf(-z));
}
__global__ void k_x2()
{
    int idx = (blockIdx.x * 256 + threadIdx.x) * 4;
    int m = idx / EE, c = idx % EE;
    float4 v = *(const float4*)&g_cat[idx];
    float4 s = *(const float4*)&g_s[c];
    float r[4] = {v.x * s.x, v.y * s.y, v.z * s.z, v.w * s.w};
    *(float4*)&g_x2[idx] = *(float4*)r;
    __nv_bfloat16 hi[4], lo[4];
#pragma unroll
    for (int t = 0; t < 4; t++) {
        hi[t] = __float2bfloat16(r[t]);
        lo[t] = __float2bfloat16(r[t] - __bfloat162float(hi[t]));
    }
    *(uint2*)&g_x2s[(size_t)m * KSPLIT + c] = *(uint2*)hi;
    *(uint2*)&g_x2s[(size_t)m * KSPLIT + 768 + c] = *(uint2*)lo;
}
__global__ void k_colmax()
{
    int rr = blockIdx.x, t = threadIdx.x;
    float m = -1e30f;
    for (int i = t; i < 4096; i += 256) m = fmaxf(m, g_q2[(size_t)i * 384 + rr]);
    __shared__ float red[256];
    red[t] = m; __syncthreads();
    for (int s = 128; s > 0; s >>= 1) { if (t < s) red[t] = fmaxf(red[t], red[t + s]); __syncthreads(); }
    if (t == 0) g_mx[rr] = red[0];
}
__global__ void k_softmax384()
{
    int t = threadIdx.x;
    __shared__ float b[384];
    __shared__ float mx, sm;
    b[t] = g_mx[t]; __syncthreads();
    if (t == 0) { float m = b[0]; for (int i = 1; i < 384; i++) m = fmaxf(m, b[i]); mx = m; }
    __syncthreads();
    float e = expf(b[t] - mx);
    b[t] = e; __syncthreads();
    if (t == 0) { float s = 0; for (int i = 0; i < 384; i++) s += b[i]; sm = s; }
    __syncthreads();
    g_wq2[t] = e / sm;
}
__global__ void k_u(const float* __restrict__ spv)
{
    int c = threadIdx.x;
    float s = 0;
    for (int r = 0; r < 384; r++) s += g_wq2[r] * spv[r * EE + c];
    g_u[c] = s;
}
__global__ void k_final(const float* __restrict__ x5, const float* __restrict__ ng,
                        const float* __restrict__ nb, float* __restrict__ out)
{
    int hw = blockIdx.x, t = threadIdx.x;
    __shared__ float v[768];
    __shared__ float red[256];
    const float* x2r = g_x2 + (size_t)hw * EE;
    const float* catr = g_cat + (size_t)hw * EE;
    const float* x5r = x5 + (size_t)hw * EE;
    float d = 0;
    for (int c = t; c < 768; c += 256) d += g_u[c] * x2r[c];
    red[t] = d; __syncthreads();
    for (int s = 128; s > 0; s >>= 1) { if (t < s) red[t] += red[t + s]; __syncthreads(); }
    float wz2 = 1.f / (1.f + expf(-red[0])); __syncthreads();
    float ls = 0;
    for (int c = t; c < 768; c += 256) { float val = wz2 * x2r[c] + catr[c] + x5r[c]; v[c] = val; ls += val; }
    red[t] = ls; __syncthreads();
    for (int s = 128; s > 0; s >>= 1) { if (t < s) red[t] += red[t + s]; __syncthreads(); }
    float mu = red[0] * (1.f / 768.f); __syncthreads();
    float lq = 0;
    for (int c = t; c < 768; c += 256) { float dd = v[c] - mu; lq += dd * dd; }
    red[t] = lq; __syncthreads();
    for (int s = 128; s > 0; s >>= 1) { if (t < s) red[t] += red[t + s]; __syncthreads(); }
    float rstd = rsqrtf(red[0] * (1.f / 768.f) + 1e-5f); __syncthreads();
    for (int c = t; c < 768; c += 256) out[(size_t)hw * EE + c] = (v[c] - mu) * rstd * ng[c] + nb[c];
}

extern "C" void kernel_launch(void* const* d_in, const int* in_sizes, int n_in,
                              void* d_out, int out_size)
{
    const float* x[5];
    for (int i = 0; i < 5; i++) x[i] = (const float*)d_in[i];
    const float* convw = (const float*)d_in[5];
    const float* convb = (const float*)d_in[6];
    const float* offw = (const float*)d_in[7];
    const float* offb = (const float*)d_in[8];
    const float* mskw = (const float*)d_in[9];
    const float* mskb = (const float*)d_in[10];
    const float* bng = (const float*)d_in[11];
    const float* bnb = (const float*)d_in[12];
    const float* chq = (const float*)d_in[13];
    const float* chv = (const float*)d_in[14];
    const float* chz = (const float*)d_in[15];
    const float* lng = (const float*)d_in[16];
    const float* lnb = (const float*)d_in[17];
    const float* spq = (const float*)d_in[18];
    const float* spv = (const float*)d_in[19];
    const float* wa[5] = {(const float*)d_in[20], (const float*)d_in[21], (const float*)d_in[22],
                          (const float*)d_in[24], (const float*)d_in[26]};
    const float* wb[5] = {nullptr, nullptr, (const float*)d_in[23],
                          (const float*)d_in[25], (const float*)d_in[27]};
    const float* normg = (const float*)d_in[28];
    const float* normb = (const float*)d_in[29];

    float *pC, *pOw, *pBoff, *pCat, *pX2, *pQ2, *pQ, *pT, *pR, *pWz;
    __nv_bfloat16 *pXs, *pActs, *pX2s, *pWp, *pWsp;
    cudaGetSymbolAddress((void**)&pC, g_C);
    cudaGetSymbolAddress((void**)&pOw, g_ow);
    cudaGetSymbolAddress((void**)&pBoff, g_boff);
    cudaGetSymbolAddress((void**)&pCat, g_cat);
    cudaGetSymbolAddress((void**)&pX2, g_x2);
    cudaGetSymbolAddress((void**)&pQ2, g_q2);
    cudaGetSymbolAddress((void**)&pQ, g_q);
    cudaGetSymbolAddress((void**)&pT, g_t);
    cudaGetSymbolAddress((void**)&pR, g_r);
    cudaGetSymbolAddress((void**)&pWz, g_wz);
    cudaGetSymbolAddress((void**)&pXs, g_xs);
    cudaGetSymbolAddress((void**)&pActs, g_acts);
    cudaGetSymbolAddress((void**)&pX2s, g_x2s);
    cudaGetSymbolAddress((void**)&pWp, g_Wp);
    cudaGetSymbolAddress((void**)&pWsp, g_Wsp);

    const int SMEM_MAIN = 3 * 32768;
    const int SMEM_PROJ = 2 * 32768;
    cudaFuncSetAttribute(k_mma_main, cudaFuncAttributeMaxDynamicSharedMemorySize, SMEM_MAIN);
    cudaFuncSetAttribute(k_mma_proj, cudaFuncAttributeMaxDynamicSharedMemorySize, SMEM_PROJ);

    // ---- prep ----
    k_prep_ow<<<(27 * EE + 255) / 256, 256>>>(offw, mskw);
    k_gemv<<<18, 128>>>(pOw, convb, offb, pBoff, 768);
    k_gemv<<<9, 128>>>(pOw + 18 * 768, convb, mskb, pBoff + 18, 768);
    k_fusedF_part<<<dim3(27, 32), 256>>>(convw);
    k_fusedF_red<<<27 * 6912 / 256, 256>>>();
    k_buildB_taps<<<768, 256>>>(convw);
    k_buildB_fused<<<((LDC - 6912) * EE + 255) / 256, 256>>>();
    int chN[5] = {30, 100, 150, 220, 268};
    int chOff[5] = {0, 30, 130, 280, 500};
    for (int b = 0; b < 5; b++) {
        k_buildWp<<<(384 * 768 + 255) / 256, 256>>>(wa[b], pWp + (size_t)b * 384 * KW, chN[b], 0);
        if (wb[b])
            k_buildWp<<<(384 * 768 + 255) / 256, 256>>>(wb[b], pWp + (size_t)b * 384 * KW, chN[b], 1);
    }
    k_buildWp<<<(384 * 768 + 255) / 256, 256>>>(spq, pWsp, 384, 0);

    // ---- 5 blocks ----
    for (int b = 0; b < 5; b++) {
        k_splitA<<<(HW * EE + 255) / 256, 256>>>(x[b]);
        k_mma_main<<<dim3(56, 32), 256, SMEM_MAIN>>>(pC);
        k_offmask<<<HW, 32>>>();
        k_deform_gather<<<HW, 192>>>(convb);
        k_bn_partial<<<32, 256>>>();
        k_bn_final<<<1, 768>>>(bng, bnb);
        k_bn_relu<<<HW * EE / 1024, 256>>>();
        int nt = (chN[b] + 127) / 128;
        k_mma_proj<<<dim3(nt, 32), 256, SMEM_PROJ>>>(
            pActs, pXs, pWp + (size_t)b * 384 * KW, pCat, 768, chOff[b], chN[b],
            wb[b] ? 72 : 36);
    }

    // ---- CAM ----
    k_gemv<<<HW, 128>>>(pCat, chq, nullptr, pQ, 768);
    k_softmax_hw<<<1, 1024>>>();
    k_poolw<<<32, 256>>>();
    k_pool_fin<<<1, 768>>>();
    k_gemv<<<384, 128>>>(chv, pT, nullptr, pR, 768);
    k_gemv<<<768, 128>>>(chz, pR, nullptr, pWz, 384);
    k_ln_sigmoid<<<1, 768>>>(lng, lnb);
    k_x2<<<HW * EE / 1024, 256>>>();
    k_mma_proj<<<dim3(3, 32), 256, SMEM_PROJ>>>(pX2s, nullptr, pWsp, pQ2, 384, 0, 384, 36);
    k_colmax<<<384, 256>>>();
    k_softmax384<<<1, 384>>>();
    k_u<<<1, 768>>>(spv);
    k_final<<<HW, 256>>>(x[4], normg, normb, (float*)d_out);
}

// round 13
// speedup vs baseline: 4.5874x; 1.4805x over previous
#include <cuda_runtime.h>
#include <cuda_bf16.h>
#include <cuda_fp16.h>
#include <math.h>
#include <stdint.h>

#define HW 4096
#define EE 768
#define NCOL 7155
#define LDC 7168
#define KSPLIT 1536   // bf16 split row: [hi(768) | lo(768)] (proj path)
#define KW 3072       // proj weight row: [src0 hi|lo | src1 hi|lo] bf16

static __device__ float g_C[(size_t)HW * LDC];
static __device__ __half g_Ah[(size_t)HW * EE];                 // x fp16 (main, single)
static __device__ __half g_Bh[(size_t)LDC * EE];                // B fp16 (main, single)
static __device__ __nv_bfloat16 g_xs[(size_t)HW * KSPLIT];      // x split bf16 (proj)
static __device__ __nv_bfloat16 g_acts[(size_t)HW * KSPLIT];    // act split bf16 (proj)
static __device__ __nv_bfloat16 g_x2s[(size_t)HW * KSPLIT];     // x2 split bf16 (proj)
static __device__ __nv_bfloat16 g_Wp[5 * 384 * KW];
static __device__ __nv_bfloat16 g_Wsp[384 * KW];
static __device__ float g_F[27 * 6912];
static __device__ float g_Fp[32 * 27 * 6912];
static __device__ float g_ow[27 * EE];
static __device__ float g_boff[27];
static __device__ float g_off[HW * 18];
static __device__ float g_mask[HW * 9];
static __device__ float g_blk[(size_t)HW * EE];
static __device__ float g_cat[(size_t)HW * EE];
static __device__ float g_x2[(size_t)HW * EE];
static __device__ float g_q2[(size_t)HW * 384];
static __device__ float g_ps[32 * EE], g_pq[32 * EE], g_sc[EE], g_sh[EE];
static __device__ float g_q[HW], g_wq[HW];
static __device__ float g_pt[32 * EE], g_t[EE], g_r[384], g_wz[EE], g_s[EE];
static __device__ float g_mx[384], g_wq2[384], g_u[EE];

// ================= helpers =================
__device__ __forceinline__ uint32_t smem_u32(const void* p) {
    uint32_t a;
    asm("{ .reg .u64 t; cvta.to.shared.u64 t, %1; cvt.u32.u64 %0, t; }" : "=r"(a) : "l"(p));
    return a;
}
__device__ __forceinline__ void cp16(uint32_t dst, const void* src) {
    asm volatile("cp.async.cg.shared.global [%0], [%1], 16;" :: "r"(dst), "l"(src) : "memory");
}
template <int N> __device__ __forceinline__ void cp_wait() {
    asm volatile("cp.async.wait_group %0;" :: "n"(N) : "memory");
}
__device__ __forceinline__ void ldm_x4(uint32_t& r0, uint32_t& r1, uint32_t& r2, uint32_t& r3,
                                       uint32_t addr) {
    asm volatile("ldmatrix.sync.aligned.m8n8.x4.shared.b16 {%0,%1,%2,%3}, [%4];"
                 : "=r"(r0), "=r"(r1), "=r"(r2), "=r"(r3) : "r"(addr));
}
__device__ __forceinline__ void mma_bf16(float& d0, float& d1, float& d2, float& d3,
                                         uint32_t a0, uint32_t a1, uint32_t a2, uint32_t a3,
                                         uint32_t b0, uint32_t b1) {
    asm volatile(
        "mma.sync.aligned.m16n8k16.row.col.f32.bf16.bf16.f32 "
        "{%0,%1,%2,%3}, {%4,%5,%6,%7}, {%8,%9}, {%0,%1,%2,%3};"
        : "+f"(d0), "+f"(d1), "+f"(d2), "+f"(d3)
        : "r"(a0), "r"(a1), "r"(a2), "r"(a3), "r"(b0), "r"(b1));
}
__device__ __forceinline__ void mma_f16(float& d0, float& d1, float& d2, float& d3,
                                        uint32_t a0, uint32_t a1, uint32_t a2, uint32_t a3,
                                        uint32_t b0, uint32_t b1) {
    asm volatile(
        "mma.sync.aligned.m16n8k16.row.col.f32.f16.f16.f32 "
        "{%0,%1,%2,%3}, {%4,%5,%6,%7}, {%8,%9}, {%0,%1,%2,%3};"
        : "+f"(d0), "+f"(d1), "+f"(d2), "+f"(d3)
        : "r"(a0), "r"(a1), "r"(a2), "r"(a3), "r"(b0), "r"(b1));
}
#define SWZ128(x) ((x) ^ (((x) >> 3) & 0x70))

__device__ __forceinline__ void chunk_koffs(int chunk, int& kA, int& kB) {
    kA = (chunk < 12) ? chunk * 64 : (chunk < 24 ? (chunk - 12) * 64 : 768 + (chunk - 24) * 64);
    kB = (chunk < 12) ? chunk * 64 : (chunk < 24 ? 768 + (chunk - 12) * 64 : (chunk - 24) * 64);
}

// main plain fp16: 12 chunks of K=64
__device__ __forceinline__ void load_chunk_main(uint32_t sbase, int s, int chunk,
                                                int row0, int col0, int tid) {
    int k0 = chunk * 64;
    int r = tid & 127;
    bool isB = tid >= 128;
    const __half* g = isB ? &g_Bh[(size_t)(col0 + r) * EE + k0]
                          : &g_Ah[(size_t)(row0 + r) * EE + k0];
    uint32_t base = sbase + s * 32768 + (isB ? 16384 : 0);
    int rb = r * 128;
#pragma unroll
    for (int seg = 0; seg < 8; seg++)
        cp16(base + SWZ128(rb + seg * 16), g + seg * 8);
    asm volatile("cp.async.commit_group;" ::: "memory");
}

// ========== main GEMM: C[4096 x 7168] = a_f16 @ b_f16^T; 3-stage ==========
__global__ __launch_bounds__(256, 2)
void k_mma_main(float* __restrict__ C)
{
    extern __shared__ char smem_raw[];
    uint32_t sbase = smem_u32(smem_raw);
    int tid = threadIdx.x, wid = tid >> 5, lane = tid & 31;
    int row0 = blockIdx.y * 128, col0 = blockIdx.x * 128;
    int wm = (wid & 1) * 64, wn = (wid >> 1) * 32;

    float acc[4][4][4];
#pragma unroll
    for (int i = 0; i < 4; i++)
#pragma unroll
        for (int j = 0; j < 4; j++)
#pragma unroll
            for (int k = 0; k < 4; k++) acc[i][j][k] = 0.f;

    load_chunk_main(sbase, 0, 0, row0, col0, tid);
    load_chunk_main(sbase, 1, 1, row0, col0, tid);
    load_chunk_main(sbase, 2, 2, row0, col0, tid);

    for (int it = 0; it < 12; it++) {
        int s = it % 3;
        if (it < 10) cp_wait<2>(); else if (it == 10) cp_wait<1>(); else cp_wait<0>();
        __syncthreads();
        uint32_t abase = sbase + s * 32768;
        uint32_t bbase = abase + 16384;
#pragma unroll
        for (int k16 = 0; k16 < 4; k16++) {
            uint32_t b[4][2];
#pragma unroll
            for (int nb2 = 0; nb2 < 2; nb2++) {
                int n_row = wn + nb2 * 16 + (lane & 7) + ((lane >> 4) << 3);
                int k_byte = k16 * 32 + ((lane >> 3) & 1) * 16;
                uint32_t addr = bbase + SWZ128(n_row * 128 + k_byte);
                ldm_x4(b[nb2 * 2][0], b[nb2 * 2][1], b[nb2 * 2 + 1][0], b[nb2 * 2 + 1][1], addr);
            }
#pragma unroll
            for (int mf = 0; mf < 4; mf++) {
                int m_row = wm + mf * 16 + (lane & 15);
                int k_byte = k16 * 32 + (lane >> 4) * 16;
                uint32_t addr = abase + SWZ128(m_row * 128 + k_byte);
                uint32_t a0, a1, a2, a3;
                ldm_x4(a0, a1, a2, a3, addr);
#pragma unroll
                for (int nf = 0; nf < 4; nf++)
                    mma_f16(acc[mf][nf][0], acc[mf][nf][1], acc[mf][nf][2], acc[mf][nf][3],
                            a0, a1, a2, a3, b[nf][0], b[nf][1]);
            }
        }
        __syncthreads();
        if (it + 3 < 12) load_chunk_main(sbase, s, it + 3, row0, col0, tid);
    }

    int rr = lane >> 2, cc = (lane & 3) * 2;
#pragma unroll
    for (int mf = 0; mf < 4; mf++) {
#pragma unroll
        for (int nf = 0; nf < 4; nf++) {
            int r = row0 + wm + mf * 16 + rr;
            int c = col0 + wn + nf * 8 + cc;
            *(float2*)&C[(size_t)r * LDC + c] = make_float2(acc[mf][nf][0], acc[mf][nf][1]);
            *(float2*)&C[(size_t)(r + 8) * LDC + c] = make_float2(acc[mf][nf][2], acc[mf][nf][3]);
        }
    }
}

// ========== proj GEMM: C[:,colOff:colOff+N] = [A0|A1] @ W^T ; 2-stage bf16 ==========
__global__ __launch_bounds__(256, 2)
void k_mma_proj(const __nv_bfloat16* __restrict__ A0, const __nv_bfloat16* __restrict__ A1,
                const __nv_bfloat16* __restrict__ W, float* __restrict__ C,
                int ldc, int colOff, int N, int nch)
{
    extern __shared__ char smem_raw[];
    uint32_t sbase = smem_u32(smem_raw);
    int tid = threadIdx.x, wid = tid >> 5, lane = tid & 31;
    int row0 = blockIdx.y * 128, col0 = blockIdx.x * 128;
    int wm = (wid & 1) * 64, wn = (wid >> 1) * 32;

    float acc[4][4][4];
#pragma unroll
    for (int i = 0; i < 4; i++)
#pragma unroll
        for (int j = 0; j < 4; j++)
#pragma unroll
            for (int k = 0; k < 4; k++) acc[i][j][k] = 0.f;

    auto load = [&](int s, int chunk) {
        int src = (chunk >= 36) ? 1 : 0;
        int cc0 = chunk - src * 36;
        int kA, kB;
        chunk_koffs(cc0, kA, kB);
        int r = tid & 127;
        const __nv_bfloat16* g;
        uint32_t base;
        if (tid < 128) {
            g = (src ? A1 : A0) + (size_t)(row0 + r) * KSPLIT + kA;
            base = sbase + s * 32768;
        } else {
            g = W + (size_t)(col0 + r) * KW + src * 1536 + kB;
            base = sbase + s * 32768 + 16384;
        }
        int rb = r * 128;
#pragma unroll
        for (int seg = 0; seg < 8; seg++)
            cp16(base + SWZ128(rb + seg * 16), g + seg * 8);
        asm volatile("cp.async.commit_group;" ::: "memory");
    };

    load(0, 0);
    load(1, 1);

    for (int it = 0; it < nch; it++) {
        int s = it & 1;
        if (it < nch - 1) cp_wait<1>(); else cp_wait<0>();
        __syncthreads();
        uint32_t abase = sbase + s * 32768;
        uint32_t bbase = abase + 16384;
#pragma unroll
        for (int k16 = 0; k16 < 4; k16++) {
            uint32_t b[4][2];
#pragma unroll
            for (int nb2 = 0; nb2 < 2; nb2++) {
                int n_row = wn + nb2 * 16 + (lane & 7) + ((lane >> 4) << 3);
                int k_byte = k16 * 32 + ((lane >> 3) & 1) * 16;
                uint32_t addr = bbase + SWZ128(n_row * 128 + k_byte);
                ldm_x4(b[nb2 * 2][0], b[nb2 * 2][1], b[nb2 * 2 + 1][0], b[nb2 * 2 + 1][1], addr);
            }
#pragma unroll
            for (int mf = 0; mf < 4; mf++) {
                int m_row = wm + mf * 16 + (lane & 15);
                int k_byte = k16 * 32 + (lane >> 4) * 16;
                uint32_t addr = abase + SWZ128(m_row * 128 + k_byte);
                uint32_t a0, a1, a2, a3;
                ldm_x4(a0, a1, a2, a3, addr);
#pragma unroll
                for (int nf = 0; nf < 4; nf++)
                    mma_bf16(acc[mf][nf][0], acc[mf][nf][1], acc[mf][nf][2], acc[mf][nf][3],
                             a0, a1, a2, a3, b[nf][0], b[nf][1]);
            }
        }
        __syncthreads();
        if (it + 2 < nch) load(s, it + 2);
    }

    int rr = lane >> 2, cc = (lane & 3) * 2;
#pragma unroll
    for (int mf = 0; mf < 4; mf++) {
#pragma unroll
        for (int nf = 0; nf < 4; nf++) {
            int c = col0 + wn + nf * 8 + cc;
            if (c < N) {
                int r = row0 + wm + mf * 16 + rr;
                *(float2*)&C[(size_t)r * ldc + colOff + c] =
                    make_float2(acc[mf][nf][0], acc[mf][nf][1]);
                *(float2*)&C[(size_t)(r + 8) * ldc + colOff + c] =
                    make_float2(acc[mf][nf][2], acc[mf][nf][3]);
            }
        }
    }
}

// ---------- split / weight builders ----------
// writes fp16 (main, single) and bf16 split (proj A1 source)
__global__ void k_splitA(const float* __restrict__ x)
{
    int idx = blockIdx.x * 256 + threadIdx.x;
    if (idx < HW * EE) {
        int m = idx / EE, c = idx % EE;
        float v = x[idx];
        g_Ah[idx] = __float2half(v);
        __nv_bfloat16 bh = __float2bfloat16(v);
        g_xs[(size_t)m * KSPLIT + c] = bh;
        g_xs[(size_t)m * KSPLIT + 768 + c] = __float2bfloat16(v - __bfloat162float(bh));
    }
}
__global__ void k_fusedF_part(const float* __restrict__ convw)
{
    __shared__ float sow[27 * 24];
    int r = blockIdx.x * 256 + threadIdx.x;
    int os = blockIdx.y * 24;
    for (int i = threadIdx.x; i < 27 * 24; i += 256)
        sow[i] = g_ow[(i / 24) * 768 + os + (i % 24)];
    __syncthreads();
    float acc[27];
#pragma unroll
    for (int j = 0; j < 27; j++) acc[j] = 0.f;
    for (int oo = 0; oo < 24; oo++) {
        float cv = convw[(size_t)(os + oo) * 6912 + r];
#pragma unroll
        for (int j = 0; j < 27; j++) acc[j] = fmaf(sow[j * 24 + oo], cv, acc[j]);
    }
#pragma unroll
    for (int j = 0; j < 27; j++)
        g_Fp[(size_t)blockIdx.y * (27 * 6912) + j * 6912 + r] = acc[j];
}
__global__ void k_fusedF_red()
{
    int i = blockIdx.x * 256 + threadIdx.x;
    float s = 0.f;
#pragma unroll
    for (int p = 0; p < 32; p++) s += g_Fp[(size_t)p * (27 * 6912) + i];
    g_F[i] = s;
}
__global__ void k_buildB_taps(const float* __restrict__ convw)
{
    __shared__ float s[6912];
    int o = blockIdx.x, t = threadIdx.x;
    const float* src = convw + (size_t)o * 6912;
    for (int i = t; i < 6912; i += 256) s[i] = src[i];
    __syncthreads();
#pragma unroll
    for (int kk = 0; kk < 9; kk++) {
        size_t base = (size_t)(kk * 768 + o) * EE;
        for (int c = t; c < 768; c += 256)
            g_Bh[base + c] = __float2half(s[c * 9 + kk]);
    }
}
__global__ void k_buildB_fused()
{
    int idx = blockIdx.x * 256 + threadIdx.x;
    if (idx >= (LDC - 6912) * EE) return;
    int nr = idx / EE, c = idx % EE;
    int n = 6912 + nr;
    float v = 0.f;
    if (n < NCOL) {
        int j = nr / 9, kk = nr % 9;
        v = g_F[j * 6912 + c * 9 + kk];
    }
    g_Bh[(size_t)n * EE + c] = __float2half(v);
}
__global__ void k_buildWp(const float* __restrict__ w, __nv_bfloat16* __restrict__ dst,
                          int chN, int srcslot)
{
    int idx = blockIdx.x * 256 + threadIdx.x;
    if (idx >= 384 * 768) return;
    int n = idx / 768, c = idx % 768;
    float v = (n < chN) ? w[n * 768 + c] : 0.f;
    __nv_bfloat16 h = __float2bfloat16(v);
    dst[(size_t)n * KW + srcslot * 1536 + c] = h;
    dst[(size_t)n * KW + srcslot * 1536 + 768 + c] = __float2bfloat16(v - __bfloat162float(h));
}

__global__ void k_gemv(const float* __restrict__ W, const float* __restrict__ x,
                       const float* __restrict__ bias, float* __restrict__ y, int K)
{
    int m = blockIdx.x, t = threadIdx.x;
    float a = 0.f;
    for (int k = t; k < K; k += 128) a += W[(size_t)m * K + k] * x[k];
    __shared__ float red[128];
    red[t] = a; __syncthreads();
    for (int s = 64; s > 0; s >>= 1) { if (t < s) red[t] += red[t + s]; __syncthreads(); }
    if (t == 0) y[m] = red[0] + (bias ? bias[m] : 0.f);
}
__global__ void k_prep_ow(const float* __restrict__ offw, const float* __restrict__ mskw)
{
    int i = blockIdx.x * 256 + threadIdx.x;
    if (i < 27 * EE) { int j = i / EE, c = i % EE; g_ow[i] = (j < 18) ? offw[j * EE + c] : mskw[(j - 18) * EE + c]; }
}

__global__ void k_offmask()
{
    int hw = blockIdx.x, y = hw >> 6, x = hw & 63;
    int j = threadIdx.x;
    __shared__ float lg[9];
    __shared__ float mx_s, sum_s;
    if (j < 27) {
        float v = g_boff[j];
#pragma unroll
        for (int k = 0; k < 9; k++) {
            int yy = y + k / 3 - 1, xx = x + k % 3 - 1;
            if (yy >= 0 && yy < 64 && xx >= 0 && xx < 64)
                v += g_C[(size_t)(yy * 64 + xx) * LDC + 6912 + j * 9 + k];
        }
        if (j < 18) g_off[hw * 18 + j] = v; else lg[j - 18] = v;
    }
    __syncthreads();
    if (j == 0) {
        float mx = lg[0];
        for (int t = 1; t < 9; t++) mx = fmaxf(mx, lg[t]);
        float s = 0.f;
        for (int t = 0; t < 9; t++) s += expf(lg[t] - mx);
        mx_s = mx; sum_s = s;
    }
    __syncthreads();
    if (j < 9) g_mask[hw * 9 + j] = expf(lg[j] - mx_s) / sum_s;
}

__global__ __launch_bounds__(192)
void k_deform_gather(const float* __restrict__ convb)
{
    int hw = blockIdx.x, y = hw >> 6, x = hw & 63;
    __shared__ int sidx[9][4];
    __shared__ float swgt[9][4];
    int tid = threadIdx.x;
    if (tid < 9) {
        int k = tid;
        float dy = g_off[hw * 18 + 2 * k], dx = g_off[hw * 18 + 2 * k + 1];
        float m = g_mask[k * HW + hw];  // raw-reshape mask indexing
        float py = (float)(y + k / 3 - 1) + dy;
        float px = (float)(x + k % 3 - 1) + dx;
        float y0f = floorf(py), x0f = floorf(px);
        float wy1 = py - y0f, wx1 = px - x0f;
        int y0 = (int)y0f, x0 = (int)x0f;
#pragma unroll
        for (int c = 0; c < 4; c++) {
            int yy = y0 + (c >> 1), xx = x0 + (c & 1);
            bool valid = (yy >= 0 && yy <= 63 && xx >= 0 && xx <= 63);
            int yc = min(max(yy, 0), 63), xc = min(max(xx, 0), 63);
            float w = ((c >> 1) ? wy1 : 1.f - wy1) * ((c & 1) ? wx1 : 1.f - wx1);
            sidx[k][c] = yc * 64 + xc;
            swgt[k][c] = valid ? w * m : 0.f;
        }
    }
    __syncthreads();
    int o = tid * 4;
    float4 acc = *(const float4*)(convb + o);
#pragma unroll
    for (int k = 0; k < 9; k++) {
        size_t cb = (size_t)k * EE + o;
#pragma unroll
        for (int c = 0; c < 4; c++) {
            float w = swgt[k][c];
            const float4 v = *(const float4*)(&g_C[(size_t)sidx[k][c] * LDC + cb]);
            acc.x = fmaf(w, v.x, acc.x); acc.y = fmaf(w, v.y, acc.y);
            acc.z = fmaf(w, v.z, acc.z); acc.w = fmaf(w, v.w, acc.w);
        }
    }
    *(float4*)(&g_blk[(size_t)hw * EE + o]) = acc;
}

__global__ void k_bn_partial()
{
    int b = blockIdx.x, t = threadIdx.x;
    float s0 = 0, s1 = 0, s2 = 0, q0 = 0, q1 = 0, q2v = 0;
    for (int r = 0; r < 128; r++) {
        const float* row = &g_blk[(size_t)(b * 128 + r) * EE];
        float v0 = row[t], v1 = row[t + 256], v2 = row[t + 512];
        s0 += v0; s1 += v1; s2 += v2; q0 += v0 * v0; q1 += v1 * v1; q2v += v2 * v2;
    }
    g_ps[b * EE + t] = s0; g_ps[b * EE + t + 256] = s1; g_ps[b * EE + t + 512] = s2;
    g_pq[b * EE + t] = q0; g_pq[b * EE + t + 256] = q1; g_pq[b * EE + t + 512] = q2v;
}
__global__ void k_bn_final(const float* __restrict__ bng, const float* __restrict__ bnb)
{
    int c = threadIdx.x;
    float s = 0, q = 0;
    for (int b = 0; b < 32; b++) { s += g_ps[b * EE + c]; q += g_pq[b * EE + c]; }
    float mu = s * (1.f / 4096.f);
    float var = q * (1.f / 4096.f) - mu * mu;
    float sc = rsqrtf(var + 1e-5f) * bng[c];
    g_sc[c] = sc; g_sh[c] = bnb[c] - mu * sc;
}
__global__ void k_bn_relu()
{
    int idx = (blockIdx.x * 256 + threadIdx.x) * 4;
    int m = idx / EE, c = idx % EE;
    float4 v = *(const float4*)&g_blk[idx];
    float4 sc = *(const float4*)&g_sc[c];
    float4 sh = *(const float4*)&g_sh[c];
    float r[4];
    r[0] = fmaxf(0.f, fmaf(v.x, sc.x, sh.x)); r[1] = fmaxf(0.f, fmaf(v.y, sc.y, sh.y));
    r[2] = fmaxf(0.f, fmaf(v.z, sc.z, sh.z)); r[3] = fmaxf(0.f, fmaf(v.w, sc.w, sh.w));
    __nv_bfloat16 hi[4], lo[4];
#pragma unroll
    for (int t = 0; t < 4; t++) {
        hi[t] = __float2bfloat16(r[t]);
        lo[t] = __float2bfloat16(r[t] - __bfloat162float(hi[t]));
    }
    *(uint2*)&g_acts[(size_t)m * KSPLIT + c] = *(uint2*)hi;
    *(uint2*)&g_acts[(size_t)m * KSPLIT + 768 + c] = *(uint2*)lo;
}

__global__ void k_softmax_hw()
{
    __shared__ float sm[4096];
    __shared__ float red[1024];
    int t = threadIdx.x;
    float lm = -1e30f;
    for (int i = t; i < 4096; i += 1024) { float v = g_q[i]; sm[i] = v; lm = fmaxf(lm, v); }
    red[t] = lm; __syncthreads();
    for (int s = 512; s > 0; s >>= 1) { if (t < s) red[t] = fmaxf(red[t], red[t + s]); __syncthreads(); }
    float mx = red[0]; __syncthreads();
    float ls = 0.f;
    for (int i = t; i < 4096; i += 1024) { float e = expf(sm[i] - mx); sm[i] = e; ls += e; }
    red[t] = ls; __syncthreads();
    for (int s = 512; s > 0; s >>= 1) { if (t < s) red[t] += red[t + s]; __syncthreads(); }
    float inv = 1.f / red[0]; __syncthreads();
    for (int i = t; i < 4096; i += 1024) g_wq[i] = sm[i] * inv;
}
__global__ void k_poolw()
{
    int b = blockIdx.x, t = threadIdx.x;
    float a0 = 0, a1 = 0, a2 = 0;
    for (int r = 0; r < 128; r++) {
        int hw = b * 128 + r;
        float w = g_wq[hw];
        const float* row = &g_cat[(size_t)hw * EE];
        a0 += w * row[t]; a1 += w * row[t + 256]; a2 += w * row[t + 512];
    }
    g_pt[b * EE + t] = a0; g_pt[b * EE + t + 256] = a1; g_pt[b * EE + t + 512] = a2;
}
__global__ void k_pool_fin()
{
    int c = threadIdx.x;
    float s = 0;
    for (int b = 0; b < 32; b++) s += g_pt[b * EE + c];
    g_t[c] = s;
}
__global__ void k_ln_sigmoid(const float* __restrict__ lng, const float* __restrict__ lnb)
{
    int c = threadIdx.x;
    __shared__ float buf[768];
    __shared__ float red[256];
    float v = g_wz[c];
    buf[c] = v; __syncthreads();
    if (c < 256) red[c] = buf[c] + buf[c + 256] + buf[c + 512];
    __syncthreads();
    for (int s = 128; s > 0; s >>= 1) { if (c < s) red[c] += red[c + s]; __syncthreads(); }
    float mu = red[0] * (1.f / 768.f); __syncthreads();
    float d = v - mu;
    buf[c] = d * d; __syncthreads();
    if (c < 256) red[c] = buf[c] + buf[c + 256] + buf[c + 512];
    __syncthreads();
    for (int s = 128; s > 0; s >>= 1) { if (c < s) red[c] += red[c + s]; __syncthreads(); }
    float var = red[0] * (1.f / 768.f);
    float z = d * rsqrtf(var + 1e-5f) * lng[c] + lnb[c];
    g_s[c] = 1.f / (1.f + expf(-z));
}
__global__ void k_x2()
{
    int idx = (blockIdx.x * 256 + threadIdx.x) * 4;
    int m = idx / EE, c = idx % EE;
    float4 v = *(const float4*)&g_cat[idx];
    float4 s = *(const float4*)&g_s[c];
    float r[4] = {v.x * s.x, v.y * s.y, v.z * s.z, v.w * s.w};
    *(float4*)&g_x2[idx] = *(float4*)r;
    __nv_bfloat16 hi[4], lo[4];
#pragma unroll
    for (int t = 0; t < 4; t++) {
        hi[t] = __float2bfloat16(r[t]);
        lo[t] = __float2bfloat16(r[t] - __bfloat162float(hi[t]));
    }
    *(uint2*)&g_x2s[(size_t)m * KSPLIT + c] = *(uint2*)hi;
    *(uint2*)&g_x2s[(size_t)m * KSPLIT + 768 + c] = *(uint2*)lo;
}
__global__ void k_colmax()
{
    int rr = blockIdx.x, t = threadIdx.x;
    float m = -1e30f;
    for (int i = t; i < 4096; i += 256) m = fmaxf(m, g_q2[(size_t)i * 384 + rr]);
    __shared__ float red[256];
    red[t] = m; __syncthreads();
    for (int s = 128; s > 0; s >>= 1) { if (t < s) red[t] = fmaxf(red[t], red[t + s]); __syncthreads(); }
    if (t == 0) g_mx[rr] = red[0];
}
__global__ void k_softmax384()
{
    int t = threadIdx.x;
    __shared__ float b[384];
    __shared__ float mx, sm;
    b[t] = g_mx[t]; __syncthreads();
    if (t == 0) { float m = b[0]; for (int i = 1; i < 384; i++) m = fmaxf(m, b[i]); mx = m; }
    __syncthreads();
    float e = expf(b[t] - mx);
    b[t] = e; __syncthreads();
    if (t == 0) { float s = 0; for (int i = 0; i < 384; i++) s += b[i]; sm = s; }
    __syncthreads();
    g_wq2[t] = e / sm;
}
__global__ void k_u(const float* __restrict__ spv)
{
    int c = threadIdx.x;
    float s = 0;
    for (int r = 0; r < 384; r++) s += g_wq2[r] * spv[r * EE + c];
    g_u[c] = s;
}
__global__ void k_final(const float* __restrict__ x5, const float* __restrict__ ng,
                        const float* __restrict__ nb, float* __restrict__ out)
{
    int hw = blockIdx.x, t = threadIdx.x;
    __shared__ float v[768];
    __shared__ float red[256];
    const float* x2r = g_x2 + (size_t)hw * EE;
    const float* catr = g_cat + (size_t)hw * EE;
    const float* x5r = x5 + (size_t)hw * EE;
    float d = 0;
    for (int c = t; c < 768; c += 256) d += g_u[c] * x2r[c];
    red[t] = d; __syncthreads();
    for (int s = 128; s > 0; s >>= 1) { if (t < s) red[t] += red[t + s]; __syncthreads(); }
    float wz2 = 1.f / (1.f + expf(-red[0])); __syncthreads();
    float ls = 0;
    for (int c = t; c < 768; c += 256) { float val = wz2 * x2r[c] + catr[c] + x5r[c]; v[c] = val; ls += val; }
    red[t] = ls; __syncthreads();
    for (int s = 128; s > 0; s >>= 1) { if (t < s) red[t] += red[t + s]; __syncthreads(); }
    float mu = red[0] * (1.f / 768.f); __syncthreads();
    float lq = 0;
    for (int c = t; c < 768; c += 256) { float dd = v[c] - mu; lq += dd * dd; }
    red[t] = lq; __syncthreads();
    for (int s = 128; s > 0; s >>= 1) { if (t < s) red[t] += red[t + s]; __syncthreads(); }
    float rstd = rsqrtf(red[0] * (1.f / 768.f) + 1e-5f); __syncthreads();
    for (int c = t; c < 768; c += 256) out[(size_t)hw * EE + c] = (v[c] - mu) * rstd * ng[c] + nb[c];
}

extern "C" void kernel_launch(void* const* d_in, const int* in_sizes, int n_in,
                              void* d_out, int out_size)
{
    const float* x[5];
    for (int i = 0; i < 5; i++) x[i] = (const float*)d_in[i];
    const float* convw = (const float*)d_in[5];
    const float* convb = (const float*)d_in[6];
    const float* offw = (const float*)d_in[7];
    const float* offb = (const float*)d_in[8];
    const float* mskw = (const float*)d_in[9];
    const float* mskb = (const float*)d_in[10];
    const float* bng = (const float*)d_in[11];
    const float* bnb = (const float*)d_in[12];
    const float* chq = (const float*)d_in[13];
    const float* chv = (const float*)d_in[14];
    const float* chz = (const float*)d_in[15];
    const float* lng = (const float*)d_in[16];
    const float* lnb = (const float*)d_in[17];
    const float* spq = (const float*)d_in[18];
    const float* spv = (const float*)d_in[19];
    const float* wa[5] = {(const float*)d_in[20], (const float*)d_in[21], (const float*)d_in[22],
                          (const float*)d_in[24], (const float*)d_in[26]};
    const float* wb[5] = {nullptr, nullptr, (const float*)d_in[23],
                          (const float*)d_in[25], (const float*)d_in[27]};
    const float* normg = (const float*)d_in[28];
    const float* normb = (const float*)d_in[29];

    float *pC, *pOw, *pBoff, *pCat, *pX2, *pQ2, *pQ, *pT, *pR, *pWz;
    __nv_bfloat16 *pXs, *pActs, *pX2s, *pWp, *pWsp;
    cudaGetSymbolAddress((void**)&pC, g_C);
    cudaGetSymbolAddress((void**)&pOw, g_ow);
    cudaGetSymbolAddress((void**)&pBoff, g_boff);
    cudaGetSymbolAddress((void**)&pCat, g_cat);
    cudaGetSymbolAddress((void**)&pX2, g_x2);
    cudaGetSymbolAddress((void**)&pQ2, g_q2);
    cudaGetSymbolAddress((void**)&pQ, g_q);
    cudaGetSymbolAddress((void**)&pT, g_t);
    cudaGetSymbolAddress((void**)&pR, g_r);
    cudaGetSymbolAddress((void**)&pWz, g_wz);
    cudaGetSymbolAddress((void**)&pXs, g_xs);
    cudaGetSymbolAddress((void**)&pActs, g_acts);
    cudaGetSymbolAddress((void**)&pX2s, g_x2s);
    cudaGetSymbolAddress((void**)&pWp, g_Wp);
    cudaGetSymbolAddress((void**)&pWsp, g_Wsp);

    const int SMEM_MAIN = 3 * 32768;
    const int SMEM_PROJ = 2 * 32768;
    cudaFuncSetAttribute(k_mma_main, cudaFuncAttributeMaxDynamicSharedMemorySize, SMEM_MAIN);
    cudaFuncSetAttribute(k_mma_proj, cudaFuncAttributeMaxDynamicSharedMemorySize, SMEM_PROJ);

    // ---- prep ----
    k_prep_ow<<<(27 * EE + 255) / 256, 256>>>(offw, mskw);
    k_gemv<<<18, 128>>>(pOw, convb, offb, pBoff, 768);
    k_gemv<<<9, 128>>>(pOw + 18 * 768, convb, mskb, pBoff + 18, 768);
    k_fusedF_part<<<dim3(27, 32), 256>>>(convw);
    k_fusedF_red<<<27 * 6912 / 256, 256>>>();
    k_buildB_taps<<<768, 256>>>(convw);
    k_buildB_fused<<<((LDC - 6912) * EE + 255) / 256, 256>>>();
    int chN[5] = {30, 100, 150, 220, 268};
    int chOff[5] = {0, 30, 130, 280, 500};
    for (int b = 0; b < 5; b++) {
        k_buildWp<<<(384 * 768 + 255) / 256, 256>>>(wa[b], pWp + (size_t)b * 384 * KW, chN[b], 0);
        if (wb[b])
            k_buildWp<<<(384 * 768 + 255) / 256, 256>>>(wb[b], pWp + (size_t)b * 384 * KW, chN[b], 1);
    }
    k_buildWp<<<(384 * 768 + 255) / 256, 256>>>(spq, pWsp, 384, 0);

    // ---- 5 blocks ----
    for (int b = 0; b < 5; b++) {
        k_splitA<<<(HW * EE + 255) / 256, 256>>>(x[b]);
        k_mma_main<<<dim3(56, 32), 256, SMEM_MAIN>>>(pC);
        k_offmask<<<HW, 32>>>();
        k_deform_gather<<<HW, 192>>>(convb);
        k_bn_partial<<<32, 256>>>();
        k_bn_final<<<1, 768>>>(bng, bnb);
        k_bn_relu<<<HW * EE / 1024, 256>>>();
        int nt = (chN[b] + 127) / 128;
        k_mma_proj<<<dim3(nt, 32), 256, SMEM_PROJ>>>(
            pActs, pXs, pWp + (size_t)b * 384 * KW, pCat, 768, chOff[b], chN[b],
            wb[b] ? 72 : 36);
    }

    // ---- CAM ----
    k_gemv<<<HW, 128>>>(pCat, chq, nullptr, pQ, 768);
    k_softmax_hw<<<1, 1024>>>();
    k_poolw<<<32, 256>>>();
    k_pool_fin<<<1, 768>>>();
    k_gemv<<<384, 128>>>(chv, pT, nullptr, pR, 768);
    k_gemv<<<768, 128>>>(chz, pR, nullptr, pWz, 384);
    k_ln_sigmoid<<<1, 768>>>(lng, lnb);
    k_x2<<<HW * EE / 1024, 256>>>();
    k_mma_proj<<<dim3(3, 32), 256, SMEM_PROJ>>>(pX2s, nullptr, pWsp, pQ2, 384, 0, 384, 36);
    k_colmax<<<384, 256>>>();
    k_softmax384<<<1, 384>>>();
    k_u<<<1, 768>>>(spv);
    k_final<<<HW, 256>>>(x[4], normg, normb, (float*)d_out);
}

// round 14
// speedup vs baseline: 4.8021x; 1.0468x over previous
#include <cuda_runtime.h>
#include <cuda_bf16.h>
#include <cuda_fp16.h>
#include <math.h>
#include <stdint.h>

#define HW 4096
#define EE 768
#define NCOL 7155
#define LDC 7168
#define KSPLIT 1536   // bf16 split row: [hi(768) | lo(768)] (proj path)
#define KW 3072       // proj weight row: [src0 hi|lo | src1 hi|lo] bf16

static __device__ __half g_Ch[(size_t)HW * LDC];                // main GEMM output (fp16, 58 MB)
static __device__ __half g_Ah[(size_t)HW * EE];                 // x fp16 (main)
static __device__ __half g_Bh[(size_t)LDC * EE];                // B fp16 (main)
static __device__ __nv_bfloat16 g_xs[(size_t)HW * KSPLIT];      // x split bf16 (proj)
static __device__ __nv_bfloat16 g_acts[(size_t)HW * KSPLIT];    // act split bf16 (proj)
static __device__ __nv_bfloat16 g_x2s[(size_t)HW * KSPLIT];     // x2 split bf16 (proj)
static __device__ __nv_bfloat16 g_Wp[5 * 384 * KW];
static __device__ __nv_bfloat16 g_Wsp[384 * KW];
static __device__ float g_F[27 * 6912];
static __device__ float g_Fp[32 * 27 * 6912];
static __device__ float g_ow[27 * EE];
static __device__ float g_boff[27];
static __device__ float g_off[HW * 18];
static __device__ float g_mask[HW * 9];
static __device__ float g_blk[(size_t)HW * EE];
static __device__ float g_cat[(size_t)HW * EE];
static __device__ float g_x2[(size_t)HW * EE];
static __device__ float g_q2[(size_t)HW * 384];
static __device__ float g_ps[32 * EE], g_pq[32 * EE], g_sc[EE], g_sh[EE];
static __device__ float g_q[HW], g_wq[HW];
static __device__ float g_pt[32 * EE], g_t[EE], g_r[384], g_wz[EE], g_s[EE];
static __device__ float g_mx[384], g_wq2[384], g_u[EE];

// ================= helpers =================
__device__ __forceinline__ uint32_t smem_u32(const void* p) {
    uint32_t a;
    asm("{ .reg .u64 t; cvta.to.shared.u64 t, %1; cvt.u32.u64 %0, t; }" : "=r"(a) : "l"(p));
    return a;
}
__device__ __forceinline__ void cp16(uint32_t dst, const void* src) {
    asm volatile("cp.async.cg.shared.global [%0], [%1], 16;" :: "r"(dst), "l"(src) : "memory");
}
template <int N> __device__ __forceinline__ void cp_wait() {
    asm volatile("cp.async.wait_group %0;" :: "n"(N) : "memory");
}
__device__ __forceinline__ void ldm_x4(uint32_t& r0, uint32_t& r1, uint32_t& r2, uint32_t& r3,
                                       uint32_t addr) {
    asm volatile("ldmatrix.sync.aligned.m8n8.x4.shared.b16 {%0,%1,%2,%3}, [%4];"
                 : "=r"(r0), "=r"(r1), "=r"(r2), "=r"(r3) : "r"(addr));
}
__device__ __forceinline__ void mma_bf16(float& d0, float& d1, float& d2, float& d3,
                                         uint32_t a0, uint32_t a1, uint32_t a2, uint32_t a3,
                                         uint32_t b0, uint32_t b1) {
    asm volatile(
        "mma.sync.aligned.m16n8k16.row.col.f32.bf16.bf16.f32 "
        "{%0,%1,%2,%3}, {%4,%5,%6,%7}, {%8,%9}, {%0,%1,%2,%3};"
        : "+f"(d0), "+f"(d1), "+f"(d2), "+f"(d3)
        : "r"(a0), "r"(a1), "r"(a2), "r"(a3), "r"(b0), "r"(b1));
}
__device__ __forceinline__ void mma_f16(float& d0, float& d1, float& d2, float& d3,
                                        uint32_t a0, uint32_t a1, uint32_t a2, uint32_t a3,
                                        uint32_t b0, uint32_t b1) {
    asm volatile(
        "mma.sync.aligned.m16n8k16.row.col.f32.f16.f16.f32 "
        "{%0,%1,%2,%3}, {%4,%5,%6,%7}, {%8,%9}, {%0,%1,%2,%3};"
        : "+f"(d0), "+f"(d1), "+f"(d2), "+f"(d3)
        : "r"(a0), "r"(a1), "r"(a2), "r"(a3), "r"(b0), "r"(b1));
}
#define SWZ128(x) ((x) ^ (((x) >> 3) & 0x70))

__device__ __forceinline__ void chunk_koffs(int chunk, int& kA, int& kB) {
    kA = (chunk < 12) ? chunk * 64 : (chunk < 24 ? (chunk - 12) * 64 : 768 + (chunk - 24) * 64);
    kB = (chunk < 12) ? chunk * 64 : (chunk < 24 ? 768 + (chunk - 12) * 64 : (chunk - 24) * 64);
}

// main plain fp16: 12 chunks of K=64
__device__ __forceinline__ void load_chunk_main(uint32_t sbase, int s, int chunk,
                                                int row0, int col0, int tid) {
    int k0 = chunk * 64;
    int r = tid & 127;
    bool isB = tid >= 128;
    const __half* g = isB ? &g_Bh[(size_t)(col0 + r) * EE + k0]
                          : &g_Ah[(size_t)(row0 + r) * EE + k0];
    uint32_t base = sbase + s * 32768 + (isB ? 16384 : 0);
    int rb = r * 128;
#pragma unroll
    for (int seg = 0; seg < 8; seg++)
        cp16(base + SWZ128(rb + seg * 16), g + seg * 8);
    asm volatile("cp.async.commit_group;" ::: "memory");
}

// ========== main GEMM: C_h[4096 x 7168] = a_f16 @ b_f16^T; 3-stage; fp16 output ==========
__global__ __launch_bounds__(256, 2)
void k_mma_main()
{
    extern __shared__ char smem_raw[];
    uint32_t sbase = smem_u32(smem_raw);
    int tid = threadIdx.x, wid = tid >> 5, lane = tid & 31;
    int row0 = blockIdx.y * 128, col0 = blockIdx.x * 128;
    int wm = (wid & 1) * 64, wn = (wid >> 1) * 32;

    float acc[4][4][4];
#pragma unroll
    for (int i = 0; i < 4; i++)
#pragma unroll
        for (int j = 0; j < 4; j++)
#pragma unroll
            for (int k = 0; k < 4; k++) acc[i][j][k] = 0.f;

    load_chunk_main(sbase, 0, 0, row0, col0, tid);
    load_chunk_main(sbase, 1, 1, row0, col0, tid);
    load_chunk_main(sbase, 2, 2, row0, col0, tid);

    for (int it = 0; it < 12; it++) {
        int s = it % 3;
        if (it < 10) cp_wait<2>(); else if (it == 10) cp_wait<1>(); else cp_wait<0>();
        __syncthreads();
        uint32_t abase = sbase + s * 32768;
        uint32_t bbase = abase + 16384;
#pragma unroll
        for (int k16 = 0; k16 < 4; k16++) {
            uint32_t b[4][2];
#pragma unroll
            for (int nb2 = 0; nb2 < 2; nb2++) {
                int n_row = wn + nb2 * 16 + (lane & 7) + ((lane >> 4) << 3);
                int k_byte = k16 * 32 + ((lane >> 3) & 1) * 16;
                uint32_t addr = bbase + SWZ128(n_row * 128 + k_byte);
                ldm_x4(b[nb2 * 2][0], b[nb2 * 2][1], b[nb2 * 2 + 1][0], b[nb2 * 2 + 1][1], addr);
            }
#pragma unroll
            for (int mf = 0; mf < 4; mf++) {
                int m_row = wm + mf * 16 + (lane & 15);
                int k_byte = k16 * 32 + (lane >> 4) * 16;
                uint32_t addr = abase + SWZ128(m_row * 128 + k_byte);
                uint32_t a0, a1, a2, a3;
                ldm_x4(a0, a1, a2, a3, addr);
#pragma unroll
                for (int nf = 0; nf < 4; nf++)
                    mma_f16(acc[mf][nf][0], acc[mf][nf][1], acc[mf][nf][2], acc[mf][nf][3],
                            a0, a1, a2, a3, b[nf][0], b[nf][1]);
            }
        }
        __syncthreads();
        if (it + 3 < 12) load_chunk_main(sbase, s, it + 3, row0, col0, tid);
    }

    int rr = lane >> 2, cc = (lane & 3) * 2;
#pragma unroll
    for (int mf = 0; mf < 4; mf++) {
#pragma unroll
        for (int nf = 0; nf < 4; nf++) {
            int r = row0 + wm + mf * 16 + rr;
            int c = col0 + wn + nf * 8 + cc;
            *(__half2*)&g_Ch[(size_t)r * LDC + c] =
                __floats2half2_rn(acc[mf][nf][0], acc[mf][nf][1]);
            *(__half2*)&g_Ch[(size_t)(r + 8) * LDC + c] =
                __floats2half2_rn(acc[mf][nf][2], acc[mf][nf][3]);
        }
    }
}

// ========== proj GEMM: C[:,colOff:colOff+N] = [A0|A1] @ W^T ; 2-stage bf16 ==========
__global__ __launch_bounds__(256, 2)
void k_mma_proj(const __nv_bfloat16* __restrict__ A0, const __nv_bfloat16* __restrict__ A1,
                const __nv_bfloat16* __restrict__ W, float* __restrict__ C,
                int ldc, int colOff, int N, int nch)
{
    extern __shared__ char smem_raw[];
    uint32_t sbase = smem_u32(smem_raw);
    int tid = threadIdx.x, wid = tid >> 5, lane = tid & 31;
    int row0 = blockIdx.y * 128, col0 = blockIdx.x * 128;
    int wm = (wid & 1) * 64, wn = (wid >> 1) * 32;

    float acc[4][4][4];
#pragma unroll
    for (int i = 0; i < 4; i++)
#pragma unroll
        for (int j = 0; j < 4; j++)
#pragma unroll
            for (int k = 0; k < 4; k++) acc[i][j][k] = 0.f;

    auto load = [&](int s, int chunk) {
        int src = (chunk >= 36) ? 1 : 0;
        int cc0 = chunk - src * 36;
        int kA, kB;
        chunk_koffs(cc0, kA, kB);
        int r = tid & 127;
        const __nv_bfloat16* g;
        uint32_t base;
        if (tid < 128) {
            g = (src ? A1 : A0) + (size_t)(row0 + r) * KSPLIT + kA;
            base = sbase + s * 32768;
        } else {
            g = W + (size_t)(col0 + r) * KW + src * 1536 + kB;
            base = sbase + s * 32768 + 16384;
        }
        int rb = r * 128;
#pragma unroll
        for (int seg = 0; seg < 8; seg++)
            cp16(base + SWZ128(rb + seg * 16), g + seg * 8);
        asm volatile("cp.async.commit_group;" ::: "memory");
    };

    load(0, 0);
    load(1, 1);

    for (int it = 0; it < nch; it++) {
        int s = it & 1;
        if (it < nch - 1) cp_wait<1>(); else cp_wait<0>();
        __syncthreads();
        uint32_t abase = sbase + s * 32768;
        uint32_t bbase = abase + 16384;
#pragma unroll
        for (int k16 = 0; k16 < 4; k16++) {
            uint32_t b[4][2];
#pragma unroll
            for (int nb2 = 0; nb2 < 2; nb2++) {
                int n_row = wn + nb2 * 16 + (lane & 7) + ((lane >> 4) << 3);
                int k_byte = k16 * 32 + ((lane >> 3) & 1) * 16;
                uint32_t addr = bbase + SWZ128(n_row * 128 + k_byte);
                ldm_x4(b[nb2 * 2][0], b[nb2 * 2][1], b[nb2 * 2 + 1][0], b[nb2 * 2 + 1][1], addr);
            }
#pragma unroll
            for (int mf = 0; mf < 4; mf++) {
                int m_row = wm + mf * 16 + (lane & 15);
                int k_byte = k16 * 32 + (lane >> 4) * 16;
                uint32_t addr = abase + SWZ128(m_row * 128 + k_byte);
                uint32_t a0, a1, a2, a3;
                ldm_x4(a0, a1, a2, a3, addr);
#pragma unroll
                for (int nf = 0; nf < 4; nf++)
                    mma_bf16(acc[mf][nf][0], acc[mf][nf][1], acc[mf][nf][2], acc[mf][nf][3],
                             a0, a1, a2, a3, b[nf][0], b[nf][1]);
            }
        }
        __syncthreads();
        if (it + 2 < nch) load(s, it + 2);
    }

    int rr = lane >> 2, cc = (lane & 3) * 2;
#pragma unroll
    for (int mf = 0; mf < 4; mf++) {
#pragma unroll
        for (int nf = 0; nf < 4; nf++) {
            int c = col0 + wn + nf * 8 + cc;
            if (c < N) {
                int r = row0 + wm + mf * 16 + rr;
                *(float2*)&C[(size_t)r * ldc + colOff + c] =
                    make_float2(acc[mf][nf][0], acc[mf][nf][1]);
                *(float2*)&C[(size_t)(r + 8) * ldc + colOff + c] =
                    make_float2(acc[mf][nf][2], acc[mf][nf][3]);
            }
        }
    }
}

// ---------- split / weight builders ----------
__global__ void k_splitA(const float* __restrict__ x)
{
    int idx = blockIdx.x * 256 + threadIdx.x;
    if (idx < HW * EE) {
        int m = idx / EE, c = idx % EE;
        float v = x[idx];
        g_Ah[idx] = __float2half(v);
        __nv_bfloat16 bh = __float2bfloat16(v);
        g_xs[(size_t)m * KSPLIT + c] = bh;
        g_xs[(size_t)m * KSPLIT + 768 + c] = __float2bfloat16(v - __bfloat162float(bh));
    }
}
__global__ void k_fusedF_part(const float* __restrict__ convw)
{
    __shared__ float sow[27 * 24];
    int r = blockIdx.x * 256 + threadIdx.x;
    int os = blockIdx.y * 24;
    for (int i = threadIdx.x; i < 27 * 24; i += 256)
        sow[i] = g_ow[(i / 24) * 768 + os + (i % 24)];
    __syncthreads();
    float acc[27];
#pragma unroll
    for (int j = 0; j < 27; j++) acc[j] = 0.f;
    for (int oo = 0; oo < 24; oo++) {
        float cv = convw[(size_t)(os + oo) * 6912 + r];
#pragma unroll
        for (int j = 0; j < 27; j++) acc[j] = fmaf(sow[j * 24 + oo], cv, acc[j]);
    }
#pragma unroll
    for (int j = 0; j < 27; j++)
        g_Fp[(size_t)blockIdx.y * (27 * 6912) + j * 6912 + r] = acc[j];
}
__global__ void k_fusedF_red()
{
    int i = blockIdx.x * 256 + threadIdx.x;
    float s = 0.f;
#pragma unroll
    for (int p = 0; p < 32; p++) s += g_Fp[(size_t)p * (27 * 6912) + i];
    g_F[i] = s;
}
__global__ void k_buildB_taps(const float* __restrict__ convw)
{
    __shared__ float s[6912];
    int o = blockIdx.x, t = threadIdx.x;
    const float* src = convw + (size_t)o * 6912;
    for (int i = t; i < 6912; i += 256) s[i] = src[i];
    __syncthreads();
#pragma unroll
    for (int kk = 0; kk < 9; kk++) {
        size_t base = (size_t)(kk * 768 + o) * EE;
        for (int c = t; c < 768; c += 256)
            g_Bh[base + c] = __float2half(s[c * 9 + kk]);
    }
}
__global__ void k_buildB_fused()
{
    int idx = blockIdx.x * 256 + threadIdx.x;
    if (idx >= (LDC - 6912) * EE) return;
    int nr = idx / EE, c = idx % EE;
    int n = 6912 + nr;
    float v = 0.f;
    if (n < NCOL) {
        int j = nr / 9, kk = nr % 9;
        v = g_F[j * 6912 + c * 9 + kk];
    }
    g_Bh[(size_t)n * EE + c] = __float2half(v);
}
__global__ void k_buildWp(const float* __restrict__ w, __nv_bfloat16* __restrict__ dst,
                          int chN, int srcslot)
{
    int idx = blockIdx.x * 256 + threadIdx.x;
    if (idx >= 384 * 768) return;
    int n = idx / 768, c = idx % 768;
    float v = (n < chN) ? w[n * 768 + c] : 0.f;
    __nv_bfloat16 h = __float2bfloat16(v);
    dst[(size_t)n * KW + srcslot * 1536 + c] = h;
    dst[(size_t)n * KW + srcslot * 1536 + 768 + c] = __float2bfloat16(v - __bfloat162float(h));
}

__global__ void k_gemv(const float* __restrict__ W, const float* __restrict__ x,
                       const float* __restrict__ bias, float* __restrict__ y, int K)
{
    int m = blockIdx.x, t = threadIdx.x;
    float a = 0.f;
    for (int k = t; k < K; k += 128) a += W[(size_t)m * K + k] * x[k];
    __shared__ float red[128];
    red[t] = a; __syncthreads();
    for (int s = 64; s > 0; s >>= 1) { if (t < s) red[t] += red[t + s]; __syncthreads(); }
    if (t == 0) y[m] = red[0] + (bias ? bias[m] : 0.f);
}
__global__ void k_prep_ow(const float* __restrict__ offw, const float* __restrict__ mskw)
{
    int i = blockIdx.x * 256 + threadIdx.x;
    if (i < 27 * EE) { int j = i / EE, c = i % EE; g_ow[i] = (j < 18) ? offw[j * EE + c] : mskw[(j - 18) * EE + c]; }
}

__global__ void k_offmask()
{
    int hw = blockIdx.x, y = hw >> 6, x = hw & 63;
    int j = threadIdx.x;
    __shared__ float lg[9];
    __shared__ float mx_s, sum_s;
    if (j < 27) {
        float v = g_boff[j];
#pragma unroll
        for (int k = 0; k < 9; k++) {
            int yy = y + k / 3 - 1, xx = x + k % 3 - 1;
            if (yy >= 0 && yy < 64 && xx >= 0 && xx < 64)
                v += __half2float(g_Ch[(size_t)(yy * 64 + xx) * LDC + 6912 + j * 9 + k]);
        }
        if (j < 18) g_off[hw * 18 + j] = v; else lg[j - 18] = v;
    }
    __syncthreads();
    if (j == 0) {
        float mx = lg[0];
        for (int t = 1; t < 9; t++) mx = fmaxf(mx, lg[t]);
        float s = 0.f;
        for (int t = 0; t < 9; t++) s += expf(lg[t] - mx);
        mx_s = mx; sum_s = s;
    }
    __syncthreads();
    if (j < 9) g_mask[hw * 9 + j] = expf(lg[j] - mx_s) / sum_s;
}

__global__ __launch_bounds__(192)
void k_deform_gather(const float* __restrict__ convb)
{
    int hw = blockIdx.x, y = hw >> 6, x = hw & 63;
    __shared__ int sidx[9][4];
    __shared__ float swgt[9][4];
    int tid = threadIdx.x;
    if (tid < 9) {
        int k = tid;
        float dy = g_off[hw * 18 + 2 * k], dx = g_off[hw * 18 + 2 * k + 1];
        float m = g_mask[k * HW + hw];  // raw-reshape mask indexing
        float py = (float)(y + k / 3 - 1) + dy;
        float px = (float)(x + k % 3 - 1) + dx;
        float y0f = floorf(py), x0f = floorf(px);
        float wy1 = py - y0f, wx1 = px - x0f;
        int y0 = (int)y0f, x0 = (int)x0f;
#pragma unroll
        for (int c = 0; c < 4; c++) {
            int yy = y0 + (c >> 1), xx = x0 + (c & 1);
            bool valid = (yy >= 0 && yy <= 63 && xx >= 0 && xx <= 63);
            int yc = min(max(yy, 0), 63), xc = min(max(xx, 0), 63);
            float w = ((c >> 1) ? wy1 : 1.f - wy1) * ((c & 1) ? wx1 : 1.f - wx1);
            sidx[k][c] = yc * 64 + xc;
            swgt[k][c] = valid ? w * m : 0.f;
        }
    }
    __syncthreads();
    int o = tid * 4;
    float4 acc = *(const float4*)(convb + o);
#pragma unroll
    for (int k = 0; k < 9; k++) {
        size_t cb = (size_t)k * EE + o;
#pragma unroll
        for (int c = 0; c < 4; c++) {
            float w = swgt[k][c];
            const __half2* p = (const __half2*)&g_Ch[(size_t)sidx[k][c] * LDC + cb];
            uint2 raw = *(const uint2*)p;
            float2 v01 = __half22float2(*(const __half2*)&raw.x);
            float2 v23 = __half22float2(*(const __half2*)&raw.y);
            acc.x = fmaf(w, v01.x, acc.x); acc.y = fmaf(w, v01.y, acc.y);
            acc.z = fmaf(w, v23.x, acc.z); acc.w = fmaf(w, v23.y, acc.w);
        }
    }
    *(float4*)(&g_blk[(size_t)hw * EE + o]) = acc;
}

__global__ void k_bn_partial()
{
    int b = blockIdx.x, t = threadIdx.x;
    float s0 = 0, s1 = 0, s2 = 0, q0 = 0, q1 = 0, q2v = 0;
    for (int r = 0; r < 128; r++) {
        const float* row = &g_blk[(size_t)(b * 128 + r) * EE];
        float v0 = row[t], v1 = row[t + 256], v2 = row[t + 512];
        s0 += v0; s1 += v1; s2 += v2; q0 += v0 * v0; q1 += v1 * v1; q2v += v2 * v2;
    }
    g_ps[b * EE + t] = s0; g_ps[b * EE + t + 256] = s1; g_ps[b * EE + t + 512] = s2;
    g_pq[b * EE + t] = q0; g_pq[b * EE + t + 256] = q1; g_pq[b * EE + t + 512] = q2v;
}
__global__ void k_bn_final(const float* __restrict__ bng, const float* __restrict__ bnb)
{
    int c = threadIdx.x;
    float s = 0, q = 0;
    for (int b = 0; b < 32; b++) { s += g_ps[b * EE + c]; q += g_pq[b * EE + c]; }
    float mu = s * (1.f / 4096.f);
    float var = q * (1.f / 4096.f) - mu * mu;
    float sc = rsqrtf(var + 1e-5f) * bng[c];
    g_sc[c] = sc; g_sh[c] = bnb[c] - mu * sc;
}
__global__ void k_bn_relu()
{
    int idx = (blockIdx.x * 256 + threadIdx.x) * 4;
    int m = idx / EE, c = idx % EE;
    float4 v = *(const float4*)&g_blk[idx];
    float4 sc = *(const float4*)&g_sc[c];
    float4 sh = *(const float4*)&g_sh[c];
    float r[4];
    r[0] = fmaxf(0.f, fmaf(v.x, sc.x, sh.x)); r[1] = fmaxf(0.f, fmaf(v.y, sc.y, sh.y));
    r[2] = fmaxf(0.f, fmaf(v.z, sc.z, sh.z)); r[3] = fmaxf(0.f, fmaf(v.w, sc.w, sh.w));
    __nv_bfloat16 hi[4], lo[4];
#pragma unroll
    for (int t = 0; t < 4; t++) {
        hi[t] = __float2bfloat16(r[t]);
        lo[t] = __float2bfloat16(r[t] - __bfloat162float(hi[t]));
    }
    *(uint2*)&g_acts[(size_t)m * KSPLIT + c] = *(uint2*)hi;
    *(uint2*)&g_acts[(size_t)m * KSPLIT + 768 + c] = *(uint2*)lo;
}

__global__ void k_softmax_hw()
{
    __shared__ float sm[4096];
    __shared__ float red[1024];
    int t = threadIdx.x;
    float lm = -1e30f;
    for (int i = t; i < 4096; i += 1024) { float v = g_q[i]; sm[i] = v; lm = fmaxf(lm, v); }
    red[t] = lm; __syncthreads();
    for (int s = 512; s > 0; s >>= 1) { if (t < s) red[t] = fmaxf(red[t], red[t + s]); __syncthreads(); }
    float mx = red[0]; __syncthreads();
    float ls = 0.f;
    for (int i = t; i < 4096; i += 1024) { float e = expf(sm[i] - mx); sm[i] = e; ls += e; }
    red[t] = ls; __syncthreads();
    for (int s = 512; s > 0; s >>= 1) { if (t < s) red[t] += red[t + s]; __syncthreads(); }
    float inv = 1.f / red[0]; __syncthreads();
    for (int i = t; i < 4096; i += 1024) g_wq[i] = sm[i] * inv;
}
__global__ void k_poolw()
{
    int b = blockIdx.x, t = threadIdx.x;
    float a0 = 0, a1 = 0, a2 = 0;
    for (int r = 0; r < 128; r++) {
        int hw = b * 128 + r;
        float w = g_wq[hw];
        const float* row = &g_cat[(size_t)hw * EE];
        a0 += w * row[t]; a1 += w * row[t + 256]; a2 += w * row[t + 512];
    }
    g_pt[b * EE + t] = a0; g_pt[b * EE + t + 256] = a1; g_pt[b * EE + t + 512] = a2;
}
__global__ void k_pool_fin()
{
    int c = threadIdx.x;
    float s = 0;
    for (int b = 0; b < 32; b++) s += g_pt[b * EE + c];
    g_t[c] = s;
}
__global__ void k_ln_sigmoid(const float* __restrict__ lng, const float* __restrict__ lnb)
{
    int c = threadIdx.x;
    __shared__ float buf[768];
    __shared__ float red[256];
    float v = g_wz[c];
    buf[c] = v; __syncthreads();
    if (c < 256) red[c] = buf[c] + buf[c + 256] + buf[c + 512];
    __syncthreads();
    for (int s = 128; s > 0; s >>= 1) { if (c < s) red[c] += red[c + s]; __syncthreads(); }
    float mu = red[0] * (1.f / 768.f); __syncthreads();
    float d = v - mu;
    buf[c] = d * d; __syncthreads();
    if (c < 256) red[c] = buf[c] + buf[c + 256] + buf[c + 512];
    __syncthreads();
    for (int s = 128; s > 0; s >>= 1) { if (c < s) red[c] += red[c + s]; __syncthreads(); }
    float var = red[0] * (1.f / 768.f);
    float z = d * rsqrtf(var + 1e-5f) * lng[c] + lnb[c];
    g_s[c] = 1.f / (1.f + expf(-z));
}
__global__ void k_x2()
{
    int idx = (blockIdx.x * 256 + threadIdx.x) * 4;
    int m = idx / EE, c = idx % EE;
    float4 v = *(const float4*)&g_cat[idx];
    float4 s = *(const float4*)&g_s[c];
    float r[4] = {v.x * s.x, v.y * s.y, v.z * s.z, v.w * s.w};
    *(float4*)&g_x2[idx] = *(float4*)r;
    __nv_bfloat16 hi[4], lo[4];
#pragma unroll
    for (int t = 0; t < 4; t++) {
        hi[t] = __float2bfloat16(r[t]);
        lo[t] = __float2bfloat16(r[t] - __bfloat162float(hi[t]));
    }
    *(uint2*)&g_x2s[(size_t)m * KSPLIT + c] = *(uint2*)hi;
    *(uint2*)&g_x2s[(size_t)m * KSPLIT + 768 + c] = *(uint2*)lo;
}
__global__ void k_colmax()
{
    int rr = blockIdx.x, t = threadIdx.x;
    float m = -1e30f;
    for (int i = t; i < 4096; i += 256) m = fmaxf(m, g_q2[(size_t)i * 384 + rr]);
    __shared__ float red[256];
    red[t] = m; __syncthreads();
    for (int s = 128; s > 0; s >>= 1) { if (t < s) red[t] = fmaxf(red[t], red[t + s]); __syncthreads(); }
    if (t == 0) g_mx[rr] = red[0];
}
__global__ void k_softmax384()
{
    int t = threadIdx.x;
    __shared__ float b[384];
    __shared__ float mx, sm;
    b[t] = g_mx[t]; __syncthreads();
    if (t == 0) { float m = b[0]; for (int i = 1; i < 384; i++) m = fmaxf(m, b[i]); mx = m; }
    __syncthreads();
    float e = expf(b[t] - mx);
    b[t] = e; __syncthreads();
    if (t == 0) { float s = 0; for (int i = 0; i < 384; i++) s += b[i]; sm = s; }
    __syncthreads();
    g_wq2[t] = e / sm;
}
__global__ void k_u(const float* __restrict__ spv)
{
    int c = threadIdx.x;
    float s = 0;
    for (int r = 0; r < 384; r++) s += g_wq2[r] * spv[r * EE + c];
    g_u[c] = s;
}
__global__ void k_final(const float* __restrict__ x5, const float* __restrict__ ng,
                        const float* __restrict__ nb, float* __restrict__ out)
{
    int hw = blockIdx.x, t = threadIdx.x;
    __shared__ float v[768];
    __shared__ float red[256];
    const float* x2r = g_x2 + (size_t)hw * EE;
    const float* catr = g_cat + (size_t)hw * EE;
    const float* x5r = x5 + (size_t)hw * EE;
    float d = 0;
    for (int c = t; c < 768; c += 256) d += g_u[c] * x2r[c];
    red[t] = d; __syncthreads();
    for (int s = 128; s > 0; s >>= 1) { if (t < s) red[t] += red[t + s]; __syncthreads(); }
    float wz2 = 1.f / (1.f + expf(-red[0])); __syncthreads();
    float ls = 0;
    for (int c = t; c < 768; c += 256) { float val = wz2 * x2r[c] + catr[c] + x5r[c]; v[c] = val; ls += val; }
    red[t] = ls; __syncthreads();
    for (int s = 128; s > 0; s >>= 1) { if (t < s) red[t] += red[t + s]; __syncthreads(); }
    float mu = red[0] * (1.f / 768.f); __syncthreads();
    float lq = 0;
    for (int c = t; c < 768; c += 256) { float dd = v[c] - mu; lq += dd * dd; }
    red[t] = lq; __syncthreads();
    for (int s = 128; s > 0; s >>= 1) { if (t < s) red[t] += red[t + s]; __syncthreads(); }
    float rstd = rsqrtf(red[0] * (1.f / 768.f) + 1e-5f); __syncthreads();
    for (int c = t; c < 768; c += 256) out[(size_t)hw * EE + c] = (v[c] - mu) * rstd * ng[c] + nb[c];
}

extern "C" void kernel_launch(void* const* d_in, const int* in_sizes, int n_in,
                              void* d_out, int out_size)
{
    const float* x[5];
    for (int i = 0; i < 5; i++) x[i] = (const float*)d_in[i];
    const float* convw = (const float*)d_in[5];
    const float* convb = (const float*)d_in[6];
    const float* offw = (const float*)d_in[7];
    const float* offb = (const float*)d_in[8];
    const float* mskw = (const float*)d_in[9];
    const float* mskb = (const float*)d_in[10];
    const float* bng = (const float*)d_in[11];
    const float* bnb = (const float*)d_in[12];
    const float* chq = (const float*)d_in[13];
    const float* chv = (const float*)d_in[14];
    const float* chz = (const float*)d_in[15];
    const float* lng = (const float*)d_in[16];
    const float* lnb = (const float*)d_in[17];
    const float* spq = (const float*)d_in[18];
    const float* spv = (const float*)d_in[19];
    const float* wa[5] = {(const float*)d_in[20], (const float*)d_in[21], (const float*)d_in[22],
                          (const float*)d_in[24], (const float*)d_in[26]};
    const float* wb[5] = {nullptr, nullptr, (const float*)d_in[23],
                          (const float*)d_in[25], (const float*)d_in[27]};
    const float* normg = (const float*)d_in[28];
    const float* normb = (const float*)d_in[29];

    float *pOw, *pBoff, *pCat, *pX2, *pQ2, *pQ, *pT, *pR, *pWz;
    __nv_bfloat16 *pXs, *pActs, *pX2s, *pWp, *pWsp;
    cudaGetSymbolAddress((void**)&pOw, g_ow);
    cudaGetSymbolAddress((void**)&pBoff, g_boff);
    cudaGetSymbolAddress((void**)&pCat, g_cat);
    cudaGetSymbolAddress((void**)&pX2, g_x2);
    cudaGetSymbolAddress((void**)&pQ2, g_q2);
    cudaGetSymbolAddress((void**)&pQ, g_q);
    cudaGetSymbolAddress((void**)&pT, g_t);
    cudaGetSymbolAddress((void**)&pR, g_r);
    cudaGetSymbolAddress((void**)&pWz, g_wz);
    cudaGetSymbolAddress((void**)&pXs, g_xs);
    cudaGetSymbolAddress((void**)&pActs, g_acts);
    cudaGetSymbolAddress((void**)&pX2s, g_x2s);
    cudaGetSymbolAddress((void**)&pWp, g_Wp);
    cudaGetSymbolAddress((void**)&pWsp, g_Wsp);

    const int SMEM_MAIN = 3 * 32768;
    const int SMEM_PROJ = 2 * 32768;
    cudaFuncSetAttribute(k_mma_main, cudaFuncAttributeMaxDynamicSharedMemorySize, SMEM_MAIN);
    cudaFuncSetAttribute(k_mma_proj, cudaFuncAttributeMaxDynamicSharedMemorySize, SMEM_PROJ);

    // ---- prep ----
    k_prep_ow<<<(27 * EE + 255) / 256, 256>>>(offw, mskw);
    k_gemv<<<18, 128>>>(pOw, convb, offb, pBoff, 768);
    k_gemv<<<9, 128>>>(pOw + 18 * 768, convb, mskb, pBoff + 18, 768);
    k_fusedF_part<<<dim3(27, 32), 256>>>(convw);
    k_fusedF_red<<<27 * 6912 / 256, 256>>>();
    k_buildB_taps<<<768, 256>>>(convw);
    k_buildB_fused<<<((LDC - 6912) * EE + 255) / 256, 256>>>();
    int chN[5] = {30, 100, 150, 220, 268};
    int chOff[5] = {0, 30, 130, 280, 500};
    for (int b = 0; b < 5; b++) {
        k_buildWp<<<(384 * 768 + 255) / 256, 256>>>(wa[b], pWp + (size_t)b * 384 * KW, chN[b], 0);
        if (wb[b])
            k_buildWp<<<(384 * 768 + 255) / 256, 256>>>(wb[b], pWp + (size_t)b * 384 * KW, chN[b], 1);
    }
    k_buildWp<<<(384 * 768 + 255) / 256, 256>>>(spq, pWsp, 384, 0);

    // ---- 5 blocks ----
    for (int b = 0; b < 5; b++) {
        k_splitA<<<(HW * EE + 255) / 256, 256>>>(x[b]);
        k_mma_main<<<dim3(56, 32), 256, SMEM_MAIN>>>();
        k_offmask<<<HW, 32>>>();
        k_deform_gather<<<HW, 192>>>(convb);
        k_bn_partial<<<32, 256>>>();
        k_bn_final<<<1, 768>>>(bng, bnb);
        k_bn_relu<<<HW * EE / 1024, 256>>>();
        int nt = (chN[b] + 127) / 128;
        k_mma_proj<<<dim3(nt, 32), 256, SMEM_PROJ>>>(
            pActs, pXs, pWp + (size_t)b * 384 * KW, pCat, 768, chOff[b], chN[b],
            wb[b] ? 72 : 36);
    }

    // ---- CAM ----
    k_gemv<<<HW, 128>>>(pCat, chq, nullptr, pQ, 768);
    k_softmax_hw<<<1, 1024>>>();
    k_poolw<<<32, 256>>>();
    k_pool_fin<<<1, 768>>>();
    k_gemv<<<384, 128>>>(chv, pT, nullptr, pR, 768);
    k_gemv<<<768, 128>>>(chz, pR, nullptr, pWz, 384);
    k_ln_sigmoid<<<1, 768>>>(lng, lnb);
    k_x2<<<HW * EE / 1024, 256>>>();
    k_mma_proj<<<dim3(3, 32), 256, SMEM_PROJ>>>(pX2s, nullptr, pWsp, pQ2, 384, 0, 384, 36);
    k_colmax<<<384, 256>>>();
    k_softmax384<<<1, 384>>>();
    k_u<<<1, 768>>>(spv);
    k_final<<<HW, 256>>>(x[4], normg, normb, (float*)d_out);
}

// round 16
// speedup vs baseline: 5.7592x; 1.1993x over previous
#include <cuda_runtime.h>
#include <cuda_bf16.h>
#include <cuda_fp16.h>
#include <math.h>
#include <stdint.h>

#define HW 4096
#define EE 768
#define NCOL 7155
#define LDC 7168
#define KW2 1536      // proj weight row: [src0(768) | src1(768)] fp16

static __device__ __half g_Ch[(size_t)HW * LDC];                // main GEMM output fp16
static __device__ __half g_Ah[(size_t)HW * EE];                 // x fp16 (main + proj A1)
static __device__ __half g_Bh[(size_t)LDC * EE];                // B fp16 (main)
static __device__ __half g_acts[(size_t)HW * EE];               // act fp16 (proj A0)
static __device__ __half g_x2s[(size_t)HW * EE];                // x2 fp16 (proj)
static __device__ __half g_Wp[5 * 384 * KW2];                   // proj weights fp16
static __device__ __half g_Wsp[384 * KW2];                      // spq weights fp16
static __device__ float g_F[27 * 6912];
static __device__ float g_Fp[32 * 27 * 6912];
static __device__ float g_ow[27 * EE];
static __device__ float g_boff[27];
static __device__ float g_off[HW * 18];
static __device__ float g_mask[HW * 9];
static __device__ float g_blk[(size_t)HW * EE];
static __device__ float g_cat[(size_t)HW * EE];
static __device__ float g_x2[(size_t)HW * EE];
static __device__ float g_q2[(size_t)HW * 384];
static __device__ float g_ps[32 * EE], g_pq[32 * EE], g_sc[EE], g_sh[EE];
static __device__ float g_q[HW], g_wq[HW];
static __device__ float g_pt[32 * EE], g_t[EE], g_r[384], g_wz[EE], g_s[EE];
static __device__ float g_mx[384], g_wq2[384], g_u[EE];

// ================= helpers =================
__device__ __forceinline__ uint32_t smem_u32(const void* p) {
    uint32_t a;
    asm("{ .reg .u64 t; cvta.to.shared.u64 t, %1; cvt.u32.u64 %0, t; }" : "=r"(a) : "l"(p));
    return a;
}
__device__ __forceinline__ void cp16(uint32_t dst, const void* src) {
    asm volatile("cp.async.cg.shared.global [%0], [%1], 16;" :: "r"(dst), "l"(src) : "memory");
}
template <int N> __device__ __forceinline__ void cp_wait() {
    asm volatile("cp.async.wait_group %0;" :: "n"(N) : "memory");
}
__device__ __forceinline__ void ldm_x4(uint32_t& r0, uint32_t& r1, uint32_t& r2, uint32_t& r3,
                                       uint32_t addr) {
    asm volatile("ldmatrix.sync.aligned.m8n8.x4.shared.b16 {%0,%1,%2,%3}, [%4];"
                 : "=r"(r0), "=r"(r1), "=r"(r2), "=r"(r3) : "r"(addr));
}
__device__ __forceinline__ void mma_f16(float& d0, float& d1, float& d2, float& d3,
                                        uint32_t a0, uint32_t a1, uint32_t a2, uint32_t a3,
                                        uint32_t b0, uint32_t b1) {
    asm volatile(
        "mma.sync.aligned.m16n8k16.row.col.f32.f16.f16.f32 "
        "{%0,%1,%2,%3}, {%4,%5,%6,%7}, {%8,%9}, {%0,%1,%2,%3};"
        : "+f"(d0), "+f"(d1), "+f"(d2), "+f"(d3)
        : "r"(a0), "r"(a1), "r"(a2), "r"(a3), "r"(b0), "r"(b1));
}
#define SWZ128(x) ((x) ^ (((x) >> 3) & 0x70))

// main plain fp16: 12 chunks of K=64
__device__ __forceinline__ void load_chunk_main(uint32_t sbase, int s, int chunk,
                                                int row0, int col0, int tid) {
    int k0 = chunk * 64;
    int r = tid & 127;
    bool isB = tid >= 128;
    const __half* g = isB ? &g_Bh[(size_t)(col0 + r) * EE + k0]
                          : &g_Ah[(size_t)(row0 + r) * EE + k0];
    uint32_t base = sbase + s * 32768 + (isB ? 16384 : 0);
    int rb = r * 128;
#pragma unroll
    for (int seg = 0; seg < 8; seg++)
        cp16(base + SWZ128(rb + seg * 16), g + seg * 8);
    asm volatile("cp.async.commit_group;" ::: "memory");
}

// ========== main GEMM: C_h[4096 x 7168] = a_f16 @ b_f16^T; 3-stage; fp16 out ==========
__global__ __launch_bounds__(256, 2)
void k_mma_main()
{
    extern __shared__ char smem_raw[];
    uint32_t sbase = smem_u32(smem_raw);
    int tid = threadIdx.x, wid = tid >> 5, lane = tid & 31;
    int row0 = blockIdx.y * 128, col0 = blockIdx.x * 128;
    int wm = (wid & 1) * 64, wn = (wid >> 1) * 32;

    float acc[4][4][4];
#pragma unroll
    for (int i = 0; i < 4; i++)
#pragma unroll
        for (int j = 0; j < 4; j++)
#pragma unroll
            for (int k = 0; k < 4; k++) acc[i][j][k] = 0.f;

    load_chunk_main(sbase, 0, 0, row0, col0, tid);
    load_chunk_main(sbase, 1, 1, row0, col0, tid);
    load_chunk_main(sbase, 2, 2, row0, col0, tid);

    for (int it = 0; it < 12; it++) {
        int s = it % 3;
        if (it < 10) cp_wait<2>(); else if (it == 10) cp_wait<1>(); else cp_wait<0>();
        __syncthreads();
        uint32_t abase = sbase + s * 32768;
        uint32_t bbase = abase + 16384;
#pragma unroll
        for (int k16 = 0; k16 < 4; k16++) {
            uint32_t b[4][2];
#pragma unroll
            for (int nb2 = 0; nb2 < 2; nb2++) {
                int n_row = wn + nb2 * 16 + (lane & 7) + ((lane >> 4) << 3);
                int k_byte = k16 * 32 + ((lane >> 3) & 1) * 16;
                uint32_t addr = bbase + SWZ128(n_row * 128 + k_byte);
                ldm_x4(b[nb2 * 2][0], b[nb2 * 2][1], b[nb2 * 2 + 1][0], b[nb2 * 2 + 1][1], addr);
            }
#pragma unroll
            for (int mf = 0; mf < 4; mf++) {
                int m_row = wm + mf * 16 + (lane & 15);
                int k_byte = k16 * 32 + (lane >> 4) * 16;
                uint32_t addr = abase + SWZ128(m_row * 128 + k_byte);
                uint32_t a0, a1, a2, a3;
                ldm_x4(a0, a1, a2, a3, addr);
#pragma unroll
                for (int nf = 0; nf < 4; nf++)
                    mma_f16(acc[mf][nf][0], acc[mf][nf][1], acc[mf][nf][2], acc[mf][nf][3],
                            a0, a1, a2, a3, b[nf][0], b[nf][1]);
            }
        }
        __syncthreads();
        if (it + 3 < 12) load_chunk_main(sbase, s, it + 3, row0, col0, tid);
    }

    int rr = lane >> 2, cc = (lane & 3) * 2;
#pragma unroll
    for (int mf = 0; mf < 4; mf++) {
#pragma unroll
        for (int nf = 0; nf < 4; nf++) {
            int r = row0 + wm + mf * 16 + rr;
            int c = col0 + wn + nf * 8 + cc;
            *(__half2*)&g_Ch[(size_t)r * LDC + c] =
                __floats2half2_rn(acc[mf][nf][0], acc[mf][nf][1]);
            *(__half2*)&g_Ch[(size_t)(r + 8) * LDC + c] =
                __floats2half2_rn(acc[mf][nf][2], acc[mf][nf][3]);
        }
    }
}

// ========== proj GEMM (fp16): C[:,colOff:+N] = [A0|A1] @ W^T ; 2-stage ==========
// chunks 0..11 = src0 (A0, W[...,0:768]); chunks 12..23 = src1 (A1, W[...,768:1536])
__global__ __launch_bounds__(256, 2)
void k_mma_proj(const __half* __restrict__ A0, const __half* __restrict__ A1,
                const __half* __restrict__ W, float* __restrict__ C,
                int ldc, int colOff, int N, int nch)
{
    extern __shared__ char smem_raw[];
    uint32_t sbase = smem_u32(smem_raw);
    int tid = threadIdx.x, wid = tid >> 5, lane = tid & 31;
    int row0 = blockIdx.y * 128, col0 = blockIdx.x * 128;
    int wm = (wid & 1) * 64, wn = (wid >> 1) * 32;

    float acc[4][4][4];
#pragma unroll
    for (int i = 0; i < 4; i++)
#pragma unroll
        for (int j = 0; j < 4; j++)
#pragma unroll
            for (int k = 0; k < 4; k++) acc[i][j][k] = 0.f;

    auto load = [&](int s, int chunk) {
        int src = (chunk >= 12) ? 1 : 0;
        int k0 = (chunk - src * 12) * 64;
        int r = tid & 127;
        const __half* g;
        uint32_t base;
        if (tid < 128) {
            g = (src ? A1 : A0) + (size_t)(row0 + r) * EE + k0;
            base = sbase + s * 32768;
        } else {
            g = W + (size_t)(col0 + r) * KW2 + src * 768 + k0;
            base = sbase + s * 32768 + 16384;
        }
        int rb = r * 128;
#pragma unroll
        for (int seg = 0; seg < 8; seg++)
            cp16(base + SWZ128(rb + seg * 16), g + seg * 8);
        asm volatile("cp.async.commit_group;" ::: "memory");
    };

    load(0, 0);
    load(1, 1);

    for (int it = 0; it < nch; it++) {
        int s = it & 1;
        if (it < nch - 1) cp_wait<1>(); else cp_wait<0>();
        __syncthreads();
        uint32_t abase = sbase + s * 32768;
        uint32_t bbase = abase + 16384;
#pragma unroll
        for (int k16 = 0; k16 < 4; k16++) {
            uint32_t b[4][2];
#pragma unroll
            for (int nb2 = 0; nb2 < 2; nb2++) {
                int n_row = wn + nb2 * 16 + (lane & 7) + ((lane >> 4) << 3);
                int k_byte = k16 * 32 + ((lane >> 3) & 1) * 16;
                uint32_t addr = bbase + SWZ128(n_row * 128 + k_byte);
                ldm_x4(b[nb2 * 2][0], b[nb2 * 2][1], b[nb2 * 2 + 1][0], b[nb2 * 2 + 1][1], addr);
            }
#pragma unroll
            for (int mf = 0; mf < 4; mf++) {
                int m_row = wm + mf * 16 + (lane & 15);
                int k_byte = k16 * 32 + (lane >> 4) * 16;
                uint32_t addr = abase + SWZ128(m_row * 128 + k_byte);
                uint32_t a0, a1, a2, a3;
                ldm_x4(a0, a1, a2, a3, addr);
#pragma unroll
                for (int nf = 0; nf < 4; nf++)
                    mma_f16(acc[mf][nf][0], acc[mf][nf][1], acc[mf][nf][2], acc[mf][nf][3],
                            a0, a1, a2, a3, b[nf][0], b[nf][1]);
            }
        }
        __syncthreads();
        if (it + 2 < nch) load(s, it + 2);
    }

    int rr = lane >> 2, cc = (lane & 3) * 2;
#pragma unroll
    for (int mf = 0; mf < 4; mf++) {
#pragma unroll
        for (int nf = 0; nf < 4; nf++) {
            int c = col0 + wn + nf * 8 + cc;
            if (c < N) {
                int r = row0 + wm + mf * 16 + rr;
                *(float2*)&C[(size_t)r * ldc + colOff + c] =
                    make_float2(acc[mf][nf][0], acc[mf][nf][1]);
                *(float2*)&C[(size_t)(r + 8) * ldc + colOff + c] =
                    make_float2(acc[mf][nf][2], acc[mf][nf][3]);
            }
        }
    }
}

// ---------- split / weight builders ----------
__global__ void k_splitA(const float* __restrict__ x)
{
    int idx = blockIdx.x * 256 + threadIdx.x;
    if (idx < HW * EE) g_Ah[idx] = __float2half(x[idx]);
}
__global__ void k_fusedF_part(const float* __restrict__ convw)
{
    __shared__ float sow[27 * 24];
    int r = blockIdx.x * 256 + threadIdx.x;
    int os = blockIdx.y * 24;
    for (int i = threadIdx.x; i < 27 * 24; i += 256)
        sow[i] = g_ow[(i / 24) * 768 + os + (i % 24)];
    __syncthreads();
    float acc[27];
#pragma unroll
    for (int j = 0; j < 27; j++) acc[j] = 0.f;
    for (int oo = 0; oo < 24; oo++) {
        float cv = convw[(size_t)(os + oo) * 6912 + r];
#pragma unroll
        for (int j = 0; j < 27; j++) acc[j] = fmaf(sow[j * 24 + oo], cv, acc[j]);
    }
#pragma unroll
    for (int j = 0; j < 27; j++)
        g_Fp[(size_t)blockIdx.y * (27 * 6912) + j * 6912 + r] = acc[j];
}
__global__ void k_fusedF_red()
{
    int i = blockIdx.x * 256 + threadIdx.x;
    float s = 0.f;
#pragma unroll
    for (int p = 0; p < 32; p++) s += g_Fp[(size_t)p * (27 * 6912) + i];
    g_F[i] = s;
}
__global__ void k_buildB_taps(const float* __restrict__ convw)
{
    __shared__ float s[6912];
    int o = blockIdx.x, t = threadIdx.x;
    const float* src = convw + (size_t)o * 6912;
    for (int i = t; i < 6912; i += 256) s[i] = src[i];
    __syncthreads();
#pragma unroll
    for (int kk = 0; kk < 9; kk++) {
        size_t base = (size_t)(kk * 768 + o) * EE;
        for (int c = t; c < 768; c += 256)
            g_Bh[base + c] = __float2half(s[c * 9 + kk]);
    }
}
__global__ void k_buildB_fused()
{
    int idx = blockIdx.x * 256 + threadIdx.x;
    if (idx >= (LDC - 6912) * EE) return;
    int nr = idx / EE, c = idx % EE;
    int n = 6912 + nr;
    float v = 0.f;
    if (n < NCOL) {
        int j = nr / 9, kk = nr % 9;
        v = g_F[j * 6912 + c * 9 + kk];
    }
    g_Bh[(size_t)n * EE + c] = __float2half(v);
}
__global__ void k_buildWp(const float* __restrict__ w, __half* __restrict__ dst,
                          int chN, int srcslot)
{
    int idx = blockIdx.x * 256 + threadIdx.x;
    if (idx >= 384 * 768) return;
    int n = idx / 768, c = idx % 768;
    float v = (n < chN) ? w[n * 768 + c] : 0.f;
    dst[(size_t)n * KW2 + srcslot * 768 + c] = __float2half(v);
}

__global__ void k_gemv(const float* __restrict__ W, const float* __restrict__ x,
                       const float* __restrict__ bias, float* __restrict__ y, int K)
{
    int m = blockIdx.x, t = threadIdx.x;
    float a = 0.f;
    for (int k = t; k < K; k += 128) a += W[(size_t)m * K + k] * x[k];
    __shared__ float red[128];
    red[t] = a; __syncthreads();
    for (int s = 64; s > 0; s >>= 1) { if (t < s) red[t] += red[t + s]; __syncthreads(); }
    if (t == 0) y[m] = red[0] + (bias ? bias[m] : 0.f);
}
__global__ void k_prep_ow(const float* __restrict__ offw, const float* __restrict__ mskw)
{
    int i = blockIdx.x * 256 + threadIdx.x;
    if (i < 27 * EE) { int j = i / EE, c = i % EE; g_ow[i] = (j < 18) ? offw[j * EE + c] : mskw[(j - 18) * EE + c]; }
}

__global__ void k_offmask()
{
    int hw = blockIdx.x, y = hw >> 6, x = hw & 63;
    int j = threadIdx.x;
    __shared__ float lg[9];
    __shared__ float mx_s, sum_s;
    if (j < 27) {
        float v = g_boff[j];
#pragma unroll
        for (int k = 0; k < 9; k++) {
            int yy = y + k / 3 - 1, xx = x + k % 3 - 1;
            if (yy >= 0 && yy < 64 && xx >= 0 && xx < 64)
                v += __half2float(g_Ch[(size_t)(yy * 64 + xx) * LDC + 6912 + j * 9 + k]);
        }
        if (j < 18) g_off[hw * 18 + j] = v; else lg[j - 18] = v;
    }
    __syncthreads();
    if (j == 0) {
        float mx = lg[0];
        for (int t = 1; t < 9; t++) mx = fmaxf(mx, lg[t]);
        float s = 0.f;
        for (int t = 0; t < 9; t++) s += expf(lg[t] - mx);
        mx_s = mx; sum_s = s;
    }
    __syncthreads();
    if (j < 9) g_mask[hw * 9 + j] = expf(lg[j] - mx_s) / sum_s;
}

__global__ __launch_bounds__(192)
void k_deform_gather(const float* __restrict__ convb)
{
    int hw = blockIdx.x, y = hw >> 6, x = hw & 63;
    __shared__ int sidx[9][4];
    __shared__ float swgt[9][4];
    int tid = threadIdx.x;
    if (tid < 9) {
        int k = tid;
        float dy = g_off[hw * 18 + 2 * k], dx = g_off[hw * 18 + 2 * k + 1];
        float m = g_mask[k * HW + hw];  // raw-reshape mask indexing
        float py = (float)(y + k / 3 - 1) + dy;
        float px = (float)(x + k % 3 - 1) + dx;
        float y0f = floorf(py), x0f = floorf(px);
        float wy1 = py - y0f, wx1 = px - x0f;
        int y0 = (int)y0f, x0 = (int)x0f;
#pragma unroll
        for (int c = 0; c < 4; c++) {
            int yy = y0 + (c >> 1), xx = x0 + (c & 1);
            bool valid = (yy >= 0 && yy <= 63 && xx >= 0 && xx <= 63);
            int yc = min(max(yy, 0), 63), xc = min(max(xx, 0), 63);
            float w = ((c >> 1) ? wy1 : 1.f - wy1) * ((c & 1) ? wx1 : 1.f - wx1);
            sidx[k][c] = yc * 64 + xc;
            swgt[k][c] = valid ? w * m : 0.f;
        }
    }
    __syncthreads();
    int o = tid * 4;
    float4 acc = *(const float4*)(convb + o);
#pragma unroll
    for (int k = 0; k < 9; k++) {
        size_t cb = (size_t)k * EE + o;
#pragma unroll
        for (int c = 0; c < 4; c++) {
            float w = swgt[k][c];
            uint2 raw = *(const uint2*)&g_Ch[(size_t)sidx[k][c] * LDC + cb];
            float2 v01 = __half22float2(*(const __half2*)&raw.x);
            float2 v23 = __half22float2(*(const __half2*)&raw.y);
            acc.x = fmaf(w, v01.x, acc.x); acc.y = fmaf(w, v01.y, acc.y);
            acc.z = fmaf(w, v23.x, acc.z); acc.w = fmaf(w, v23.y, acc.w);
        }
    }
    *(float4*)(&g_blk[(size_t)hw * EE + o]) = acc;
}

__global__ void k_bn_partial()
{
    int b = blockIdx.x, t = threadIdx.x;
    float s0 = 0, s1 = 0, s2 = 0, q0 = 0, q1 = 0, q2v = 0;
    for (int r = 0; r < 128; r++) {
        const float* row = &g_blk[(size_t)(b * 128 + r) * EE];
        float v0 = row[t], v1 = row[t + 256], v2 = row[t + 512];
        s0 += v0; s1 += v1; s2 += v2; q0 += v0 * v0; q1 += v1 * v1; q2v += v2 * v2;
    }
    g_ps[b * EE + t] = s0; g_ps[b * EE + t + 256] = s1; g_ps[b * EE + t + 512] = s2;
    g_pq[b * EE + t] = q0; g_pq[b * EE + t + 256] = q1; g_pq[b * EE + t + 512] = q2v;
}
__global__ void k_bn_final(const float* __restrict__ bng, const float* __restrict__ bnb)
{
    int c = threadIdx.x;
    float s = 0, q = 0;
    for (int b = 0; b < 32; b++) { s += g_ps[b * EE + c]; q += g_pq[b * EE + c]; }
    float mu = s * (1.f / 4096.f);
    float var = q * (1.f / 4096.f) - mu * mu;
    float sc = rsqrtf(var + 1e-5f) * bng[c];
    g_sc[c] = sc; g_sh[c] = bnb[c] - mu * sc;
}
// BN + relu, emits fp16 act
__global__ void k_bn_relu()
{
    int idx = (blockIdx.x * 256 + threadIdx.x) * 4;
    int c = idx % EE;
    float4 v = *(const float4*)&g_blk[idx];
    float4 sc = *(const float4*)&g_sc[c];
    float4 sh = *(const float4*)&g_sh[c];
    float r0 = fmaxf(0.f, fmaf(v.x, sc.x, sh.x));
    float r1 = fmaxf(0.f, fmaf(v.y, sc.y, sh.y));
    float r2 = fmaxf(0.f, fmaf(v.z, sc.z, sh.z));
    float r3 = fmaxf(0.f, fmaf(v.w, sc.w, sh.w));
    __half2 h01 = __floats2half2_rn(r0, r1);
    __half2 h23 = __floats2half2_rn(r2, r3);
    uint2 packed = make_uint2(*(uint32_t*)&h01, *(uint32_t*)&h23);
    *(uint2*)&g_acts[idx] = packed;
}

__global__ void k_softmax_hw()
{
    __shared__ float sm[4096];
    __shared__ float red[1024];
    int t = threadIdx.x;
    float lm = -1e30f;
    for (int i = t; i < 4096; i += 1024) { float v = g_q[i]; sm[i] = v; lm = fmaxf(lm, v); }
    red[t] = lm; __syncthreads();
    for (int s = 512; s > 0; s >>= 1) { if (t < s) red[t] = fmaxf(red[t], red[t + s]); __syncthreads(); }
    float mx = red[0]; __syncthreads();
    float ls = 0.f;
    for (int i = t; i < 4096; i += 1024) { float e = expf(sm[i] - mx); sm[i] = e; ls += e; }
    red[t] = ls; __syncthreads();
    for (int s = 512; s > 0; s >>= 1) { if (t < s) red[t] += red[t + s]; __syncthreads(); }
    float inv = 1.f / red[0]; __syncthreads();
    for (int i = t; i < 4096; i += 1024) g_wq[i] = sm[i] * inv;
}
__global__ void k_poolw()
{
    int b = blockIdx.x, t = threadIdx.x;
    float a0 = 0, a1 = 0, a2 = 0;
    for (int r = 0; r < 128; r++) {
        int hw = b * 128 + r;
        float w = g_wq[hw];
        const float* row = &g_cat[(size_t)hw * EE];
        a0 += w * row[t]; a1 += w * row[t + 256]; a2 += w * row[t + 512];
    }
    g_pt[b * EE + t] = a0; g_pt[b * EE + t + 256] = a1; g_pt[b * EE + t + 512] = a2;
}
__global__ void k_pool_fin()
{
    int c = threadIdx.x;
    float s = 0;
    for (int b = 0; b < 32; b++) s += g_pt[b * EE + c];
    g_t[c] = s;
}
__global__ void k_ln_sigmoid(const float* __restrict__ lng, const float* __restrict__ lnb)
{
    int c = threadIdx.x;
    __shared__ float buf[768];
    __shared__ float red[256];
    float v = g_wz[c];
    buf[c] = v; __syncthreads();
    if (c < 256) red[c] = buf[c] + buf[c + 256] + buf[c + 512];
    __syncthreads();
    for (int s = 128; s > 0; s >>= 1) { if (c < s) red[c] += red[c + s]; __syncthreads(); }
    float mu = red[0] * (1.f / 768.f); __syncthreads();
    float d = v - mu;
    buf[c] = d * d; __syncthreads();
    if (c < 256) red[c] = buf[c] + buf[c + 256] + buf[c + 512];
    __syncthreads();
    for (int s = 128; s > 0; s >>= 1) { if (c < s) red[c] += red[c + s]; __syncthreads(); }
    float var = red[0] * (1.f / 768.f);
    float z = d * rsqrtf(var + 1e-5f) * lng[c] + lnb[c];
    g_s[c] = 1.f / (1.f + expf(-z));
}
// x2 = sigmoid(wz)*cat; emits fp32 + fp16
__global__ void k_x2()
{
    int idx = (blockIdx.x * 256 + threadIdx.x) * 4;
    int c = idx % EE;
    float4 v = *(const float4*)&g_cat[idx];
    float4 s = *(const float4*)&g_s[c];
    float r0 = v.x * s.x, r1 = v.y * s.y, r2 = v.z * s.z, r3 = v.w * s.w;
    *(float4*)&g_x2[idx] = make_float4(r0, r1, r2, r3);
    __half2 h01 = __floats2half2_rn(r0, r1);
    __half2 h23 = __floats2half2_rn(r2, r3);
    *(uint2*)&g_x2s[idx] = make_uint2(*(uint32_t*)&h01, *(uint32_t*)&h23);
}
__global__ void k_colmax()
{
    int rr = blockIdx.x, t = threadIdx.x;
    float m = -1e30f;
    for (int i = t; i < 4096; i += 256) m = fmaxf(m, g_q2[(size_t)i * 384 + rr]);
    __shared__ float red[256];
    red[t] = m; __syncthreads();
    for (int s = 128; s > 0; s >>= 1) { if (t < s) red[t] = fmaxf(red[t], red[t + s]); __syncthreads(); }
    if (t == 0) g_mx[rr] = red[0];
}
__global__ void k_softmax384()
{
    int t = threadIdx.x;
    __shared__ float b[384];
    __shared__ float mx, sm;
    b[t] = g_mx[t]; __syncthreads();
    if (t == 0) { float m = b[0]; for (int i = 1; i < 384; i++) m = fmaxf(m, b[i]); mx = m; }
    __syncthreads();
    float e = expf(b[t] - mx);
    b[t] = e; __syncthreads();
    if (t == 0) { float s = 0; for (int i = 0; i < 384; i++) s += b[i]; sm = s; }
    __syncthreads();
    g_wq2[t] = e / sm;
}
__global__ void k_u(const float* __restrict__ spv)
{
    int c = threadIdx.x;
    float s = 0;
    for (int r = 0; r < 384; r++) s += g_wq2[r] * spv[r * EE + c];
    g_u[c] = s;
}
__global__ void k_final(const float* __restrict__ x5, const float* __restrict__ ng,
                        const float* __restrict__ nb, float* __restrict__ out)
{
    int hw = blockIdx.x, t = threadIdx.x;
    __shared__ float v[768];
    __shared__ float red[256];
    const float* x2r = g_x2 + (size_t)hw * EE;
    const float* catr = g_cat + (size_t)hw * EE;
    const float* x5r = x5 + (size_t)hw * EE;
    float d = 0;
    for (int c = t; c < 768; c += 256) d += g_u[c] * x2r[c];
    red[t] = d; __syncthreads();
    for (int s = 128; s > 0; s >>= 1) { if (t < s) red[t] += red[t + s]; __syncthreads(); }
    float wz2 = 1.f / (1.f + expf(-red[0])); __syncthreads();
    float ls = 0;
    for (int c = t; c < 768; c += 256) { float val = wz2 * x2r[c] + catr[c] + x5r[c]; v[c] = val; ls += val; }
    red[t] = ls; __syncthreads();
    for (int s = 128; s > 0; s >>= 1) { if (t < s) red[t] += red[t + s]; __syncthreads(); }
    float mu = red[0] * (1.f / 768.f); __syncthreads();
    float lq = 0;
    for (int c = t; c < 768; c += 256) { float dd = v[c] - mu; lq += dd * dd; }
    red[t] = lq; __syncthreads();
    for (int s = 128; s > 0; s >>= 1) { if (t < s) red[t] += red[t + s]; __syncthreads(); }
    float rstd = rsqrtf(red[0] * (1.f / 768.f) + 1e-5f); __syncthreads();
    for (int c = t; c < 768; c += 256) out[(size_t)hw * EE + c] = (v[c] - mu) * rstd * ng[c] + nb[c];
}

extern "C" void kernel_launch(void* const* d_in, const int* in_sizes, int n_in,
                              void* d_out, int out_size)
{
    const float* x[5];
    for (int i = 0; i < 5; i++) x[i] = (const float*)d_in[i];
    const float* convw = (const float*)d_in[5];
    const float* convb = (const float*)d_in[6];
    const float* offw = (const float*)d_in[7];
    const float* offb = (const float*)d_in[8];
    const float* mskw = (const float*)d_in[9];
    const float* mskb = (const float*)d_in[10];
    const float* bng = (const float*)d_in[11];
    const float* bnb = (const float*)d_in[12];
    const float* chq = (const float*)d_in[13];
    const float* chv = (const float*)d_in[14];
    const float* chz = (const float*)d_in[15];
    const float* lng = (const float*)d_in[16];
    const float* lnb = (const float*)d_in[17];
    const float* spq = (const float*)d_in[18];
    const float* spv = (const float*)d_in[19];
    const float* wa[5] = {(const float*)d_in[20], (const float*)d_in[21], (const float*)d_in[22],
                          (const float*)d_in[24], (const float*)d_in[26]};
    const float* wb[5] = {nullptr, nullptr, (const float*)d_in[23],
                          (const float*)d_in[25], (const float*)d_in[27]};
    const float* normg = (const float*)d_in[28];
    const float* normb = (const float*)d_in[29];

    float *pOw, *pBoff, *pCat, *pX2, *pQ2, *pQ, *pT, *pR, *pWz;
    __half *pAh, *pActs, *pX2s, *pWp, *pWsp;
    cudaGetSymbolAddress((void**)&pOw, g_ow);
    cudaGetSymbolAddress((void**)&pBoff, g_boff);
    cudaGetSymbolAddress((void**)&pCat, g_cat);
    cudaGetSymbolAddress((void**)&pX2, g_x2);
    cudaGetSymbolAddress((void**)&pQ2, g_q2);
    cudaGetSymbolAddress((void**)&pQ, g_q);
    cudaGetSymbolAddress((void**)&pT, g_t);
    cudaGetSymbolAddress((void**)&pR, g_r);
    cudaGetSymbolAddress((void**)&pWz, g_wz);
    cudaGetSymbolAddress((void**)&pAh, g_Ah);
    cudaGetSymbolAddress((void**)&pActs, g_acts);
    cudaGetSymbolAddress((void**)&pX2s, g_x2s);
    cudaGetSymbolAddress((void**)&pWp, g_Wp);
    cudaGetSymbolAddress((void**)&pWsp, g_Wsp);

    const int SMEM_MAIN = 3 * 32768;
    const int SMEM_PROJ = 2 * 32768;
    cudaFuncSetAttribute(k_mma_main, cudaFuncAttributeMaxDynamicSharedMemorySize, SMEM_MAIN);
    cudaFuncSetAttribute(k_mma_proj, cudaFuncAttributeMaxDynamicSharedMemorySize, SMEM_PROJ);

    // ---- prep ----
    k_prep_ow<<<(27 * EE + 255) / 256, 256>>>(offw, mskw);
    k_gemv<<<18, 128>>>(pOw, convb, offb, pBoff, 768);
    k_gemv<<<9, 128>>>(pOw + 18 * 768, convb, mskb, pBoff + 18, 768);
    k_fusedF_part<<<dim3(27, 32), 256>>>(convw);
    k_fusedF_red<<<27 * 6912 / 256, 256>>>();
    k_buildB_taps<<<768, 256>>>(convw);
    k_buildB_fused<<<((LDC - 6912) * EE + 255) / 256, 256>>>();
    int chN[5] = {30, 100, 150, 220, 268};
    int chOff[5] = {0, 30, 130, 280, 500};
    for (int b = 0; b < 5; b++) {
        k_buildWp<<<(384 * 768 + 255) / 256, 256>>>(wa[b], pWp + (size_t)b * 384 * KW2, chN[b], 0);
        if (wb[b])
            k_buildWp<<<(384 * 768 + 255) / 256, 256>>>(wb[b], pWp + (size_t)b * 384 * KW2, chN[b], 1);
    }
    k_buildWp<<<(384 * 768 + 255) / 256, 256>>>(spq, pWsp, 384, 0);

    // ---- 5 blocks ----
    for (int b = 0; b < 5; b++) {
        k_splitA<<<(HW * EE + 255) / 256, 256>>>(x[b]);
        k_mma_main<<<dim3(56, 32), 256, SMEM_MAIN>>>();
        k_offmask<<<HW, 32>>>();
        k_deform_gather<<<HW, 192>>>(convb);
        k_bn_partial<<<32, 256>>>();
        k_bn_final<<<1, 768>>>(bng, bnb);
        k_bn_relu<<<HW * EE / 1024, 256>>>();
        int nt = (chN[b] + 127) / 128;
        k_mma_proj<<<dim3(nt, 32), 256, SMEM_PROJ>>>(
            pActs, pAh, pWp + (size_t)b * 384 * KW2, pCat, 768, chOff[b], chN[b],
            wb[b] ? 24 : 12);
    }

    // ---- CAM ----
    k_gemv<<<HW, 128>>>(pCat, chq, nullptr, pQ, 768);
    k_softmax_hw<<<1, 1024>>>();
    k_poolw<<<32, 256>>>();
    k_pool_fin<<<1, 768>>>();
    k_gemv<<<384, 128>>>(chv, pT, nullptr, pR, 768);
    k_gemv<<<768, 128>>>(chz, pR, nullptr, pWz, 384);
    k_ln_sigmoid<<<1, 768>>>(lng, lnb);
    k_x2<<<HW * EE / 1024, 256>>>();
    k_mma_proj<<<dim3(3, 32), 256, SMEM_PROJ>>>(pX2s, nullptr, pWsp, pQ2, 384, 0, 384, 12);
    k_colmax<<<384, 256>>>();
    k_softmax384<<<1, 384>>>();
    k_u<<<1, 768>>>(spv);
    k_final<<<HW, 256>>>(x[4], normg, normb, (float*)d_out);
}

// round 17
// speedup vs baseline: 6.4276x; 1.1161x over previous
#include <cuda_runtime.h>
#include <cuda_bf16.h>
#include <cuda_fp16.h>
#include <math.h>
#include <stdint.h>

#define HW 4096
#define EE 768
#define NCOL 7155
#define LDC 7168
#define NB 5
#define KW2 1536      // proj weight row: [src0(768) | src1(768)] fp16

__constant__ int c_chN[5]   = {30, 100, 150, 220, 268};
__constant__ int c_chOff[5] = {0, 30, 130, 280, 500};
__constant__ int c_nch[5]   = {12, 12, 24, 24, 24};

static __device__ __half g_Ch[(size_t)NB * HW * LDC];           // 5x main GEMM out fp16
static __device__ __half g_Ah[(size_t)NB * HW * EE];            // 5x x fp16
static __device__ __half g_Bh[(size_t)LDC * EE];                // B fp16 (shared)
static __device__ __half g_acts[(size_t)NB * HW * EE];          // 5x act fp16
static __device__ __half g_x2s[(size_t)HW * EE];                // x2 fp16
static __device__ __half g_Wp[5 * 384 * KW2];
static __device__ __half g_Wsp[384 * KW2];
static __device__ float g_F[27 * 6912];
static __device__ float g_Fp[32 * 27 * 6912];
static __device__ float g_ow[27 * EE];
static __device__ float g_boff[27];
static __device__ float g_off[(size_t)NB * HW * 18];
static __device__ float g_mask[(size_t)NB * HW * 9];
static __device__ float g_blk[(size_t)NB * HW * EE];
static __device__ float g_cat[(size_t)HW * EE];
static __device__ float g_x2[(size_t)HW * EE];
static __device__ float g_q2[(size_t)HW * 384];
static __device__ float g_ps[NB * 32 * EE], g_pq[NB * 32 * EE], g_sc[NB * EE], g_sh[NB * EE];
static __device__ float g_q[HW], g_wq[HW];
static __device__ float g_pt[32 * EE], g_t[EE], g_r[384], g_wz[EE], g_s[EE];
static __device__ float g_mx[384], g_wq2[384], g_u[EE];

// ================= helpers =================
__device__ __forceinline__ uint32_t smem_u32(const void* p) {
    uint32_t a;
    asm("{ .reg .u64 t; cvta.to.shared.u64 t, %1; cvt.u32.u64 %0, t; }" : "=r"(a) : "l"(p));
    return a;
}
__device__ __forceinline__ void cp16(uint32_t dst, const void* src) {
    asm volatile("cp.async.cg.shared.global [%0], [%1], 16;" :: "r"(dst), "l"(src) : "memory");
}
template <int N> __device__ __forceinline__ void cp_wait() {
    asm volatile("cp.async.wait_group %0;" :: "n"(N) : "memory");
}
__device__ __forceinline__ void ldm_x4(uint32_t& r0, uint32_t& r1, uint32_t& r2, uint32_t& r3,
                                       uint32_t addr) {
    asm volatile("ldmatrix.sync.aligned.m8n8.x4.shared.b16 {%0,%1,%2,%3}, [%4];"
                 : "=r"(r0), "=r"(r1), "=r"(r2), "=r"(r3) : "r"(addr));
}
__device__ __forceinline__ void mma_f16(float& d0, float& d1, float& d2, float& d3,
                                        uint32_t a0, uint32_t a1, uint32_t a2, uint32_t a3,
                                        uint32_t b0, uint32_t b1) {
    asm volatile(
        "mma.sync.aligned.m16n8k16.row.col.f32.f16.f16.f32 "
        "{%0,%1,%2,%3}, {%4,%5,%6,%7}, {%8,%9}, {%0,%1,%2,%3};"
        : "+f"(d0), "+f"(d1), "+f"(d2), "+f"(d3)
        : "r"(a0), "r"(a1), "r"(a2), "r"(a3), "r"(b0), "r"(b1));
}
#define SWZ128(x) ((x) ^ (((x) >> 3) & 0x70))

// ========== batched main GEMM: C_h[b][4096 x 7168] = a_f16 @ b_f16^T; grid (56,32,5) ==========
__global__ __launch_bounds__(256, 2)
void k_mma_main()
{
    extern __shared__ char smem_raw[];
    uint32_t sbase = smem_u32(smem_raw);
    int tid = threadIdx.x, wid = tid >> 5, lane = tid & 31;
    int row0 = blockIdx.y * 128, col0 = blockIdx.x * 128;
    int b = blockIdx.z;
    const __half* Abase = g_Ah + (size_t)b * HW * EE;
    __half* Cbase = g_Ch + (size_t)b * HW * LDC;
    int wm = (wid & 1) * 64, wn = (wid >> 1) * 32;

    auto load = [&](int s, int chunk) {
        int k0 = chunk * 64;
        int r = tid & 127;
        bool isB = tid >= 128;
        const __half* g = isB ? &g_Bh[(size_t)(col0 + r) * EE + k0]
                              : &Abase[(size_t)(row0 + r) * EE + k0];
        uint32_t base = sbase + s * 32768 + (isB ? 16384 : 0);
        int rb = r * 128;
#pragma unroll
        for (int seg = 0; seg < 8; seg++)
            cp16(base + SWZ128(rb + seg * 16), g + seg * 8);
        asm volatile("cp.async.commit_group;" ::: "memory");
    };

    float acc[4][4][4];
#pragma unroll
    for (int i = 0; i < 4; i++)
#pragma unroll
        for (int j = 0; j < 4; j++)
#pragma unroll
            for (int k = 0; k < 4; k++) acc[i][j][k] = 0.f;

    load(0, 0); load(1, 1); load(2, 2);

    for (int it = 0; it < 12; it++) {
        int s = it % 3;
        if (it < 10) cp_wait<2>(); else if (it == 10) cp_wait<1>(); else cp_wait<0>();
        __syncthreads();
        uint32_t abase = sbase + s * 32768;
        uint32_t bbase = abase + 16384;
#pragma unroll
        for (int k16 = 0; k16 < 4; k16++) {
            uint32_t bb[4][2];
#pragma unroll
            for (int nb2 = 0; nb2 < 2; nb2++) {
                int n_row = wn + nb2 * 16 + (lane & 7) + ((lane >> 4) << 3);
                int k_byte = k16 * 32 + ((lane >> 3) & 1) * 16;
                uint32_t addr = bbase + SWZ128(n_row * 128 + k_byte);
                ldm_x4(bb[nb2 * 2][0], bb[nb2 * 2][1], bb[nb2 * 2 + 1][0], bb[nb2 * 2 + 1][1], addr);
            }
#pragma unroll
            for (int mf = 0; mf < 4; mf++) {
                int m_row = wm + mf * 16 + (lane & 15);
                int k_byte = k16 * 32 + (lane >> 4) * 16;
                uint32_t addr = abase + SWZ128(m_row * 128 + k_byte);
                uint32_t a0, a1, a2, a3;
                ldm_x4(a0, a1, a2, a3, addr);
#pragma unroll
                for (int nf = 0; nf < 4; nf++)
                    mma_f16(acc[mf][nf][0], acc[mf][nf][1], acc[mf][nf][2], acc[mf][nf][3],
                            a0, a1, a2, a3, bb[nf][0], bb[nf][1]);
            }
        }
        __syncthreads();
        if (it + 3 < 12) load(s, it + 3);
    }

    int rr = lane >> 2, cc = (lane & 3) * 2;
#pragma unroll
    for (int mf = 0; mf < 4; mf++) {
#pragma unroll
        for (int nf = 0; nf < 4; nf++) {
            int r = row0 + wm + mf * 16 + rr;
            int c = col0 + wn + nf * 8 + cc;
            *(__half2*)&Cbase[(size_t)r * LDC + c] =
                __floats2half2_rn(acc[mf][nf][0], acc[mf][nf][1]);
            *(__half2*)&Cbase[(size_t)(r + 8) * LDC + c] =
                __floats2half2_rn(acc[mf][nf][2], acc[mf][nf][3]);
        }
    }
}

// ---- shared proj mainloop (macro-free duplication kept small via lambda-style body) ----
__device__ __forceinline__ void proj_body(
    uint32_t sbase, int tid, int wid, int lane, int row0, int col0,
    const __half* A0, const __half* A1, const __half* W,
    float* C, int ldc, int colOff, int N, int nch)
{
    int wm = (wid & 1) * 64, wn = (wid >> 1) * 32;
    float acc[4][4][4];
#pragma unroll
    for (int i = 0; i < 4; i++)
#pragma unroll
        for (int j = 0; j < 4; j++)
#pragma unroll
            for (int k = 0; k < 4; k++) acc[i][j][k] = 0.f;

    auto load = [&](int s, int chunk) {
        int src = (chunk >= 12) ? 1 : 0;
        int k0 = (chunk - src * 12) * 64;
        int r = tid & 127;
        const __half* g;
        uint32_t base;
        if (tid < 128) {
            g = (src ? A1 : A0) + (size_t)(row0 + r) * EE + k0;
            base = sbase + s * 32768;
        } else {
            g = W + (size_t)(col0 + r) * KW2 + src * 768 + k0;
            base = sbase + s * 32768 + 16384;
        }
        int rb = r * 128;
#pragma unroll
        for (int seg = 0; seg < 8; seg++)
            cp16(base + SWZ128(rb + seg * 16), g + seg * 8);
        asm volatile("cp.async.commit_group;" ::: "memory");
    };

    load(0, 0);
    load(1, 1);

    for (int it = 0; it < nch; it++) {
        int s = it & 1;
        if (it < nch - 1) cp_wait<1>(); else cp_wait<0>();
        __syncthreads();
        uint32_t abase = sbase + s * 32768;
        uint32_t bbase = abase + 16384;
#pragma unroll
        for (int k16 = 0; k16 < 4; k16++) {
            uint32_t bb[4][2];
#pragma unroll
            for (int nb2 = 0; nb2 < 2; nb2++) {
                int n_row = wn + nb2 * 16 + (lane & 7) + ((lane >> 4) << 3);
                int k_byte = k16 * 32 + ((lane >> 3) & 1) * 16;
                uint32_t addr = bbase + SWZ128(n_row * 128 + k_byte);
                ldm_x4(bb[nb2 * 2][0], bb[nb2 * 2][1], bb[nb2 * 2 + 1][0], bb[nb2 * 2 + 1][1], addr);
            }
#pragma unroll
            for (int mf = 0; mf < 4; mf++) {
                int m_row = wm + mf * 16 + (lane & 15);
                int k_byte = k16 * 32 + (lane >> 4) * 16;
                uint32_t addr = abase + SWZ128(m_row * 128 + k_byte);
                uint32_t a0, a1, a2, a3;
                ldm_x4(a0, a1, a2, a3, addr);
#pragma unroll
                for (int nf = 0; nf < 4; nf++)
                    mma_f16(acc[mf][nf][0], acc[mf][nf][1], acc[mf][nf][2], acc[mf][nf][3],
                            a0, a1, a2, a3, bb[nf][0], bb[nf][1]);
            }
        }
        __syncthreads();
        if (it + 2 < nch) load(s, it + 2);
    }

    int rr = lane >> 2, cc = (lane & 3) * 2;
#pragma unroll
    for (int mf = 0; mf < 4; mf++) {
#pragma unroll
        for (int nf = 0; nf < 4; nf++) {
            int c = col0 + wn + nf * 8 + cc;
            if (c < N) {
                int r = row0 + wm + mf * 16 + rr;
                *(float2*)&C[(size_t)r * ldc + colOff + c] =
                    make_float2(acc[mf][nf][0], acc[mf][nf][1]);
                *(float2*)&C[(size_t)(r + 8) * ldc + colOff + c] =
                    make_float2(acc[mf][nf][2], acc[mf][nf][3]);
            }
        }
    }
}

// batched per-block proj: grid (3, 32, 5)
__global__ __launch_bounds__(256, 2)
void k_mma_projb()
{
    extern __shared__ char smem_raw[];
    int b = blockIdx.z;
    int N = c_chN[b];
    if (blockIdx.x * 128 >= N) return;
    proj_body(smem_u32(smem_raw), threadIdx.x, threadIdx.x >> 5, threadIdx.x & 31,
              blockIdx.y * 128, blockIdx.x * 128,
              g_acts + (size_t)b * HW * EE, g_Ah + (size_t)b * HW * EE,
              g_Wp + (size_t)b * 384 * KW2, g_cat, 768, c_chOff[b], N, c_nch[b]);
}
// generic proj (q2)
__global__ __launch_bounds__(256, 2)
void k_mma_proj(const __half* __restrict__ A0, const __half* __restrict__ W,
                float* __restrict__ C, int ldc, int N, int nch)
{
    extern __shared__ char smem_raw[];
    proj_body(smem_u32(smem_raw), threadIdx.x, threadIdx.x >> 5, threadIdx.x & 31,
              blockIdx.y * 128, blockIdx.x * 128, A0, nullptr, W, C, ldc, 0, N, nch);
}

// ---------- builders ----------
__global__ void k_splitA(const float* x0, const float* x1, const float* x2,
                         const float* x3, const float* x4)
{
    int idx = blockIdx.x * 256 + threadIdx.x;
    int b = blockIdx.y;
    const float* x = (b == 0) ? x0 : (b == 1) ? x1 : (b == 2) ? x2 : (b == 3) ? x3 : x4;
    if (idx < HW * EE) g_Ah[(size_t)b * HW * EE + idx] = __float2half(x[idx]);
}
__global__ void k_fusedF_part(const float* __restrict__ convw)
{
    __shared__ float sow[27 * 24];
    int r = blockIdx.x * 256 + threadIdx.x;
    int os = blockIdx.y * 24;
    for (int i = threadIdx.x; i < 27 * 24; i += 256)
        sow[i] = g_ow[(i / 24) * 768 + os + (i % 24)];
    __syncthreads();
    float acc[27];
#pragma unroll
    for (int j = 0; j < 27; j++) acc[j] = 0.f;
    for (int oo = 0; oo < 24; oo++) {
        float cv = convw[(size_t)(os + oo) * 6912 + r];
#pragma unroll
        for (int j = 0; j < 27; j++) acc[j] = fmaf(sow[j * 24 + oo], cv, acc[j]);
    }
#pragma unroll
    for (int j = 0; j < 27; j++)
        g_Fp[(size_t)blockIdx.y * (27 * 6912) + j * 6912 + r] = acc[j];
}
__global__ void k_fusedF_red()
{
    int i = blockIdx.x * 256 + threadIdx.x;
    float s = 0.f;
#pragma unroll
    for (int p = 0; p < 32; p++) s += g_Fp[(size_t)p * (27 * 6912) + i];
    g_F[i] = s;
}
__global__ void k_buildB_taps(const float* __restrict__ convw)
{
    __shared__ float s[6912];
    int o = blockIdx.x, t = threadIdx.x;
    const float* src = convw + (size_t)o * 6912;
    for (int i = t; i < 6912; i += 256) s[i] = src[i];
    __syncthreads();
#pragma unroll
    for (int kk = 0; kk < 9; kk++) {
        size_t base = (size_t)(kk * 768 + o) * EE;
        for (int c = t; c < 768; c += 256)
            g_Bh[base + c] = __float2half(s[c * 9 + kk]);
    }
}
__global__ void k_buildB_fused()
{
    int idx = blockIdx.x * 256 + threadIdx.x;
    if (idx >= (LDC - 6912) * EE) return;
    int nr = idx / EE, c = idx % EE;
    int n = 6912 + nr;
    float v = 0.f;
    if (n < NCOL) {
        int j = nr / 9, kk = nr % 9;
        v = g_F[j * 6912 + c * 9 + kk];
    }
    g_Bh[(size_t)n * EE + c] = __float2half(v);
}
__global__ void k_buildWp(const float* __restrict__ w, __half* __restrict__ dst,
                          int chN, int srcslot)
{
    int idx = blockIdx.x * 256 + threadIdx.x;
    if (idx >= 384 * 768) return;
    int n = idx / 768, c = idx % 768;
    float v = (n < chN) ? w[n * 768 + c] : 0.f;
    dst[(size_t)n * KW2 + srcslot * 768 + c] = __float2half(v);
}

__global__ void k_gemv(const float* __restrict__ W, const float* __restrict__ x,
                       const float* __restrict__ bias, float* __restrict__ y, int K)
{
    int m = blockIdx.x, t = threadIdx.x;
    float a = 0.f;
    for (int k = t; k < K; k += 128) a += W[(size_t)m * K + k] * x[k];
    __shared__ float red[128];
    red[t] = a; __syncthreads();
    for (int s = 64; s > 0; s >>= 1) { if (t < s) red[t] += red[t + s]; __syncthreads(); }
    if (t == 0) y[m] = red[0] + (bias ? bias[m] : 0.f);
}
__global__ void k_prep_ow(const float* __restrict__ offw, const float* __restrict__ mskw)
{
    int i = blockIdx.x * 256 + threadIdx.x;
    if (i < 27 * EE) { int j = i / EE, c = i % EE; g_ow[i] = (j < 18) ? offw[j * EE + c] : mskw[(j - 18) * EE + c]; }
}

// batched offmask: grid (HW, 5)
__global__ void k_offmask()
{
    int hw = blockIdx.x, b = blockIdx.y, y = hw >> 6, x = hw & 63;
    int j = threadIdx.x;
    const __half* Cb = g_Ch + (size_t)b * HW * LDC;
    __shared__ float lg[9];
    __shared__ float mx_s, sum_s;
    if (j < 27) {
        float v = g_boff[j];
#pragma unroll
        for (int k = 0; k < 9; k++) {
            int yy = y + k / 3 - 1, xx = x + k % 3 - 1;
            if (yy >= 0 && yy < 64 && xx >= 0 && xx < 64)
                v += __half2float(Cb[(size_t)(yy * 64 + xx) * LDC + 6912 + j * 9 + k]);
        }
        if (j < 18) g_off[((size_t)b * HW + hw) * 18 + j] = v; else lg[j - 18] = v;
    }
    __syncthreads();
    if (j == 0) {
        float mx = lg[0];
        for (int t = 1; t < 9; t++) mx = fmaxf(mx, lg[t]);
        float s = 0.f;
        for (int t = 0; t < 9; t++) s += expf(lg[t] - mx);
        mx_s = mx; sum_s = s;
    }
    __syncthreads();
    if (j < 9) g_mask[(size_t)b * HW * 9 + hw * 9 + j] = expf(lg[j] - mx_s) / sum_s;
}

// batched gather: grid (HW, 5)
__global__ __launch_bounds__(192)
void k_deform_gather(const float* __restrict__ convb)
{
    int hw = blockIdx.x, b = blockIdx.y, y = hw >> 6, x = hw & 63;
    const __half* Cb = g_Ch + (size_t)b * HW * LDC;
    const float* offb = g_off + (size_t)b * HW * 18;
    const float* maskb = g_mask + (size_t)b * HW * 9;
    float* blkb = g_blk + (size_t)b * HW * EE;
    __shared__ int sidx[9][4];
    __shared__ float swgt[9][4];
    int tid = threadIdx.x;
    if (tid < 9) {
        int k = tid;
        float dy = offb[hw * 18 + 2 * k], dx = offb[hw * 18 + 2 * k + 1];
        float m = maskb[k * HW + hw];  // raw-reshape mask indexing
        float py = (float)(y + k / 3 - 1) + dy;
        float px = (float)(x + k % 3 - 1) + dx;
        float y0f = floorf(py), x0f = floorf(px);
        float wy1 = py - y0f, wx1 = px - x0f;
        int y0 = (int)y0f, x0 = (int)x0f;
#pragma unroll
        for (int c = 0; c < 4; c++) {
            int yy = y0 + (c >> 1), xx = x0 + (c & 1);
            bool valid = (yy >= 0 && yy <= 63 && xx >= 0 && xx <= 63);
            int yc = min(max(yy, 0), 63), xc = min(max(xx, 0), 63);
            float w = ((c >> 1) ? wy1 : 1.f - wy1) * ((c & 1) ? wx1 : 1.f - wx1);
            sidx[k][c] = yc * 64 + xc;
            swgt[k][c] = valid ? w * m : 0.f;
        }
    }
    __syncthreads();
    int o = tid * 4;
    float4 acc = *(const float4*)(convb + o);
#pragma unroll
    for (int k = 0; k < 9; k++) {
        size_t cb = (size_t)k * EE + o;
#pragma unroll
        for (int c = 0; c < 4; c++) {
            float w = swgt[k][c];
            uint2 raw = *(const uint2*)&Cb[(size_t)sidx[k][c] * LDC + cb];
            float2 v01 = __half22float2(*(const __half2*)&raw.x);
            float2 v23 = __half22float2(*(const __half2*)&raw.y);
            acc.x = fmaf(w, v01.x, acc.x); acc.y = fmaf(w, v01.y, acc.y);
            acc.z = fmaf(w, v23.x, acc.z); acc.w = fmaf(w, v23.y, acc.w);
        }
    }
    *(float4*)(&blkb[(size_t)hw * EE + o]) = acc;
}

// batched BN: partial grid (32,5); final grid (5); relu grid (3072,5)
__global__ void k_bn_partial()
{
    int g = blockIdx.x, b = blockIdx.y, t = threadIdx.x;
    const float* blkb = g_blk + (size_t)b * HW * EE;
    float s0 = 0, s1 = 0, s2 = 0, q0 = 0, q1 = 0, q2v = 0;
    for (int r = 0; r < 128; r++) {
        const float* row = &blkb[(size_t)(g * 128 + r) * EE];
        float v0 = row[t], v1 = row[t + 256], v2 = row[t + 512];
        s0 += v0; s1 += v1; s2 += v2; q0 += v0 * v0; q1 += v1 * v1; q2v += v2 * v2;
    }
    float* ps = g_ps + (size_t)(b * 32 + g) * EE;
    float* pq = g_pq + (size_t)(b * 32 + g) * EE;
    ps[t] = s0; ps[t + 256] = s1; ps[t + 512] = s2;
    pq[t] = q0; pq[t + 256] = q1; pq[t + 512] = q2v;
}
__global__ void k_bn_final(const float* __restrict__ bng, const float* __restrict__ bnb)
{
    int b = blockIdx.x, c = threadIdx.x;
    float s = 0, q = 0;
    for (int p = 0; p < 32; p++) {
        s += g_ps[(size_t)(b * 32 + p) * EE + c];
        q += g_pq[(size_t)(b * 32 + p) * EE + c];
    }
    float mu = s * (1.f / 4096.f);
    float var = q * (1.f / 4096.f) - mu * mu;
    float sc = rsqrtf(var + 1e-5f) * bng[c];
    g_sc[b * EE + c] = sc; g_sh[b * EE + c] = bnb[c] - mu * sc;
}
__global__ void k_bn_relu()
{
    int b = blockIdx.y;
    int idx = (blockIdx.x * 256 + threadIdx.x) * 4;
    int c = idx % EE;
    const float* blkb = g_blk + (size_t)b * HW * EE;
    float4 v = *(const float4*)&blkb[idx];
    float4 sc = *(const float4*)&g_sc[b * EE + c];
    float4 sh = *(const float4*)&g_sh[b * EE + c];
    float r0 = fmaxf(0.f, fmaf(v.x, sc.x, sh.x));
    float r1 = fmaxf(0.f, fmaf(v.y, sc.y, sh.y));
    float r2 = fmaxf(0.f, fmaf(v.z, sc.z, sh.z));
    float r3 = fmaxf(0.f, fmaf(v.w, sc.w, sh.w));
    __half2 h01 = __floats2half2_rn(r0, r1);
    __half2 h23 = __floats2half2_rn(r2, r3);
    *(uint2*)&g_acts[(size_t)b * HW * EE + idx] =
        make_uint2(*(uint32_t*)&h01, *(uint32_t*)&h23);
}

__global__ void k_softmax_hw()
{
    __shared__ float sm[4096];
    __shared__ float red[1024];
    int t = threadIdx.x;
    float lm = -1e30f;
    for (int i = t; i < 4096; i += 1024) { float v = g_q[i]; sm[i] = v; lm = fmaxf(lm, v); }
    red[t] = lm; __syncthreads();
    for (int s = 512; s > 0; s >>= 1) { if (t < s) red[t] = fmaxf(red[t], red[t + s]); __syncthreads(); }
    float mx = red[0]; __syncthreads();
    float ls = 0.f;
    for (int i = t; i < 4096; i += 1024) { float e = expf(sm[i] - mx); sm[i] = e; ls += e; }
    red[t] = ls; __syncthreads();
    for (int s = 512; s > 0; s >>= 1) { if (t < s) red[t] += red[t + s]; __syncthreads(); }
    float inv = 1.f / red[0]; __syncthreads();
    for (int i = t; i < 4096; i += 1024) g_wq[i] = sm[i] * inv;
}
__global__ void k_poolw()
{
    int b = blockIdx.x, t = threadIdx.x;
    float a0 = 0, a1 = 0, a2 = 0;
    for (int r = 0; r < 128; r++) {
        int hw = b * 128 + r;
        float w = g_wq[hw];
        const float* row = &g_cat[(size_t)hw * EE];
        a0 += w * row[t]; a1 += w * row[t + 256]; a2 += w * row[t + 512];
    }
    g_pt[b * EE + t] = a0; g_pt[b * EE + t + 256] = a1; g_pt[b * EE + t + 512] = a2;
}
__global__ void k_pool_fin()
{
    int c = threadIdx.x;
    float s = 0;
    for (int b = 0; b < 32; b++) s += g_pt[b * EE + c];
    g_t[c] = s;
}
__global__ void k_ln_sigmoid(const float* __restrict__ lng, const float* __restrict__ lnb)
{
    int c = threadIdx.x;
    __shared__ float buf[768];
    __shared__ float red[256];
    float v = g_wz[c];
    buf[c] = v; __syncthreads();
    if (c < 256) red[c] = buf[c] + buf[c + 256] + buf[c + 512];
    __syncthreads();
    for (int s = 128; s > 0; s >>= 1) { if (c < s) red[c] += red[c + s]; __syncthreads(); }
    float mu = red[0] * (1.f / 768.f); __syncthreads();
    float d = v - mu;
    buf[c] = d * d; __syncthreads();
    if (c < 256) red[c] = buf[c] + buf[c + 256] + buf[c + 512];
    __syncthreads();
    for (int s = 128; s > 0; s >>= 1) { if (c < s) red[c] += red[c + s]; __syncthreads(); }
    float var = red[0] * (1.f / 768.f);
    float z = d * rsqrtf(var + 1e-5f) * lng[c] + lnb[c];
    g_s[c] = 1.f / (1.f + expf(-z));
}
__global__ void k_x2()
{
    int idx = (blockIdx.x * 256 + threadIdx.x) * 4;
    int c = idx % EE;
    float4 v = *(const float4*)&g_cat[idx];
    float4 s = *(const float4*)&g_s[c];
    float r0 = v.x * s.x, r1 = v.y * s.y, r2 = v.z * s.z, r3 = v.w * s.w;
    *(float4*)&g_x2[idx] = make_float4(r0, r1, r2, r3);
    __half2 h01 = __floats2half2_rn(r0, r1);
    __half2 h23 = __floats2half2_rn(r2, r3);
    *(uint2*)&g_x2s[idx] = make_uint2(*(uint32_t*)&h01, *(uint32_t*)&h23);
}
__global__ void k_colmax()
{
    int rr = blockIdx.x, t = threadIdx.x;
    float m = -1e30f;
    for (int i = t; i < 4096; i += 256) m = fmaxf(m, g_q2[(size_t)i * 384 + rr]);
    __shared__ float red[256];
    red[t] = m; __syncthreads();
    for (int s = 128; s > 0; s >>= 1) { if (t < s) red[t] = fmaxf(red[t], red[t + s]); __syncthreads(); }
    if (t == 0) g_mx[rr] = red[0];
}
__global__ void k_softmax384()
{
    int t = threadIdx.x;
    __shared__ float b[384];
    __shared__ float mx, sm;
    b[t] = g_mx[t]; __syncthreads();
    if (t == 0) { float m = b[0]; for (int i = 1; i < 384; i++) m = fmaxf(m, b[i]); mx = m; }
    __syncthreads();
    float e = expf(b[t] - mx);
    b[t] = e; __syncthreads();
    if (t == 0) { float s = 0; for (int i = 0; i < 384; i++) s += b[i]; sm = s; }
    __syncthreads();
    g_wq2[t] = e / sm;
}
__global__ void k_u(const float* __restrict__ spv)
{
    int c = threadIdx.x;
    float s = 0;
    for (int r = 0; r < 384; r++) s += g_wq2[r] * spv[r * EE + c];
    g_u[c] = s;
}
__global__ void k_final(const float* __restrict__ x5, const float* __restrict__ ng,
                        const float* __restrict__ nb, float* __restrict__ out)
{
    int hw = blockIdx.x, t = threadIdx.x;
    __shared__ float v[768];
    __shared__ float red[256];
    const float* x2r = g_x2 + (size_t)hw * EE;
    const float* catr = g_cat + (size_t)hw * EE;
    const float* x5r = x5 + (size_t)hw * EE;
    float d = 0;
    for (int c = t; c < 768; c += 256) d += g_u[c] * x2r[c];
    red[t] = d; __syncthreads();
    for (int s = 128; s > 0; s >>= 1) { if (t < s) red[t] += red[t + s]; __syncthreads(); }
    float wz2 = 1.f / (1.f + expf(-red[0])); __syncthreads();
    float ls = 0;
    for (int c = t; c < 768; c += 256) { float val = wz2 * x2r[c] + catr[c] + x5r[c]; v[c] = val; ls += val; }
    red[t] = ls; __syncthreads();
    for (int s = 128; s > 0; s >>= 1) { if (t < s) red[t] += red[t + s]; __syncthreads(); }
    float mu = red[0] * (1.f / 768.f); __syncthreads();
    float lq = 0;
    for (int c = t; c < 768; c += 256) { float dd = v[c] - mu; lq += dd * dd; }
    red[t] = lq; __syncthreads();
    for (int s = 128; s > 0; s >>= 1) { if (t < s) red[t] += red[t + s]; __syncthreads(); }
    float rstd = rsqrtf(red[0] * (1.f / 768.f) + 1e-5f); __syncthreads();
    for (int c = t; c < 768; c += 256) out[(size_t)hw * EE + c] = (v[c] - mu) * rstd * ng[c] + nb[c];
}

extern "C" void kernel_launch(void* const* d_in, const int* in_sizes, int n_in,
                              void* d_out, int out_size)
{
    const float* x[5];
    for (int i = 0; i < 5; i++) x[i] = (const float*)d_in[i];
    const float* convw = (const float*)d_in[5];
    const float* convb = (const float*)d_in[6];
    const float* offw = (const float*)d_in[7];
    const float* offb = (const float*)d_in[8];
    const float* mskw = (const float*)d_in[9];
    const float* mskb = (const float*)d_in[10];
    const float* bng = (const float*)d_in[11];
    const float* bnb = (const float*)d_in[12];
    const float* chq = (const float*)d_in[13];
    const float* chv = (const float*)d_in[14];
    const float* chz = (const float*)d_in[15];
    const float* lng = (const float*)d_in[16];
    const float* lnb = (const float*)d_in[17];
    const float* spq = (const float*)d_in[18];
    const float* spv = (const float*)d_in[19];
    const float* wa[5] = {(const float*)d_in[20], (const float*)d_in[21], (const float*)d_in[22],
                          (const float*)d_in[24], (const float*)d_in[26]};
    const float* wb[5] = {nullptr, nullptr, (const float*)d_in[23],
                          (const float*)d_in[25], (const float*)d_in[27]};
    const float* normg = (const float*)d_in[28];
    const float* normb = (const float*)d_in[29];

    float *pOw, *pBoff, *pCat, *pQ2, *pQ, *pT, *pR, *pWz;
    __half *pX2s, *pWp, *pWsp;
    cudaGetSymbolAddress((void**)&pOw, g_ow);
    cudaGetSymbolAddress((void**)&pBoff, g_boff);
    cudaGetSymbolAddress((void**)&pCat, g_cat);
    cudaGetSymbolAddress((void**)&pQ2, g_q2);
    cudaGetSymbolAddress((void**)&pQ, g_q);
    cudaGetSymbolAddress((void**)&pT, g_t);
    cudaGetSymbolAddress((void**)&pR, g_r);
    cudaGetSymbolAddress((void**)&pWz, g_wz);
    cudaGetSymbolAddress((void**)&pX2s, g_x2s);
    cudaGetSymbolAddress((void**)&pWp, g_Wp);
    cudaGetSymbolAddress((void**)&pWsp, g_Wsp);

    const int SMEM_MAIN = 3 * 32768;
    const int SMEM_PROJ = 2 * 32768;
    cudaFuncSetAttribute(k_mma_main, cudaFuncAttributeMaxDynamicSharedMemorySize, SMEM_MAIN);
    cudaFuncSetAttribute(k_mma_projb, cudaFuncAttributeMaxDynamicSharedMemorySize, SMEM_PROJ);
    cudaFuncSetAttribute(k_mma_proj, cudaFuncAttributeMaxDynamicSharedMemorySize, SMEM_PROJ);

    // ---- prep ----
    k_prep_ow<<<(27 * EE + 255) / 256, 256>>>(offw, mskw);
    k_gemv<<<18, 128>>>(pOw, convb, offb, pBoff, 768);
    k_gemv<<<9, 128>>>(pOw + 18 * 768, convb, mskb, pBoff + 18, 768);
    k_fusedF_part<<<dim3(27, 32), 256>>>(convw);
    k_fusedF_red<<<27 * 6912 / 256, 256>>>();
    k_buildB_taps<<<768, 256>>>(convw);
    k_buildB_fused<<<((LDC - 6912) * EE + 255) / 256, 256>>>();
    int chN[5] = {30, 100, 150, 220, 268};
    for (int b = 0; b < 5; b++) {
        k_buildWp<<<(384 * 768 + 255) / 256, 256>>>(wa[b], pWp + (size_t)b * 384 * KW2, chN[b], 0);
        if (wb[b])
            k_buildWp<<<(384 * 768 + 255) / 256, 256>>>(wb[b], pWp + (size_t)b * 384 * KW2, chN[b], 1);
    }
    k_buildWp<<<(384 * 768 + 255) / 256, 256>>>(spq, pWsp, 384, 0);

    // ---- batched 5-block pipeline ----
    k_splitA<<<dim3((HW * EE + 255) / 256, 5), 256>>>(x[0], x[1], x[2], x[3], x[4]);
    k_mma_main<<<dim3(56, 32, 5), 256, SMEM_MAIN>>>();
    k_offmask<<<dim3(HW, 5), 32>>>();
    k_deform_gather<<<dim3(HW, 5), 192>>>(convb);
    k_bn_partial<<<dim3(32, 5), 256>>>();
    k_bn_final<<<5, 768>>>(bng, bnb);
    k_bn_relu<<<dim3(HW * EE / 1024, 5), 256>>>();
    k_mma_projb<<<dim3(3, 32, 5), 256, SMEM_PROJ>>>();

    // ---- CAM ----
    k_gemv<<<HW, 128>>>(pCat, chq, nullptr, pQ, 768);
    k_softmax_hw<<<1, 1024>>>();
    k_poolw<<<32, 256>>>();
    k_pool_fin<<<1, 768>>>();
    k_gemv<<<384, 128>>>(chv, pT, nullptr, pR, 768);
    k_gemv<<<768, 128>>>(chz, pR, nullptr, pWz, 384);
    k_ln_sigmoid<<<1, 768>>>(lng, lnb);
    k_x2<<<HW * EE / 1024, 256>>>();
    k_mma_proj<<<dim3(3, 32), 256, SMEM_PROJ>>>(pX2s, pWsp, pQ2, 384, 384, 12);
    k_colmax<<<384, 256>>>();
    k_softmax384<<<1, 384>>>();
    k_u<<<1, 768>>>(spv);
    k_final<<<HW, 256>>>(x[4], normg, normb, (float*)d_out);
}